// round 1
// baseline (speedup 1.0000x reference)
#include <cuda_runtime.h>

#define WN 128
#define NMAXN 100000
#define GMAX 64

// ---------------- scratch (static device globals; no allocation) ----------------
__device__ float g_B0[(size_t)NMAXN * WN];
__device__ float g_B1[(size_t)NMAXN * WN];
__device__ float g_B2[(size_t)NMAXN * WN];
__device__ float g_dinv[NMAXN];
__device__ int   g_cnt[NMAXN];
__device__ float g_stats[2 * WN];
__device__ float g_bnp[2 * WN];
__device__ float g_pooled[GMAX * WN];

// ---------------- degree ----------------
__global__ void deg_kernel(const int* __restrict__ dst, int E) {
    int e = blockIdx.x * blockDim.x + threadIdx.x;
    if (e < E) atomicAdd(&g_cnt[dst[e]], 1);
}

__global__ void dinv_kernel(int N) {
    int i = blockIdx.x * blockDim.x + threadIdx.x;
    if (i < N) g_dinv[i] = rsqrtf((float)g_cnt[i] + 1.0f);
}

// ---------------- GEMM: C[M,128] = op(A)[M,K] @ W[K,128] (+bias) ----------------
// BN=true applies y -> relu(y*scale+shift) to A elements (per input feature k).
template<int K, bool BN>
__global__ __launch_bounds__(256, 2) void gemm_kernel(
        const float* __restrict__ A, const float* __restrict__ W,
        const float* __restrict__ bias, float* __restrict__ C, int M) {
    __shared__ float As[128][17];
    __shared__ float Ws[16][WN];
    int tid = threadIdx.x;
    int tx = tid & 15, ty = tid >> 4;
    int row0 = blockIdx.x * 128;

    float acc[8][8];
#pragma unroll
    for (int i = 0; i < 8; ++i)
#pragma unroll
        for (int j = 0; j < 8; ++j) acc[i][j] = 0.f;

    for (int kb = 0; kb < K; kb += 16) {
        // stage A chunk [128 rows][16 k]
#pragma unroll
        for (int l = 0; l < 2; ++l) {
            int idx = tid + l * 256;
            int r = idx >> 2;
            int kq = (idx & 3) * 4;
            float4 v = make_float4(0.f, 0.f, 0.f, 0.f);
            if (row0 + r < M)
                v = *(const float4*)(A + (size_t)(row0 + r) * K + kb + kq);
            if (BN) {
                v.x = fmaxf(0.f, fmaf(v.x, g_bnp[kb + kq + 0], g_bnp[WN + kb + kq + 0]));
                v.y = fmaxf(0.f, fmaf(v.y, g_bnp[kb + kq + 1], g_bnp[WN + kb + kq + 1]));
                v.z = fmaxf(0.f, fmaf(v.z, g_bnp[kb + kq + 2], g_bnp[WN + kb + kq + 2]));
                v.w = fmaxf(0.f, fmaf(v.w, g_bnp[kb + kq + 3], g_bnp[WN + kb + kq + 3]));
            }
            As[r][kq + 0] = v.x; As[r][kq + 1] = v.y;
            As[r][kq + 2] = v.z; As[r][kq + 3] = v.w;
        }
        // stage W chunk [16 k][128 cols]
#pragma unroll
        for (int l = 0; l < 2; ++l) {
            int idx = tid + l * 256;
            int k = idx >> 5;
            int c = (idx & 31) * 4;
            *(float4*)&Ws[k][c] = *(const float4*)(W + (size_t)(kb + k) * WN + c);
        }
        __syncthreads();
#pragma unroll
        for (int kk = 0; kk < 16; ++kk) {
            float a[8], b[8];
#pragma unroll
            for (int i = 0; i < 8; ++i) a[i] = As[ty * 8 + i][kk];
#pragma unroll
            for (int j = 0; j < 8; ++j) b[j] = Ws[kk][tx * 8 + j];
#pragma unroll
            for (int i = 0; i < 8; ++i)
#pragma unroll
                for (int j = 0; j < 8; ++j) acc[i][j] = fmaf(a[i], b[j], acc[i][j]);
        }
        __syncthreads();
    }

#pragma unroll
    for (int i = 0; i < 8; ++i) {
        int row = row0 + ty * 8 + i;
        if (row < M) {
#pragma unroll
            for (int j2 = 0; j2 < 2; ++j2) {
                int c = tx * 8 + j2 * 4;
                float4 o;
                o.x = acc[i][j2 * 4 + 0] + (bias ? bias[c + 0] : 0.f);
                o.y = acc[i][j2 * 4 + 1] + (bias ? bias[c + 1] : 0.f);
                o.z = acc[i][j2 * 4 + 2] + (bias ? bias[c + 2] : 0.f);
                o.w = acc[i][j2 * 4 + 3] + (bias ? bias[c + 3] : 0.f);
                *(float4*)(C + (size_t)row * WN + c) = o;
            }
        }
    }
}

// ---------------- edge scatter: g_B1[dst] += h[src] * dinv[src]*dinv[dst] ----------------
__global__ void scatter_kernel(const float* __restrict__ h,
                               const int* __restrict__ src,
                               const int* __restrict__ dst, int E) {
    int t = blockIdx.x * blockDim.x + threadIdx.x;
    int e = t >> 5;
    if (e >= E) return;
    int lane = t & 31;
    int s = src[e];
    int d = dst[e];
    float norm = g_dinv[s] * g_dinv[d];
    float4 v = ((const float4*)(h + (size_t)s * WN))[lane];
    v.x *= norm; v.y *= norm; v.z *= norm; v.w *= norm;
    float4* ap = ((float4*)(g_B1 + (size_t)d * WN)) + lane;
    asm volatile("red.global.add.v4.f32 [%0], {%1, %2, %3, %4};"
                 :: "l"(ap), "f"(v.x), "f"(v.y), "f"(v.z), "f"(v.w)
                 : "memory");
}

// ---------------- combine: out = relu(agg + h*dinv^2 + b) ----------------
__global__ void combine_kernel(const float* __restrict__ agg, const float* __restrict__ h,
                               const float* __restrict__ bias, float* __restrict__ out, int N) {
    int i = blockIdx.x * blockDim.x + threadIdx.x;
    if (i >= N * 32) return;
    int row = i >> 5;
    int c4 = i & 31;
    float dv = g_dinv[row];
    float d2 = dv * dv;
    float4 a  = ((const float4*)agg)[i];
    float4 hh = ((const float4*)h)[i];
    float4 b  = ((const float4*)bias)[c4];
    float4 o;
    o.x = fmaxf(0.f, fmaf(hh.x, d2, a.x) + b.x);
    o.y = fmaxf(0.f, fmaf(hh.y, d2, a.y) + b.y);
    o.z = fmaxf(0.f, fmaf(hh.z, d2, a.z) + b.z);
    o.w = fmaxf(0.f, fmaf(hh.w, d2, a.w) + b.w);
    ((float4*)out)[i] = o;
}

// ---------------- BN stats over [N,128] ----------------
__global__ void bnstats_kernel(const float* __restrict__ y, int N) {
    int f = threadIdx.x;  // 128 threads
    float s = 0.f, q = 0.f;
    for (int r = blockIdx.x; r < N; r += gridDim.x) {
        float v = y[(size_t)r * WN + f];
        s += v;
        q += v * v;
    }
    atomicAdd(&g_stats[f], s);
    atomicAdd(&g_stats[WN + f], q);
}

__global__ void bnfinal_kernel(const float* __restrict__ g, const float* __restrict__ be, int N) {
    int f = threadIdx.x;
    float inv = 1.0f / (float)N;
    float mu = g_stats[f] * inv;
    float var = g_stats[WN + f] * inv - mu * mu;
    float sc = g[f] * rsqrtf(var + 1e-5f);
    g_bnp[f] = sc;
    g_bnp[WN + f] = be[f] - mu * sc;
}

// ---------------- pooling: pooled[g,f] = max over nodes (clamped at 0 == relu∘max) ----------------
__global__ void pool_kernel(const float* __restrict__ z, const int* __restrict__ batch, int N) {
    int f = threadIdx.x;  // 128 threads
    int r0 = blockIdx.x * 256;
    int r1 = min(r0 + 256, N);
    float cur = 0.f;
    int curg = -1;
    for (int r = r0; r < r1; ++r) {
        int gi = batch[r];
        if (gi != curg) {
            if (curg >= 0)
                atomicMax((int*)&g_pooled[(size_t)curg * WN + f], __float_as_int(cur));
            curg = gi;
            cur = 0.f;
        }
        cur = fmaxf(cur, z[(size_t)r * WN + f]);
    }
    if (curg >= 0)
        atomicMax((int*)&g_pooled[(size_t)curg * WN + f], __float_as_int(cur));
}

// ---------------- final tiny MLP on [G,128] ----------------
__global__ void final_kernel(const float* __restrict__ W5, const float* __restrict__ b5,
                             const float* __restrict__ g2, const float* __restrict__ be2,
                             const float* __restrict__ W6, const float* __restrict__ b6,
                             float* __restrict__ out, int G) {
    __shared__ float W5s[WN * 64];     // 32 KB
    __shared__ float ys[GMAX][65];
    __shared__ float sc[64], sh[64];
    int tid = threadIdx.x;  // 256
    for (int i = tid; i < WN * 64; i += 256) W5s[i] = W5[i];
    __syncthreads();

    int g = tid & 63;
    int jb = tid >> 6;      // 0..3 -> 16-wide column slab
    float acc[16];
#pragma unroll
    for (int j = 0; j < 16; ++j) acc[j] = 0.f;
    if (g < G) {
        for (int k = 0; k < WN; ++k) {
            float p = g_pooled[(size_t)g * WN + k];
#pragma unroll
            for (int j = 0; j < 16; ++j)
                acc[j] = fmaf(p, W5s[k * 64 + jb * 16 + j], acc[j]);
        }
#pragma unroll
        for (int j = 0; j < 16; ++j)
            ys[g][jb * 16 + j] = acc[j] + b5[jb * 16 + j];
    }
    __syncthreads();

    if (tid < 64) {  // per output feature
        float s = 0.f, q = 0.f;
        for (int r = 0; r < G; ++r) {
            float v = ys[r][tid];
            s += v;
            q += v * v;
        }
        float inv = 1.0f / (float)G;
        float mu = s * inv;
        float var = q * inv - mu * mu;
        float scale = g2[tid] * rsqrtf(var + 1e-5f);
        sc[tid] = scale;
        sh[tid] = be2[tid] - mu * scale;
    }
    __syncthreads();

    if (tid < G) {
        float o = b6[0];
        for (int j = 0; j < 64; ++j) {
            float v = fmaxf(0.f, fmaf(ys[tid][j], sc[j], sh[j]));
            o = fmaf(v, W6[j], o);
        }
        out[tid] = o;
    }
}

// ---------------- launch ----------------
extern "C" void kernel_launch(void* const* d_in, const int* in_sizes, int n_in,
                              void* d_out, int out_size) {
    const float* x   = (const float*)d_in[0];
    const int*   ei  = (const int*)d_in[1];
    const int*   bat = (const int*)d_in[2];
    const float* W1  = (const float*)d_in[3];
    const float* b1  = (const float*)d_in[4];
    const float* W2  = (const float*)d_in[5];
    const float* b2  = (const float*)d_in[6];
    const float* W3  = (const float*)d_in[7];
    const float* b3  = (const float*)d_in[8];
    const float* g1  = (const float*)d_in[9];
    const float* be1 = (const float*)d_in[10];
    const float* W4  = (const float*)d_in[11];
    const float* b4  = (const float*)d_in[12];
    const float* W5  = (const float*)d_in[13];
    const float* b5  = (const float*)d_in[14];
    const float* g2  = (const float*)d_in[15];
    const float* be2 = (const float*)d_in[16];
    const float* W6  = (const float*)d_in[17];
    const float* b6  = (const float*)d_in[18];

    int N = in_sizes[2];
    int E = in_sizes[1] / 2;
    int G = out_size;
    const int* src = ei;
    const int* dst = ei + E;

    float *B0, *B1, *B2;
    void *pcnt, *pstats, *ppooled;
    cudaGetSymbolAddress((void**)&B0, g_B0);
    cudaGetSymbolAddress((void**)&B1, g_B1);
    cudaGetSymbolAddress((void**)&B2, g_B2);
    cudaGetSymbolAddress(&pcnt, g_cnt);
    cudaGetSymbolAddress(&pstats, g_stats);
    cudaGetSymbolAddress(&ppooled, g_pooled);

    cudaMemsetAsync(pcnt, 0, (size_t)N * sizeof(int));
    cudaMemsetAsync(pstats, 0, 2 * WN * sizeof(float));
    cudaMemsetAsync(ppooled, 0, (size_t)G * WN * sizeof(float));

    deg_kernel<<<(E + 255) / 256, 256>>>(dst, E);
    dinv_kernel<<<(N + 255) / 256, 256>>>(N);

    int gb = (N + 127) / 128;
    int scat_blocks = (int)(((long long)E * 32 + 255) / 256);
    int comb_blocks = (N * 32 + 255) / 256;

    // conv1
    gemm_kernel<32, false><<<gb, 256>>>(x, W1, nullptr, B0, N);
    cudaMemsetAsync(B1, 0, (size_t)N * WN * sizeof(float));
    scatter_kernel<<<scat_blocks, 256>>>(B0, src, dst, E);
    combine_kernel<<<comb_blocks, 256>>>(B1, B0, b1, B2, N);

    // conv2
    gemm_kernel<128, false><<<gb, 256>>>(B2, W2, nullptr, B0, N);
    cudaMemsetAsync(B1, 0, (size_t)N * WN * sizeof(float));
    scatter_kernel<<<scat_blocks, 256>>>(B0, src, dst, E);
    combine_kernel<<<comb_blocks, 256>>>(B1, B0, b2, B2, N);

    // mlp_first: y = x@W3 + b3 ; BN stats ; z = relu(bn(y))@W4 + b4
    gemm_kernel<128, false><<<gb, 256>>>(B2, W3, b3, B0, N);
    bnstats_kernel<<<512, 128>>>(B0, N);
    bnfinal_kernel<<<1, 128>>>(g1, be1, N);
    gemm_kernel<128, true><<<gb, 256>>>(B0, W4, b4, B1, N);

    // global max pool (relu folded in via clamp at 0)
    pool_kernel<<<(N + 255) / 256, 128>>>(B1, bat, N);

    // final MLP
    final_kernel<<<1, 256>>>(W5, b5, g2, be2, W6, b6, (float*)d_out, G);
}

// round 3
// speedup vs baseline: 1.1071x; 1.1071x over previous
#include <cuda_runtime.h>

#define WN 128
#define NMAXN 100000
#define GMAX 64

// ---------------- scratch ----------------
__device__ float g_B0[(size_t)NMAXN * WN];
__device__ float g_B1[(size_t)NMAXN * WN];
__device__ float g_B2[(size_t)NMAXN * WN];
__device__ float g_dinv[NMAXN];
__device__ int   g_cnt[NMAXN];
__device__ float g_stats[2 * WN];
__device__ float g_bnp[2 * WN];
__device__ float g_pooled[GMAX * WN];

// ---------------- degree ----------------
__global__ void deg_kernel(const int* __restrict__ dst, int E) {
    int e = blockIdx.x * blockDim.x + threadIdx.x;
    if (e < E) atomicAdd(&g_cnt[dst[e]], 1);
}

__global__ void dinv_kernel(int N) {
    int i = blockIdx.x * blockDim.x + threadIdx.x;
    if (i < N) g_dinv[i] = rsqrtf((float)g_cnt[i] + 1.0f);
}

// ---------------- packed f32x2 helpers ----------------
__device__ __forceinline__ unsigned long long dup_f32x2(float v) {
    unsigned long long d;
    unsigned int u = __float_as_uint(v);
    asm("mov.b64 %0, {%1, %1};" : "=l"(d) : "r"(u));
    return d;
}
__device__ __forceinline__ void fma2(unsigned long long& acc,
                                     unsigned long long a, unsigned long long b) {
    asm("fma.rn.f32x2 %0, %1, %2, %0;" : "+l"(acc) : "l"(a), "l"(b));
}
__device__ __forceinline__ void unpack2(unsigned long long v, float& lo, float& hi) {
    unsigned int a, b;
    asm("mov.b64 {%0, %1}, %2;" : "=r"(a), "=r"(b) : "l"(v));
    lo = __uint_as_float(a);
    hi = __uint_as_float(b);
}

// ---------------- GEMM: C[M,128] = pro(A)[M,K] @ W[K,128] ----------------
// PRO: 0 = identity, 1 = relu, 2 = relu(affine BN via g_bnp)
// SELF: C gets raw acc (no bias); C2 gets acc*dinv[row]^2 + bias  (agg init)
// !SELF: C gets acc + bias (bias may be null)
template<int K, int PRO, bool SELF>
__global__ __launch_bounds__(256, 2) void gemm_kernel(
        const float* __restrict__ A, const float* __restrict__ W,
        const float* __restrict__ bias, float* __restrict__ C,
        float* __restrict__ C2, int M) {
    __shared__ __align__(16) float As[16][132];   // k-major
    __shared__ __align__(16) float Ws[16][WN];
    int tid = threadIdx.x;
    int tx = tid & 15, ty = tid >> 4;
    int row0 = blockIdx.x * 128;

    unsigned long long acc[4][8];
#pragma unroll
    for (int i = 0; i < 4; ++i)
#pragma unroll
        for (int j = 0; j < 8; ++j) acc[i][j] = 0ull;

    for (int kb = 0; kb < K; kb += 16) {
        // stage A chunk, k-major, with prologue
#pragma unroll
        for (int l = 0; l < 2; ++l) {
            int idx = tid + l * 256;
            int r = idx >> 2;
            int kq = (idx & 3) * 4;
            float4 v = make_float4(0.f, 0.f, 0.f, 0.f);
            if (row0 + r < M)
                v = *(const float4*)(A + (size_t)(row0 + r) * K + kb + kq);
            if (PRO == 1) {
                v.x = fmaxf(0.f, v.x); v.y = fmaxf(0.f, v.y);
                v.z = fmaxf(0.f, v.z); v.w = fmaxf(0.f, v.w);
            } else if (PRO == 2) {
                v.x = fmaxf(0.f, fmaf(v.x, g_bnp[kb + kq + 0], g_bnp[WN + kb + kq + 0]));
                v.y = fmaxf(0.f, fmaf(v.y, g_bnp[kb + kq + 1], g_bnp[WN + kb + kq + 1]));
                v.z = fmaxf(0.f, fmaf(v.z, g_bnp[kb + kq + 2], g_bnp[WN + kb + kq + 2]));
                v.w = fmaxf(0.f, fmaf(v.w, g_bnp[kb + kq + 3], g_bnp[WN + kb + kq + 3]));
            }
            As[kq + 0][r] = v.x; As[kq + 1][r] = v.y;
            As[kq + 2][r] = v.z; As[kq + 3][r] = v.w;
        }
        // stage W chunk
#pragma unroll
        for (int l = 0; l < 2; ++l) {
            int idx = tid + l * 256;
            int k = idx >> 5;
            int c = (idx & 31) * 4;
            *(float4*)&Ws[k][c] = *(const float4*)(W + (size_t)(kb + k) * WN + c);
        }
        __syncthreads();
#pragma unroll
        for (int kk = 0; kk < 16; ++kk) {
            // A: 8 consecutive rows -> 4 natural f32x2 pairs
            ulonglong2 a01 = *(const ulonglong2*)&As[kk][ty * 8];
            ulonglong2 a23 = *(const ulonglong2*)&As[kk][ty * 8 + 4];
            unsigned long long ap[4] = {a01.x, a01.y, a23.x, a23.y};
            float4 b0 = *(const float4*)&Ws[kk][tx * 8];
            float4 b1 = *(const float4*)&Ws[kk][tx * 8 + 4];
            unsigned long long bd[8];
            bd[0] = dup_f32x2(b0.x); bd[1] = dup_f32x2(b0.y);
            bd[2] = dup_f32x2(b0.z); bd[3] = dup_f32x2(b0.w);
            bd[4] = dup_f32x2(b1.x); bd[5] = dup_f32x2(b1.y);
            bd[6] = dup_f32x2(b1.z); bd[7] = dup_f32x2(b1.w);
#pragma unroll
            for (int pi = 0; pi < 4; ++pi)
#pragma unroll
                for (int j = 0; j < 8; ++j) fma2(acc[pi][j], ap[pi], bd[j]);
        }
        __syncthreads();
    }

    // epilogue: rows ty*8 + 2*pi + {0,1}, cols tx*8..tx*8+7
    float bv[8];
#pragma unroll
    for (int j = 0; j < 8; ++j) bv[j] = bias ? bias[tx * 8 + j] : 0.f;

#pragma unroll
    for (int pi = 0; pi < 4; ++pi) {
        float lo[8], hi[8];
#pragma unroll
        for (int j = 0; j < 8; ++j) unpack2(acc[pi][j], lo[j], hi[j]);
#pragma unroll
        for (int h = 0; h < 2; ++h) {
            int row = row0 + ty * 8 + pi * 2 + h;
            if (row >= M) continue;
            float* vp = h ? hi : lo;
            if (SELF) {
                float dv = g_dinv[row];
                float d2 = dv * dv;
                float4 o0 = make_float4(vp[0], vp[1], vp[2], vp[3]);
                float4 o1 = make_float4(vp[4], vp[5], vp[6], vp[7]);
                *(float4*)(C + (size_t)row * WN + tx * 8) = o0;
                *(float4*)(C + (size_t)row * WN + tx * 8 + 4) = o1;
                float4 s0 = make_float4(fmaf(vp[0], d2, bv[0]), fmaf(vp[1], d2, bv[1]),
                                        fmaf(vp[2], d2, bv[2]), fmaf(vp[3], d2, bv[3]));
                float4 s1 = make_float4(fmaf(vp[4], d2, bv[4]), fmaf(vp[5], d2, bv[5]),
                                        fmaf(vp[6], d2, bv[6]), fmaf(vp[7], d2, bv[7]));
                *(float4*)(C2 + (size_t)row * WN + tx * 8) = s0;
                *(float4*)(C2 + (size_t)row * WN + tx * 8 + 4) = s1;
            } else {
                float4 o0 = make_float4(vp[0] + bv[0], vp[1] + bv[1], vp[2] + bv[2], vp[3] + bv[3]);
                float4 o1 = make_float4(vp[4] + bv[4], vp[5] + bv[5], vp[6] + bv[6], vp[7] + bv[7]);
                *(float4*)(C + (size_t)row * WN + tx * 8) = o0;
                *(float4*)(C + (size_t)row * WN + tx * 8 + 4) = o1;
            }
        }
    }
}

// ---------------- edge scatter: out[dst] += h[src] * dinv[src]*dinv[dst] ----------------
__global__ void scatter_kernel(const float* __restrict__ h,
                               const int* __restrict__ src,
                               const int* __restrict__ dst,
                               float* __restrict__ out, int E) {
    int t = blockIdx.x * blockDim.x + threadIdx.x;
    int e = t >> 5;
    if (e >= E) return;
    int lane = t & 31;
    int s = src[e];
    int d = dst[e];
    float norm = g_dinv[s] * g_dinv[d];
    float4 v = ((const float4*)(h + (size_t)s * WN))[lane];
    v.x *= norm; v.y *= norm; v.z *= norm; v.w *= norm;
    float4* ap = ((float4*)(out + (size_t)d * WN)) + lane;
    asm volatile("red.global.add.v4.f32 [%0], {%1, %2, %3, %4};"
                 :: "l"(ap), "f"(v.x), "f"(v.y), "f"(v.z), "f"(v.w)
                 : "memory");
}

// ---------------- BN stats over [N,128] ----------------
__global__ void bnstats_kernel(const float* __restrict__ y, int N) {
    int f = threadIdx.x;
    float s = 0.f, q = 0.f;
    for (int r = blockIdx.x; r < N; r += gridDim.x) {
        float v = y[(size_t)r * WN + f];
        s += v;
        q += v * v;
    }
    atomicAdd(&g_stats[f], s);
    atomicAdd(&g_stats[WN + f], q);
}

__global__ void bnfinal_kernel(const float* __restrict__ g, const float* __restrict__ be, int N) {
    int f = threadIdx.x;
    float inv = 1.0f / (float)N;
    float mu = g_stats[f] * inv;
    float var = g_stats[WN + f] * inv - mu * mu;
    float sc = g[f] * rsqrtf(var + 1e-5f);
    g_bnp[f] = sc;
    g_bnp[WN + f] = be[f] - mu * sc;
}

// ---------------- pooling ----------------
__global__ void pool_kernel(const float* __restrict__ z, const int* __restrict__ batch, int N) {
    int f = threadIdx.x;
    int r0 = blockIdx.x * 256;
    int r1 = min(r0 + 256, N);
    float cur = 0.f;
    int curg = -1;
    for (int r = r0; r < r1; ++r) {
        int gi = batch[r];
        if (gi != curg) {
            if (curg >= 0)
                atomicMax((int*)&g_pooled[(size_t)curg * WN + f], __float_as_int(cur));
            curg = gi;
            cur = 0.f;
        }
        cur = fmaxf(cur, z[(size_t)r * WN + f]);
    }
    if (curg >= 0)
        atomicMax((int*)&g_pooled[(size_t)curg * WN + f], __float_as_int(cur));
}

// ---------------- final tiny MLP ----------------
__global__ void final_kernel(const float* __restrict__ W5, const float* __restrict__ b5,
                             const float* __restrict__ g2, const float* __restrict__ be2,
                             const float* __restrict__ W6, const float* __restrict__ b6,
                             float* __restrict__ out, int G) {
    __shared__ float W5s[WN * 64];
    __shared__ float ys[GMAX][65];
    __shared__ float sc[64], sh[64];
    int tid = threadIdx.x;
    for (int i = tid; i < WN * 64; i += 256) W5s[i] = W5[i];
    __syncthreads();

    int g = tid & 63;
    int jb = tid >> 6;
    float acc[16];
#pragma unroll
    for (int j = 0; j < 16; ++j) acc[j] = 0.f;
    if (g < G) {
        for (int k = 0; k < WN; ++k) {
            float p = g_pooled[(size_t)g * WN + k];
#pragma unroll
            for (int j = 0; j < 16; ++j)
                acc[j] = fmaf(p, W5s[k * 64 + jb * 16 + j], acc[j]);
        }
#pragma unroll
        for (int j = 0; j < 16; ++j)
            ys[g][jb * 16 + j] = acc[j] + b5[jb * 16 + j];
    }
    __syncthreads();

    if (tid < 64) {
        float s = 0.f, q = 0.f;
        for (int r = 0; r < G; ++r) {
            float v = ys[r][tid];
            s += v;
            q += v * v;
        }
        float inv = 1.0f / (float)G;
        float mu = s * inv;
        float var = q * inv - mu * mu;
        float scale = g2[tid] * rsqrtf(var + 1e-5f);
        sc[tid] = scale;
        sh[tid] = be2[tid] - mu * scale;
    }
    __syncthreads();

    if (tid < G) {
        float o = b6[0];
        for (int j = 0; j < 64; ++j) {
            float v = fmaxf(0.f, fmaf(ys[tid][j], sc[j], sh[j]));
            o = fmaf(v, W6[j], o);
        }
        out[tid] = o;
    }
}

// ---------------- launch ----------------
extern "C" void kernel_launch(void* const* d_in, const int* in_sizes, int n_in,
                              void* d_out, int out_size) {
    const float* x   = (const float*)d_in[0];
    const int*   ei  = (const int*)d_in[1];
    const int*   bat = (const int*)d_in[2];
    const float* W1  = (const float*)d_in[3];
    const float* b1  = (const float*)d_in[4];
    const float* W2  = (const float*)d_in[5];
    const float* b2  = (const float*)d_in[6];
    const float* W3  = (const float*)d_in[7];
    const float* b3  = (const float*)d_in[8];
    const float* g1  = (const float*)d_in[9];
    const float* be1 = (const float*)d_in[10];
    const float* W4  = (const float*)d_in[11];
    const float* b4  = (const float*)d_in[12];
    const float* W5  = (const float*)d_in[13];
    const float* b5  = (const float*)d_in[14];
    const float* g2  = (const float*)d_in[15];
    const float* be2 = (const float*)d_in[16];
    const float* W6  = (const float*)d_in[17];
    const float* b6  = (const float*)d_in[18];

    int N = in_sizes[2];
    int E = in_sizes[1] / 2;
    int G = out_size;
    const int* src = ei;
    const int* dst = ei + E;

    float *B0, *B1, *B2;
    void *pcnt, *pstats, *ppooled;
    cudaGetSymbolAddress((void**)&B0, g_B0);
    cudaGetSymbolAddress((void**)&B1, g_B1);
    cudaGetSymbolAddress((void**)&B2, g_B2);
    cudaGetSymbolAddress(&pcnt, g_cnt);
    cudaGetSymbolAddress(&pstats, g_stats);
    cudaGetSymbolAddress(&ppooled, g_pooled);

    cudaMemsetAsync(pcnt, 0, (size_t)N * sizeof(int));
    cudaMemsetAsync(pstats, 0, 2 * WN * sizeof(float));
    cudaMemsetAsync(ppooled, 0, (size_t)G * WN * sizeof(float));

    deg_kernel<<<(E + 255) / 256, 256>>>(dst, E);
    dinv_kernel<<<(N + 255) / 256, 256>>>(N);

    int gb = (N + 127) / 128;
    int scat_blocks = (int)(((long long)E * 32 + 255) / 256);

    // conv1: h=B0, agg(init self+bias)=B1; scatter into B1
    gemm_kernel<32, 0, true><<<gb, 256>>>(x, W1, b1, B0, B1, N);
    scatter_kernel<<<scat_blocks, 256>>>(B0, src, dst, B1, E);

    // conv2: reads relu(B1); h=B0, agg=B2; scatter into B2
    gemm_kernel<128, 1, true><<<gb, 256>>>(B1, W2, b2, B0, B2, N);
    scatter_kernel<<<scat_blocks, 256>>>(B0, src, dst, B2, E);

    // mlp_first: y = relu(B2)@W3 + b3 -> B1 ; BN ; z = relu(bn(B1))@W4 + b4 -> B0
    gemm_kernel<128, 1, false><<<gb, 256>>>(B2, W3, b3, B1, nullptr, N);
    bnstats_kernel<<<512, 128>>>(B1, N);
    bnfinal_kernel<<<1, 128>>>(g1, be1, N);
    gemm_kernel<128, 2, false><<<gb, 256>>>(B1, W4, b4, B0, nullptr, N);

    // global max pool (relu folded via clamp at 0)
    pool_kernel<<<(N + 255) / 256, 128>>>(B0, bat, N);

    // final MLP
    final_kernel<<<1, 256>>>(W5, b5, g2, be2, W6, b6, (float*)d_out, G);
}

// round 5
// speedup vs baseline: 1.2577x; 1.1360x over previous
#include <cuda_runtime.h>

#define WN 128
#define NMAXN 100000
#define GMAX 64

// ---------------- scratch ----------------
__device__ float g_B0[(size_t)NMAXN * WN];
__device__ float g_B1[(size_t)NMAXN * WN];
__device__ float g_B2[(size_t)NMAXN * WN];
__device__ float g_dinv[NMAXN];
__device__ int   g_cnt[NMAXN];
__device__ float g_stats[2 * WN];
__device__ float g_bnp[2 * WN];
__device__ float g_pooled[GMAX * WN];

// ---------------- degree ----------------
__global__ void deg_kernel(const int* __restrict__ dst, int E) {
    int e = blockIdx.x * blockDim.x + threadIdx.x;
    if (e < E) atomicAdd(&g_cnt[dst[e]], 1);
}

__global__ void dinv_kernel(int N) {
    int i = blockIdx.x * blockDim.x + threadIdx.x;
    if (i < N) g_dinv[i] = rsqrtf((float)g_cnt[i] + 1.0f);
}

// ---------------- tf32 helpers ----------------
__device__ __forceinline__ unsigned cvt_tf32(float f) {
    unsigned u;
    asm("cvt.rna.tf32.f32 %0, %1;" : "=r"(u) : "f"(f));
    return u;
}
// split f into hi (tf32) and lo (tf32 of remainder)
__device__ __forceinline__ void split_tf32(float f, unsigned& hi, unsigned& lo) {
    hi = cvt_tf32(f);
    lo = cvt_tf32(f - __uint_as_float(hi));
}

__device__ __forceinline__ void mma_tf32(float* c, const unsigned* a, const unsigned* b) {
    asm volatile(
        "mma.sync.aligned.m16n8k8.row.col.f32.tf32.tf32.f32 "
        "{%0,%1,%2,%3}, {%4,%5,%6,%7}, {%8,%9}, {%0,%1,%2,%3};"
        : "+f"(c[0]), "+f"(c[1]), "+f"(c[2]), "+f"(c[3])
        : "r"(a[0]), "r"(a[1]), "r"(a[2]), "r"(a[3]), "r"(b[0]), "r"(b[1]));
}

// ---------------- 3xTF32 tensor-core GEMM: C[M,128] = pro(A)[M,K] @ W[K,128] ----------------
// PRO: 0 identity, 1 relu, 2 relu(BN affine via g_bnp)
// SELF: C = raw acc (h); C2 = acc*dinv[row]^2 + bias (agg init)
// !SELF: C = acc + bias. STATS: accumulate column sums/sumsq of C into g_stats.
template<int K, int PRO, bool SELF, bool STATS>
__global__ __launch_bounds__(256, 2) void mma_gemm(
        const float* __restrict__ A, const float* __restrict__ W,
        const float* __restrict__ bias, float* __restrict__ C,
        float* __restrict__ C2, int M) {
    constexpr int CH = 32;                   // k-chunk per stage
    constexpr int CQ = CH / 4;               // 8
    constexpr int AS = 36;                   // A smem stride (words)
    constexpr int WS = 136;                  // W smem stride (words)
    extern __shared__ unsigned smem[];
    unsigned* Wh = smem;                         // [CH][WS]
    unsigned* Wl = Wh + CH * WS;
    unsigned* Ah = Wl + CH * WS;                 // [128][AS]
    unsigned* Al = Ah + 128 * AS;
    __shared__ float sstat[2 * WN];

    int tid = threadIdx.x;
    int lane = tid & 31, wid = tid >> 5;
    int wm = wid >> 1, wn = wid & 1;
    int row0 = blockIdx.x * 128;

    if (STATS) sstat[tid] = 0.f;

    float acc[2][8][4];
#pragma unroll
    for (int mt = 0; mt < 2; ++mt)
#pragma unroll
        for (int nt = 0; nt < 8; ++nt)
#pragma unroll
            for (int q = 0; q < 4; ++q) acc[mt][nt][q] = 0.f;

    for (int kb = 0; kb < K; kb += CH) {
        __syncthreads();
        // stage W chunk (hi/lo)
        for (int i = tid; i < CH * 32; i += 256) {
            int k = i >> 5, c = (i & 31) * 4;
            float4 v = *(const float4*)(W + (size_t)(kb + k) * WN + c);
            uint4 th, tl;
            split_tf32(v.x, th.x, tl.x);
            split_tf32(v.y, th.y, tl.y);
            split_tf32(v.z, th.z, tl.z);
            split_tf32(v.w, th.w, tl.w);
            *(uint4*)&Wh[k * WS + c] = th;
            *(uint4*)&Wl[k * WS + c] = tl;
        }
        // stage A chunk with prologue (hi/lo)
        for (int i = tid; i < 128 * CQ; i += 256) {
            int r = i >> 3, q = (i & 7) * 4;
            float4 v = make_float4(0.f, 0.f, 0.f, 0.f);
            if (row0 + r < M)
                v = *(const float4*)(A + (size_t)(row0 + r) * K + kb + q);
            if (PRO == 1) {
                v.x = fmaxf(0.f, v.x); v.y = fmaxf(0.f, v.y);
                v.z = fmaxf(0.f, v.z); v.w = fmaxf(0.f, v.w);
            } else if (PRO == 2) {
                int kg = kb + q;
                v.x = fmaxf(0.f, fmaf(v.x, g_bnp[kg + 0], g_bnp[WN + kg + 0]));
                v.y = fmaxf(0.f, fmaf(v.y, g_bnp[kg + 1], g_bnp[WN + kg + 1]));
                v.z = fmaxf(0.f, fmaf(v.z, g_bnp[kg + 2], g_bnp[WN + kg + 2]));
                v.w = fmaxf(0.f, fmaf(v.w, g_bnp[kg + 3], g_bnp[WN + kg + 3]));
            }
            uint4 th, tl;
            split_tf32(v.x, th.x, tl.x);
            split_tf32(v.y, th.y, tl.y);
            split_tf32(v.z, th.z, tl.z);
            split_tf32(v.w, th.w, tl.w);
            *(uint4*)&Ah[r * AS + q] = th;
            *(uint4*)&Al[r * AS + q] = tl;
        }
        __syncthreads();

#pragma unroll
        for (int ks = 0; ks < CH / 8; ++ks) {
            int ka = ks * 8 + (lane & 3);    // chunk-local k
            unsigned ah[2][4], al[2][4];
            int r = wm * 32 + (lane >> 2);
#pragma unroll
            for (int mt = 0; mt < 2; ++mt) {
                const unsigned* ph = &Ah[(r + mt * 16) * AS + ka];
                const unsigned* pl = &Al[(r + mt * 16) * AS + ka];
                ah[mt][0] = ph[0]; ah[mt][1] = ph[8 * AS];
                ah[mt][2] = ph[4]; ah[mt][3] = ph[8 * AS + 4];
                al[mt][0] = pl[0]; al[mt][1] = pl[8 * AS];
                al[mt][2] = pl[4]; al[mt][3] = pl[8 * AS + 4];
            }
#pragma unroll
            for (int nh = 0; nh < 2; ++nh) {
                unsigned bh[4][2], bl[4][2];
#pragma unroll
                for (int j = 0; j < 4; ++j) {
                    int c = wn * 64 + (nh * 4 + j) * 8 + (lane >> 2);
                    bh[j][0] = Wh[ka * WS + c];
                    bh[j][1] = Wh[(ka + 4) * WS + c];
                    bl[j][0] = Wl[ka * WS + c];
                    bl[j][1] = Wl[(ka + 4) * WS + c];
                }
#pragma unroll
                for (int mt = 0; mt < 2; ++mt)
#pragma unroll
                    for (int j = 0; j < 4; ++j) {
                        float* cc = acc[mt][nh * 4 + j];
                        mma_tf32(cc, al[mt], bh[j]);   // small terms first
                        mma_tf32(cc, ah[mt], bl[j]);
                        mma_tf32(cc, ah[mt], bh[j]);
                    }
            }
        }
    }

    // ---------------- epilogue ----------------
    float ss[16], sq[16];
    if (STATS) {
#pragma unroll
        for (int i = 0; i < 16; ++i) { ss[i] = 0.f; sq[i] = 0.f; }
    }

#pragma unroll
    for (int mt = 0; mt < 2; ++mt) {
#pragma unroll
        for (int h = 0; h < 2; ++h) {
            int row = row0 + wm * 32 + mt * 16 + (lane >> 2) + h * 8;
            bool ok = row < M;
            float d2 = 0.f;
            if (SELF && ok) {
                float dv = g_dinv[row];
                d2 = dv * dv;
            }
#pragma unroll
            for (int nt = 0; nt < 8; ++nt) {
                int col = wn * 64 + nt * 8 + (lane & 3) * 2;
                float v0 = acc[mt][nt][h * 2 + 0];
                float v1 = acc[mt][nt][h * 2 + 1];
                if (SELF) {
                    if (ok) {
                        *(float2*)(C + (size_t)row * WN + col) = make_float2(v0, v1);
                        float b0 = bias[col], b1 = bias[col + 1];
                        *(float2*)(C2 + (size_t)row * WN + col) =
                            make_float2(fmaf(v0, d2, b0), fmaf(v1, d2, b1));
                    }
                } else {
                    float o0 = v0 + bias[col];
                    float o1 = v1 + bias[col + 1];
                    if (ok)
                        *(float2*)(C + (size_t)row * WN + col) = make_float2(o0, o1);
                    if (STATS) {
                        if (!ok) { o0 = 0.f; o1 = 0.f; }
                        ss[nt * 2 + 0] += o0; sq[nt * 2 + 0] += o0 * o0;
                        ss[nt * 2 + 1] += o1; sq[nt * 2 + 1] += o1 * o1;
                    }
                }
            }
        }
    }

    if (STATS) {
#pragma unroll
        for (int i = 0; i < 16; ++i) {
#pragma unroll
            for (int o = 4; o <= 16; o <<= 1) {
                ss[i] += __shfl_xor_sync(0xffffffffu, ss[i], o);
                sq[i] += __shfl_xor_sync(0xffffffffu, sq[i], o);
            }
        }
        if (lane < 4) {
#pragma unroll
            for (int nt = 0; nt < 8; ++nt)
#pragma unroll
                for (int c = 0; c < 2; ++c) {
                    int col = wn * 64 + nt * 8 + lane * 2 + c;
                    atomicAdd(&sstat[col], ss[nt * 2 + c]);
                    atomicAdd(&sstat[WN + col], sq[nt * 2 + c]);
                }
        }
        __syncthreads();
        atomicAdd(&g_stats[tid], sstat[tid]);
    }
}

// ---------------- edge scatter: out[dst] += h[src] * dinv[src]*dinv[dst] ----------------
__global__ void scatter_kernel(const float* __restrict__ h,
                               const int* __restrict__ src,
                               const int* __restrict__ dst,
                               float* __restrict__ out, int E) {
    int t = blockIdx.x * blockDim.x + threadIdx.x;
    int e = t >> 5;
    if (e >= E) return;
    int lane = t & 31;
    int s = src[e];
    int d = dst[e];
    float norm = g_dinv[s] * g_dinv[d];
    float4 v = ((const float4*)(h + (size_t)s * WN))[lane];
    v.x *= norm; v.y *= norm; v.z *= norm; v.w *= norm;
    float4* ap = ((float4*)(out + (size_t)d * WN)) + lane;
    asm volatile("red.global.add.v4.f32 [%0], {%1, %2, %3, %4};"
                 :: "l"(ap), "f"(v.x), "f"(v.y), "f"(v.z), "f"(v.w)
                 : "memory");
}

// ---------------- BN finalize ----------------
__global__ void bnfinal_kernel(const float* __restrict__ g, const float* __restrict__ be, int N) {
    int f = threadIdx.x;
    float inv = 1.0f / (float)N;
    float mu = g_stats[f] * inv;
    float var = g_stats[WN + f] * inv - mu * mu;
    float sc = g[f] * rsqrtf(var + 1e-5f);
    g_bnp[f] = sc;
    g_bnp[WN + f] = be[f] - mu * sc;
}

// ---------------- pooling ----------------
__global__ void pool_kernel(const float* __restrict__ z, const int* __restrict__ batch, int N) {
    int f = threadIdx.x;
    int r0 = blockIdx.x * 256;
    int r1 = min(r0 + 256, N);
    float cur = 0.f;
    int curg = -1;
    for (int r = r0; r < r1; ++r) {
        int gi = batch[r];
        if (gi != curg) {
            if (curg >= 0)
                atomicMax((int*)&g_pooled[(size_t)curg * WN + f], __float_as_int(cur));
            curg = gi;
            cur = 0.f;
        }
        cur = fmaxf(cur, z[(size_t)r * WN + f]);
    }
    if (curg >= 0)
        atomicMax((int*)&g_pooled[(size_t)curg * WN + f], __float_as_int(cur));
}

// ---------------- final tiny MLP ----------------
__global__ void final_kernel(const float* __restrict__ W5, const float* __restrict__ b5,
                             const float* __restrict__ g2, const float* __restrict__ be2,
                             const float* __restrict__ W6, const float* __restrict__ b6,
                             float* __restrict__ out, int G) {
    __shared__ float W5s[WN * 64];
    __shared__ float ys[GMAX][65];
    __shared__ float sc[64], sh[64];
    int tid = threadIdx.x;
    for (int i = tid; i < WN * 64; i += 256) W5s[i] = W5[i];
    __syncthreads();

    int g = tid & 63;
    int jb = tid >> 6;
    float acc[16];
#pragma unroll
    for (int j = 0; j < 16; ++j) acc[j] = 0.f;
    if (g < G) {
        for (int k = 0; k < WN; ++k) {
            float p = g_pooled[(size_t)g * WN + k];
#pragma unroll
            for (int j = 0; j < 16; ++j)
                acc[j] = fmaf(p, W5s[k * 64 + jb * 16 + j], acc[j]);
        }
#pragma unroll
        for (int j = 0; j < 16; ++j)
            ys[g][jb * 16 + j] = acc[j] + b5[jb * 16 + j];
    }
    __syncthreads();

    if (tid < 64) {
        float s = 0.f, q = 0.f;
        for (int r = 0; r < G; ++r) {
            float v = ys[r][tid];
            s += v;
            q += v * v;
        }
        float inv = 1.0f / (float)G;
        float mu = s * inv;
        float var = q * inv - mu * mu;
        float scale = g2[tid] * rsqrtf(var + 1e-5f);
        sc[tid] = scale;
        sh[tid] = be2[tid] - mu * scale;
    }
    __syncthreads();

    if (tid < G) {
        float o = b6[0];
        for (int j = 0; j < 64; ++j) {
            float v = fmaxf(0.f, fmaf(ys[tid][j], sc[j], sh[j]));
            o = fmaf(v, W6[j], o);
        }
        out[tid] = o;
    }
}

// ---------------- launch ----------------
extern "C" void kernel_launch(void* const* d_in, const int* in_sizes, int n_in,
                              void* d_out, int out_size) {
    const float* x   = (const float*)d_in[0];
    const int*   ei  = (const int*)d_in[1];
    const int*   bat = (const int*)d_in[2];
    const float* W1  = (const float*)d_in[3];
    const float* b1  = (const float*)d_in[4];
    const float* W2  = (const float*)d_in[5];
    const float* b2  = (const float*)d_in[6];
    const float* W3  = (const float*)d_in[7];
    const float* b3  = (const float*)d_in[8];
    const float* g1  = (const float*)d_in[9];
    const float* be1 = (const float*)d_in[10];
    const float* W4  = (const float*)d_in[11];
    const float* b4  = (const float*)d_in[12];
    const float* W5  = (const float*)d_in[13];
    const float* b5  = (const float*)d_in[14];
    const float* g2  = (const float*)d_in[15];
    const float* be2 = (const float*)d_in[16];
    const float* W6  = (const float*)d_in[17];
    const float* b6  = (const float*)d_in[18];

    int N = in_sizes[2];
    int E = in_sizes[1] / 2;
    int G = out_size;
    const int* src = ei;
    const int* dst = ei + E;

    float *B0, *B1, *B2;
    void *pcnt, *pstats, *ppooled;
    cudaGetSymbolAddress((void**)&B0, g_B0);
    cudaGetSymbolAddress((void**)&B1, g_B1);
    cudaGetSymbolAddress((void**)&B2, g_B2);
    cudaGetSymbolAddress(&pcnt, g_cnt);
    cudaGetSymbolAddress(&pstats, g_stats);
    cudaGetSymbolAddress(&ppooled, g_pooled);

    cudaMemsetAsync(pcnt, 0, (size_t)N * sizeof(int));
    cudaMemsetAsync(pstats, 0, 2 * WN * sizeof(float));
    cudaMemsetAsync(ppooled, 0, (size_t)G * WN * sizeof(float));

    deg_kernel<<<(E + 255) / 256, 256>>>(dst, E);
    dinv_kernel<<<(N + 255) / 256, 256>>>(N);

    int gb = (N + 127) / 128;
    int scat_blocks = (int)(((long long)E * 32 + 255) / 256);

    // smem: 2*(CH*WS) + 2*(128*AS) words = 2*(32*136) + 2*(128*36) = 17920 words
    int smemB = 17920 * 4;   // 71680 B -> 2 CTAs/SM
    cudaFuncSetAttribute(mma_gemm<32, 0, true, false>,
                         cudaFuncAttributeMaxDynamicSharedMemorySize, smemB);
    cudaFuncSetAttribute(mma_gemm<128, 1, true, false>,
                         cudaFuncAttributeMaxDynamicSharedMemorySize, smemB);
    cudaFuncSetAttribute(mma_gemm<128, 1, false, true>,
                         cudaFuncAttributeMaxDynamicSharedMemorySize, smemB);
    cudaFuncSetAttribute(mma_gemm<128, 2, false, false>,
                         cudaFuncAttributeMaxDynamicSharedMemorySize, smemB);

    // conv1: h=B0, agg(init self+bias)=B1; scatter into B1
    mma_gemm<32, 0, true, false><<<gb, 256, smemB>>>(x, W1, b1, B0, B1, N);
    scatter_kernel<<<scat_blocks, 256>>>(B0, src, dst, B1, E);

    // conv2: reads relu(B1); h=B0, agg=B2; scatter into B2
    mma_gemm<128, 1, true, false><<<gb, 256, smemB>>>(B1, W2, b2, B0, B2, N);
    scatter_kernel<<<scat_blocks, 256>>>(B0, src, dst, B2, E);

    // mlp_first: y = relu(B2)@W3 + b3 -> B1 (+BN stats) ; z = relu(bn(B1))@W4 + b4 -> B0
    mma_gemm<128, 1, false, true><<<gb, 256, smemB>>>(B2, W3, b3, B1, nullptr, N);
    bnfinal_kernel<<<1, 128>>>(g1, be1, N);
    mma_gemm<128, 2, false, false><<<gb, 256, smemB>>>(B1, W4, b4, B0, nullptr, N);

    // global max pool (relu folded via clamp at 0)
    pool_kernel<<<(N + 255) / 256, 128>>>(B0, bat, N);

    // final MLP
    final_kernel<<<1, 256>>>(W5, b5, g2, be2, W6, b6, (float*)d_out, G);
}

// round 6
// speedup vs baseline: 1.4819x; 1.1783x over previous
#include <cuda_runtime.h>

#define WN 128
#define NMAXN 100000
#define EMAX 600000
#define GMAX 64

// ---------------- scratch ----------------
__device__ float g_B0[(size_t)NMAXN * WN];
__device__ float g_B1[(size_t)NMAXN * WN];
__device__ float g_B2[(size_t)NMAXN * WN];
__device__ float g_dinv[NMAXN];
__device__ int   g_cnt[NMAXN];
__device__ int   g_rowtmp[NMAXN];
__device__ int   g_rowptr[NMAXN + 1];
__device__ int   g_cursor[NMAXN];
__device__ int   g_bsum[128];
__device__ int   g_boff[128];
__device__ int   g_csrc[EMAX];
__device__ float g_cdinv[EMAX];
__device__ float g_stats[2 * WN];
__device__ float g_bnp[2 * WN];
__device__ float g_pooled[GMAX * WN];

// ---------------- degree / dinv ----------------
__global__ void deg_kernel(const int* __restrict__ dst, int E) {
    int e = blockIdx.x * blockDim.x + threadIdx.x;
    if (e < E) atomicAdd(&g_cnt[dst[e]], 1);
}

__global__ void dinv_kernel(int N) {
    int i = blockIdx.x * blockDim.x + threadIdx.x;
    if (i < N) g_dinv[i] = rsqrtf((float)g_cnt[i] + 1.0f);
}

// ---------------- CSR build: scan of degrees, then bin ----------------
__global__ void scan1_kernel(int N) {
    __shared__ int sm[1024];
    int tid = threadIdx.x;
    int i = blockIdx.x * 1024 + tid;
    int v = (i < N) ? g_cnt[i] : 0;
    sm[tid] = v;
    __syncthreads();
#pragma unroll
    for (int o = 1; o < 1024; o <<= 1) {
        int t = 0;
        if (tid >= o) t = sm[tid - o];
        __syncthreads();
        if (tid >= o) sm[tid] += t;
        __syncthreads();
    }
    if (i < N) g_rowtmp[i] = sm[tid];           // inclusive scan within block
    if (tid == 1023) g_bsum[blockIdx.x] = sm[1023];
}

__global__ void scan2_kernel(int nb, int N) {
    if (threadIdx.x == 0) {
        int run = 0;
        for (int b = 0; b < nb; ++b) { g_boff[b] = run; run += g_bsum[b]; }
        g_rowptr[N] = run;
    }
}

__global__ void scan3_kernel(int N) {
    int i = blockIdx.x * blockDim.x + threadIdx.x;
    if (i < N) {
        int rp = g_rowtmp[i] - g_cnt[i] + g_boff[i >> 10];   // exclusive
        g_rowptr[i] = rp;
        g_cursor[i] = rp;
    }
}

__global__ void bin_kernel(const int* __restrict__ src, const int* __restrict__ dst, int E) {
    int e = blockIdx.x * blockDim.x + threadIdx.x;
    if (e >= E) return;
    int s = src[e], d = dst[e];
    int pos = atomicAdd(&g_cursor[d], 1);
    g_csrc[pos] = s;
    g_cdinv[pos] = g_dinv[s];
}

// ---------------- gather: out[d] = (Σ h[s]*dinv[s])*dinv[d] + h[d]*dinv[d]^2 + bias ----------------
__global__ void gather_kernel(const float* __restrict__ h, const float* __restrict__ bias,
                              float* __restrict__ out, int N) {
    int t = blockIdx.x * blockDim.x + threadIdx.x;
    int w = t >> 5;
    if (w >= N) return;
    int lane = t & 31;
    int p0 = g_rowptr[w], p1 = g_rowptr[w + 1];
    float4 acc = make_float4(0.f, 0.f, 0.f, 0.f);
    int e = p0;
    for (; e + 4 <= p1; e += 4) {
        int s0 = g_csrc[e], s1 = g_csrc[e + 1], s2 = g_csrc[e + 2], s3 = g_csrc[e + 3];
        float n0 = g_cdinv[e], n1 = g_cdinv[e + 1], n2 = g_cdinv[e + 2], n3 = g_cdinv[e + 3];
        float4 v0 = ((const float4*)(h + (size_t)s0 * WN))[lane];
        float4 v1 = ((const float4*)(h + (size_t)s1 * WN))[lane];
        float4 v2 = ((const float4*)(h + (size_t)s2 * WN))[lane];
        float4 v3 = ((const float4*)(h + (size_t)s3 * WN))[lane];
        acc.x = fmaf(v0.x, n0, acc.x); acc.y = fmaf(v0.y, n0, acc.y);
        acc.z = fmaf(v0.z, n0, acc.z); acc.w = fmaf(v0.w, n0, acc.w);
        acc.x = fmaf(v1.x, n1, acc.x); acc.y = fmaf(v1.y, n1, acc.y);
        acc.z = fmaf(v1.z, n1, acc.z); acc.w = fmaf(v1.w, n1, acc.w);
        acc.x = fmaf(v2.x, n2, acc.x); acc.y = fmaf(v2.y, n2, acc.y);
        acc.z = fmaf(v2.z, n2, acc.z); acc.w = fmaf(v2.w, n2, acc.w);
        acc.x = fmaf(v3.x, n3, acc.x); acc.y = fmaf(v3.y, n3, acc.y);
        acc.z = fmaf(v3.z, n3, acc.z); acc.w = fmaf(v3.w, n3, acc.w);
    }
    for (; e < p1; ++e) {
        int s = g_csrc[e];
        float n = g_cdinv[e];
        float4 v = ((const float4*)(h + (size_t)s * WN))[lane];
        acc.x = fmaf(v.x, n, acc.x); acc.y = fmaf(v.y, n, acc.y);
        acc.z = fmaf(v.z, n, acc.z); acc.w = fmaf(v.w, n, acc.w);
    }
    float dv = g_dinv[w];
    float d2 = dv * dv;
    float4 hd = ((const float4*)(h + (size_t)w * WN))[lane];
    float4 b = ((const float4*)bias)[lane];
    float4 o;
    o.x = fmaf(acc.x, dv, fmaf(hd.x, d2, b.x));
    o.y = fmaf(acc.y, dv, fmaf(hd.y, d2, b.y));
    o.z = fmaf(acc.z, dv, fmaf(hd.z, d2, b.z));
    o.w = fmaf(acc.w, dv, fmaf(hd.w, d2, b.w));
    ((float4*)(out + (size_t)w * WN))[lane] = o;
}

// ---------------- tf32 helpers ----------------
__device__ __forceinline__ unsigned cvt_tf32(float f) {
    unsigned u;
    asm("cvt.rna.tf32.f32 %0, %1;" : "=r"(u) : "f"(f));
    return u;
}
__device__ __forceinline__ void split_tf32(float f, unsigned& hi, unsigned& lo) {
    hi = cvt_tf32(f);
    lo = cvt_tf32(f - __uint_as_float(hi));
}
__device__ __forceinline__ void mma_tf32(float* c, const unsigned* a, const unsigned* b) {
    asm volatile(
        "mma.sync.aligned.m16n8k8.row.col.f32.tf32.tf32.f32 "
        "{%0,%1,%2,%3}, {%4,%5,%6,%7}, {%8,%9}, {%0,%1,%2,%3};"
        : "+f"(c[0]), "+f"(c[1]), "+f"(c[2]), "+f"(c[3])
        : "r"(a[0]), "r"(a[1]), "r"(a[2]), "r"(a[3]), "r"(b[0]), "r"(b[1]));
}

// ---------------- 3xTF32 tensor-core GEMM: C[M,128] = pro(A)[M,K] @ W[K,128] (+bias) ----------------
// PRO: 0 identity, 1 relu, 2 relu(BN affine via g_bnp). bias may be null.
// STATS: accumulate column sums/sumsq of C into g_stats.
template<int K, int PRO, bool STATS>
__global__ __launch_bounds__(256, 2) void mma_gemm(
        const float* __restrict__ A, const float* __restrict__ W,
        const float* __restrict__ bias, float* __restrict__ C, int M) {
    constexpr int CH = 32;
    constexpr int CQ = CH / 4;
    constexpr int AS = 36;
    constexpr int WS = 136;
    extern __shared__ unsigned smem[];
    unsigned* Wh = smem;
    unsigned* Wl = Wh + CH * WS;
    unsigned* Ah = Wl + CH * WS;
    unsigned* Al = Ah + 128 * AS;
    __shared__ float sstat[2 * WN];

    int tid = threadIdx.x;
    int lane = tid & 31, wid = tid >> 5;
    int wm = wid >> 1, wn = wid & 1;
    int row0 = blockIdx.x * 128;

    if (STATS) sstat[tid] = 0.f;

    float acc[2][8][4];
#pragma unroll
    for (int mt = 0; mt < 2; ++mt)
#pragma unroll
        for (int nt = 0; nt < 8; ++nt)
#pragma unroll
            for (int q = 0; q < 4; ++q) acc[mt][nt][q] = 0.f;

    for (int kb = 0; kb < K; kb += CH) {
        __syncthreads();
        for (int i = tid; i < CH * 32; i += 256) {
            int k = i >> 5, c = (i & 31) * 4;
            float4 v = *(const float4*)(W + (size_t)(kb + k) * WN + c);
            uint4 th, tl;
            split_tf32(v.x, th.x, tl.x);
            split_tf32(v.y, th.y, tl.y);
            split_tf32(v.z, th.z, tl.z);
            split_tf32(v.w, th.w, tl.w);
            *(uint4*)&Wh[k * WS + c] = th;
            *(uint4*)&Wl[k * WS + c] = tl;
        }
        for (int i = tid; i < 128 * CQ; i += 256) {
            int r = i >> 3, q = (i & 7) * 4;
            float4 v = make_float4(0.f, 0.f, 0.f, 0.f);
            if (row0 + r < M)
                v = *(const float4*)(A + (size_t)(row0 + r) * K + kb + q);
            if (PRO == 1) {
                v.x = fmaxf(0.f, v.x); v.y = fmaxf(0.f, v.y);
                v.z = fmaxf(0.f, v.z); v.w = fmaxf(0.f, v.w);
            } else if (PRO == 2) {
                int kg = kb + q;
                v.x = fmaxf(0.f, fmaf(v.x, g_bnp[kg + 0], g_bnp[WN + kg + 0]));
                v.y = fmaxf(0.f, fmaf(v.y, g_bnp[kg + 1], g_bnp[WN + kg + 1]));
                v.z = fmaxf(0.f, fmaf(v.z, g_bnp[kg + 2], g_bnp[WN + kg + 2]));
                v.w = fmaxf(0.f, fmaf(v.w, g_bnp[kg + 3], g_bnp[WN + kg + 3]));
            }
            uint4 th, tl;
            split_tf32(v.x, th.x, tl.x);
            split_tf32(v.y, th.y, tl.y);
            split_tf32(v.z, th.z, tl.z);
            split_tf32(v.w, th.w, tl.w);
            *(uint4*)&Ah[r * AS + q] = th;
            *(uint4*)&Al[r * AS + q] = tl;
        }
        __syncthreads();

#pragma unroll
        for (int ks = 0; ks < CH / 8; ++ks) {
            int ka = ks * 8 + (lane & 3);
            unsigned ah[2][4], al[2][4];
            int r = wm * 32 + (lane >> 2);
#pragma unroll
            for (int mt = 0; mt < 2; ++mt) {
                const unsigned* ph = &Ah[(r + mt * 16) * AS + ka];
                const unsigned* pl = &Al[(r + mt * 16) * AS + ka];
                ah[mt][0] = ph[0]; ah[mt][1] = ph[8 * AS];
                ah[mt][2] = ph[4]; ah[mt][3] = ph[8 * AS + 4];
                al[mt][0] = pl[0]; al[mt][1] = pl[8 * AS];
                al[mt][2] = pl[4]; al[mt][3] = pl[8 * AS + 4];
            }
#pragma unroll
            for (int nh = 0; nh < 2; ++nh) {
                unsigned bh[4][2], bl[4][2];
#pragma unroll
                for (int j = 0; j < 4; ++j) {
                    int c = wn * 64 + (nh * 4 + j) * 8 + (lane >> 2);
                    bh[j][0] = Wh[ka * WS + c];
                    bh[j][1] = Wh[(ka + 4) * WS + c];
                    bl[j][0] = Wl[ka * WS + c];
                    bl[j][1] = Wl[(ka + 4) * WS + c];
                }
#pragma unroll
                for (int mt = 0; mt < 2; ++mt)
#pragma unroll
                    for (int j = 0; j < 4; ++j) {
                        float* cc = acc[mt][nh * 4 + j];
                        mma_tf32(cc, al[mt], bh[j]);
                        mma_tf32(cc, ah[mt], bl[j]);
                        mma_tf32(cc, ah[mt], bh[j]);
                    }
            }
        }
    }

    // ---------------- epilogue ----------------
    float ss[16], sq[16];
    if (STATS) {
#pragma unroll
        for (int i = 0; i < 16; ++i) { ss[i] = 0.f; sq[i] = 0.f; }
    }

#pragma unroll
    for (int mt = 0; mt < 2; ++mt) {
#pragma unroll
        for (int h = 0; h < 2; ++h) {
            int row = row0 + wm * 32 + mt * 16 + (lane >> 2) + h * 8;
            bool ok = row < M;
#pragma unroll
            for (int nt = 0; nt < 8; ++nt) {
                int col = wn * 64 + nt * 8 + (lane & 3) * 2;
                float b0 = bias ? bias[col] : 0.f;
                float b1 = bias ? bias[col + 1] : 0.f;
                float o0 = acc[mt][nt][h * 2 + 0] + b0;
                float o1 = acc[mt][nt][h * 2 + 1] + b1;
                if (ok)
                    *(float2*)(C + (size_t)row * WN + col) = make_float2(o0, o1);
                if (STATS) {
                    if (!ok) { o0 = 0.f; o1 = 0.f; }
                    ss[nt * 2 + 0] += o0; sq[nt * 2 + 0] += o0 * o0;
                    ss[nt * 2 + 1] += o1; sq[nt * 2 + 1] += o1 * o1;
                }
            }
        }
    }

    if (STATS) {
#pragma unroll
        for (int i = 0; i < 16; ++i) {
#pragma unroll
            for (int o = 4; o <= 16; o <<= 1) {
                ss[i] += __shfl_xor_sync(0xffffffffu, ss[i], o);
                sq[i] += __shfl_xor_sync(0xffffffffu, sq[i], o);
            }
        }
        if (lane < 4) {
#pragma unroll
            for (int nt = 0; nt < 8; ++nt)
#pragma unroll
                for (int c = 0; c < 2; ++c) {
                    int col = wn * 64 + nt * 8 + lane * 2 + c;
                    atomicAdd(&sstat[col], ss[nt * 2 + c]);
                    atomicAdd(&sstat[WN + col], sq[nt * 2 + c]);
                }
        }
        __syncthreads();
        atomicAdd(&g_stats[tid], sstat[tid]);
    }
}

// ---------------- BN finalize ----------------
__global__ void bnfinal_kernel(const float* __restrict__ g, const float* __restrict__ be, int N) {
    int f = threadIdx.x;
    float inv = 1.0f / (float)N;
    float mu = g_stats[f] * inv;
    float var = g_stats[WN + f] * inv - mu * mu;
    float sc = g[f] * rsqrtf(var + 1e-5f);
    g_bnp[f] = sc;
    g_bnp[WN + f] = be[f] - mu * sc;
}

// ---------------- pooling ----------------
__global__ void pool_kernel(const float* __restrict__ z, const int* __restrict__ batch, int N) {
    int f = threadIdx.x;
    int r0 = blockIdx.x * 256;
    int r1 = min(r0 + 256, N);
    float cur = 0.f;
    int curg = -1;
    for (int r = r0; r < r1; ++r) {
        int gi = batch[r];
        if (gi != curg) {
            if (curg >= 0)
                atomicMax((int*)&g_pooled[(size_t)curg * WN + f], __float_as_int(cur));
            curg = gi;
            cur = 0.f;
        }
        cur = fmaxf(cur, z[(size_t)r * WN + f]);
    }
    if (curg >= 0)
        atomicMax((int*)&g_pooled[(size_t)curg * WN + f], __float_as_int(cur));
}

// ---------------- final tiny MLP ----------------
__global__ void final_kernel(const float* __restrict__ W5, const float* __restrict__ b5,
                             const float* __restrict__ g2, const float* __restrict__ be2,
                             const float* __restrict__ W6, const float* __restrict__ b6,
                             float* __restrict__ out, int G) {
    __shared__ float W5s[WN * 64];
    __shared__ float ys[GMAX][65];
    __shared__ float sc[64], sh[64];
    int tid = threadIdx.x;
    for (int i = tid; i < WN * 64; i += 256) W5s[i] = W5[i];
    __syncthreads();

    int g = tid & 63;
    int jb = tid >> 6;
    float acc[16];
#pragma unroll
    for (int j = 0; j < 16; ++j) acc[j] = 0.f;
    if (g < G) {
        for (int k = 0; k < WN; ++k) {
            float p = g_pooled[(size_t)g * WN + k];
#pragma unroll
            for (int j = 0; j < 16; ++j)
                acc[j] = fmaf(p, W5s[k * 64 + jb * 16 + j], acc[j]);
        }
#pragma unroll
        for (int j = 0; j < 16; ++j)
            ys[g][jb * 16 + j] = acc[j] + b5[jb * 16 + j];
    }
    __syncthreads();

    if (tid < 64) {
        float s = 0.f, q = 0.f;
        for (int r = 0; r < G; ++r) {
            float v = ys[r][tid];
            s += v;
            q += v * v;
        }
        float inv = 1.0f / (float)G;
        float mu = s * inv;
        float var = q * inv - mu * mu;
        float scale = g2[tid] * rsqrtf(var + 1e-5f);
        sc[tid] = scale;
        sh[tid] = be2[tid] - mu * scale;
    }
    __syncthreads();

    if (tid < G) {
        float o = b6[0];
        for (int j = 0; j < 64; ++j) {
            float v = fmaxf(0.f, fmaf(ys[tid][j], sc[j], sh[j]));
            o = fmaf(v, W6[j], o);
        }
        out[tid] = o;
    }
}

// ---------------- launch ----------------
extern "C" void kernel_launch(void* const* d_in, const int* in_sizes, int n_in,
                              void* d_out, int out_size) {
    const float* x   = (const float*)d_in[0];
    const int*   ei  = (const int*)d_in[1];
    const int*   bat = (const int*)d_in[2];
    const float* W1  = (const float*)d_in[3];
    const float* b1  = (const float*)d_in[4];
    const float* W2  = (const float*)d_in[5];
    const float* b2  = (const float*)d_in[6];
    const float* W3  = (const float*)d_in[7];
    const float* b3  = (const float*)d_in[8];
    const float* g1  = (const float*)d_in[9];
    const float* be1 = (const float*)d_in[10];
    const float* W4  = (const float*)d_in[11];
    const float* b4  = (const float*)d_in[12];
    const float* W5  = (const float*)d_in[13];
    const float* b5  = (const float*)d_in[14];
    const float* g2  = (const float*)d_in[15];
    const float* be2 = (const float*)d_in[16];
    const float* W6  = (const float*)d_in[17];
    const float* b6  = (const float*)d_in[18];

    int N = in_sizes[2];
    int E = in_sizes[1] / 2;
    int G = out_size;
    const int* src = ei;
    const int* dst = ei + E;

    float *B0, *B1, *B2;
    void *pcnt, *pstats, *ppooled;
    cudaGetSymbolAddress((void**)&B0, g_B0);
    cudaGetSymbolAddress((void**)&B1, g_B1);
    cudaGetSymbolAddress((void**)&B2, g_B2);
    cudaGetSymbolAddress(&pcnt, g_cnt);
    cudaGetSymbolAddress(&pstats, g_stats);
    cudaGetSymbolAddress(&ppooled, g_pooled);

    cudaMemsetAsync(pcnt, 0, (size_t)N * sizeof(int));
    cudaMemsetAsync(pstats, 0, 2 * WN * sizeof(float));
    cudaMemsetAsync(ppooled, 0, (size_t)G * WN * sizeof(float));

    // CSR build
    deg_kernel<<<(E + 255) / 256, 256>>>(dst, E);
    dinv_kernel<<<(N + 255) / 256, 256>>>(N);
    int nb = (N + 1023) / 1024;
    scan1_kernel<<<nb, 1024>>>(N);
    scan2_kernel<<<1, 32>>>(nb, N);
    scan3_kernel<<<(N + 255) / 256, 256>>>(N);
    bin_kernel<<<(E + 255) / 256, 256>>>(src, dst, E);

    int gb = (N + 127) / 128;
    int gather_blocks = (int)(((long long)N * 32 + 255) / 256);

    int smemB = 17920 * 4;   // 71680 B -> 2 CTAs/SM
    cudaFuncSetAttribute(mma_gemm<32, 0, false>,
                         cudaFuncAttributeMaxDynamicSharedMemorySize, smemB);
    cudaFuncSetAttribute(mma_gemm<128, 1, false>,
                         cudaFuncAttributeMaxDynamicSharedMemorySize, smemB);
    cudaFuncSetAttribute(mma_gemm<128, 1, true>,
                         cudaFuncAttributeMaxDynamicSharedMemorySize, smemB);
    cudaFuncSetAttribute(mma_gemm<128, 2, false>,
                         cudaFuncAttributeMaxDynamicSharedMemorySize, smemB);

    // conv1: h=B0 (raw); gather -> B1 (adds self + bias)
    mma_gemm<32, 0, false><<<gb, 256, smemB>>>(x, W1, nullptr, B0, N);
    gather_kernel<<<gather_blocks, 256>>>(B0, b1, B1, N);

    // conv2: reads relu(B1); h=B0; gather -> B2
    mma_gemm<128, 1, false><<<gb, 256, smemB>>>(B1, W2, nullptr, B0, N);
    gather_kernel<<<gather_blocks, 256>>>(B0, b2, B2, N);

    // mlp_first: y = relu(B2)@W3 + b3 -> B1 (+BN stats) ; z = relu(bn(B1))@W4 + b4 -> B0
    mma_gemm<128, 1, true><<<gb, 256, smemB>>>(B2, W3, b3, B1, N);
    bnfinal_kernel<<<1, 128>>>(g1, be1, N);
    mma_gemm<128, 2, false><<<gb, 256, smemB>>>(B1, W4, b4, B0, N);

    // global max pool (relu folded via clamp at 0)
    pool_kernel<<<(N + 255) / 256, 128>>>(B0, bat, N);

    // final MLP
    final_kernel<<<1, 256>>>(W5, b5, g2, be2, W6, b6, (float*)d_out, G);
}

// round 7
// speedup vs baseline: 1.6351x; 1.1033x over previous
#include <cuda_runtime.h>

#define WN 128
#define NMAXN 100000
#define EMAX 600000
#define GMAX 64

// ---------------- scratch ----------------
__device__ float g_B0[(size_t)NMAXN * WN];
__device__ float g_B1[(size_t)NMAXN * WN];
__device__ float g_B2[(size_t)NMAXN * WN];
__device__ float g_dinv[NMAXN];
__device__ int   g_cnt[NMAXN];
__device__ int   g_rowtmp[NMAXN];
__device__ int   g_rowptr[NMAXN + 1];
__device__ int   g_cursor[NMAXN];
__device__ int   g_bsum[128];
__device__ int   g_boff[128];
__device__ int   g_csrc[EMAX];
__device__ float g_cdinv[EMAX];
__device__ float g_stats[2 * WN];
__device__ float g_bnp[2 * WN];
__device__ float g_pooled[GMAX * WN];

// ---------------- degree / dinv ----------------
__global__ void deg_kernel(const int* __restrict__ dst, int E) {
    int e = blockIdx.x * blockDim.x + threadIdx.x;
    if (e < E) atomicAdd(&g_cnt[dst[e]], 1);
}

__global__ void dinv_kernel(int N) {
    int i = blockIdx.x * blockDim.x + threadIdx.x;
    if (i < N) g_dinv[i] = rsqrtf((float)g_cnt[i] + 1.0f);
}

// ---------------- CSR build ----------------
__global__ void scan1_kernel(int N) {
    __shared__ int sm[1024];
    int tid = threadIdx.x;
    int i = blockIdx.x * 1024 + tid;
    int v = (i < N) ? g_cnt[i] : 0;
    sm[tid] = v;
    __syncthreads();
#pragma unroll
    for (int o = 1; o < 1024; o <<= 1) {
        int t = 0;
        if (tid >= o) t = sm[tid - o];
        __syncthreads();
        if (tid >= o) sm[tid] += t;
        __syncthreads();
    }
    if (i < N) g_rowtmp[i] = sm[tid];
    if (tid == 1023) g_bsum[blockIdx.x] = sm[1023];
}

__global__ void scan2_kernel(int nb, int N) {
    __shared__ int sm[128];
    int t = threadIdx.x;
    int v = (t < nb) ? g_bsum[t] : 0;
    sm[t] = v;
    __syncthreads();
#pragma unroll
    for (int o = 1; o < 128; o <<= 1) {
        int u = 0;
        if (t >= o) u = sm[t - o];
        __syncthreads();
        if (t >= o) sm[t] += u;
        __syncthreads();
    }
    if (t < nb) g_boff[t] = sm[t] - v;   // exclusive
    if (t == 127) g_rowptr[N] = sm[127];
}

__global__ void scan3_kernel(int N) {
    int i = blockIdx.x * blockDim.x + threadIdx.x;
    if (i < N) {
        int rp = g_rowtmp[i] - g_cnt[i] + g_boff[i >> 10];
        g_rowptr[i] = rp;
        g_cursor[i] = rp;
    }
}

__global__ void bin_kernel(const int* __restrict__ src, const int* __restrict__ dst, int E) {
    int e = blockIdx.x * blockDim.x + threadIdx.x;
    if (e >= E) return;
    int s = src[e], d = dst[e];
    int pos = atomicAdd(&g_cursor[d], 1);
    g_csrc[pos] = s;
    g_cdinv[pos] = g_dinv[s];
}

// ---------------- gather: out[d] = (Σ h[s]*dinv[s])*dinv[d] + h[d]*dinv[d]^2 + bias ----------------
__global__ void gather_kernel(const float* __restrict__ h, const float* __restrict__ bias,
                              float* __restrict__ out, int N) {
    int t = blockIdx.x * blockDim.x + threadIdx.x;
    int w = t >> 5;
    if (w >= N) return;
    int lane = t & 31;
    int p0 = g_rowptr[w], p1 = g_rowptr[w + 1];
    float4 acc = make_float4(0.f, 0.f, 0.f, 0.f);
    int e = p0;
    for (; e + 4 <= p1; e += 4) {
        int s0 = g_csrc[e], s1 = g_csrc[e + 1], s2 = g_csrc[e + 2], s3 = g_csrc[e + 3];
        float n0 = g_cdinv[e], n1 = g_cdinv[e + 1], n2 = g_cdinv[e + 2], n3 = g_cdinv[e + 3];
        float4 v0 = ((const float4*)(h + (size_t)s0 * WN))[lane];
        float4 v1 = ((const float4*)(h + (size_t)s1 * WN))[lane];
        float4 v2 = ((const float4*)(h + (size_t)s2 * WN))[lane];
        float4 v3 = ((const float4*)(h + (size_t)s3 * WN))[lane];
        acc.x = fmaf(v0.x, n0, acc.x); acc.y = fmaf(v0.y, n0, acc.y);
        acc.z = fmaf(v0.z, n0, acc.z); acc.w = fmaf(v0.w, n0, acc.w);
        acc.x = fmaf(v1.x, n1, acc.x); acc.y = fmaf(v1.y, n1, acc.y);
        acc.z = fmaf(v1.z, n1, acc.z); acc.w = fmaf(v1.w, n1, acc.w);
        acc.x = fmaf(v2.x, n2, acc.x); acc.y = fmaf(v2.y, n2, acc.y);
        acc.z = fmaf(v2.z, n2, acc.z); acc.w = fmaf(v2.w, n2, acc.w);
        acc.x = fmaf(v3.x, n3, acc.x); acc.y = fmaf(v3.y, n3, acc.y);
        acc.z = fmaf(v3.z, n3, acc.z); acc.w = fmaf(v3.w, n3, acc.w);
    }
    for (; e < p1; ++e) {
        int s = g_csrc[e];
        float n = g_cdinv[e];
        float4 v = ((const float4*)(h + (size_t)s * WN))[lane];
        acc.x = fmaf(v.x, n, acc.x); acc.y = fmaf(v.y, n, acc.y);
        acc.z = fmaf(v.z, n, acc.z); acc.w = fmaf(v.w, n, acc.w);
    }
    float dv = g_dinv[w];
    float d2 = dv * dv;
    float4 hd = ((const float4*)(h + (size_t)w * WN))[lane];
    float4 b = ((const float4*)bias)[lane];
    float4 o;
    o.x = fmaf(acc.x, dv, fmaf(hd.x, d2, b.x));
    o.y = fmaf(acc.y, dv, fmaf(hd.y, d2, b.y));
    o.z = fmaf(acc.z, dv, fmaf(hd.z, d2, b.z));
    o.w = fmaf(acc.w, dv, fmaf(hd.w, d2, b.w));
    ((float4*)(out + (size_t)w * WN))[lane] = o;
}

// ---------------- tf32 helpers ----------------
__device__ __forceinline__ unsigned cvt_tf32(float f) {
    unsigned u;
    asm("cvt.rna.tf32.f32 %0, %1;" : "=r"(u) : "f"(f));
    return u;
}
__device__ __forceinline__ void split_tf32(float f, unsigned& hi, unsigned& lo) {
    hi = cvt_tf32(f);
    lo = cvt_tf32(f - __uint_as_float(hi));
}
__device__ __forceinline__ void mma_tf32(float* c, const unsigned* a, const unsigned* b) {
    asm volatile(
        "mma.sync.aligned.m16n8k8.row.col.f32.tf32.tf32.f32 "
        "{%0,%1,%2,%3}, {%4,%5,%6,%7}, {%8,%9}, {%0,%1,%2,%3};"
        : "+f"(c[0]), "+f"(c[1]), "+f"(c[2]), "+f"(c[3])
        : "r"(a[0]), "r"(a[1]), "r"(a[2]), "r"(a[3]), "r"(b[0]), "r"(b[1]));
}

// ---------------- 3xTF32 tensor-core GEMM: C[M,128] = pro(A)[M,K] @ W[K,128] (+bias) ----------------
// PRO: 0 identity, 1 relu, 2 relu(BN affine via g_bnp). bias may be null.
// STATS: accumulate column sums/sumsq of C into g_stats.
// POOL: no C write; atomicMax(relu(acc+bias)) into g_pooled[batch[row]].
template<int K, int PRO, bool STATS, bool POOL>
__global__ __launch_bounds__(256, 2) void mma_gemm(
        const float* __restrict__ A, const float* __restrict__ W,
        const float* __restrict__ bias, float* __restrict__ C,
        const int* __restrict__ batch, int M) {
    constexpr int CH = 32;
    constexpr int CQ = CH / 4;
    constexpr int AS = 36;
    constexpr int WS = 136;
    extern __shared__ unsigned smem[];
    unsigned* Wh = smem;
    unsigned* Wl = Wh + CH * WS;
    unsigned* Ah = Wl + CH * WS;
    unsigned* Al = Ah + 128 * AS;
    __shared__ float sstat[2 * WN];

    int tid = threadIdx.x;
    int lane = tid & 31, wid = tid >> 5;
    int wm = wid >> 1, wn = wid & 1;
    int row0 = blockIdx.x * 128;

    if (STATS) sstat[tid] = 0.f;

    float acc[2][8][4];
#pragma unroll
    for (int mt = 0; mt < 2; ++mt)
#pragma unroll
        for (int nt = 0; nt < 8; ++nt)
#pragma unroll
            for (int q = 0; q < 4; ++q) acc[mt][nt][q] = 0.f;

    for (int kb = 0; kb < K; kb += CH) {
        __syncthreads();
        for (int i = tid; i < CH * 32; i += 256) {
            int k = i >> 5, c = (i & 31) * 4;
            float4 v = *(const float4*)(W + (size_t)(kb + k) * WN + c);
            uint4 th, tl;
            split_tf32(v.x, th.x, tl.x);
            split_tf32(v.y, th.y, tl.y);
            split_tf32(v.z, th.z, tl.z);
            split_tf32(v.w, th.w, tl.w);
            *(uint4*)&Wh[k * WS + c] = th;
            *(uint4*)&Wl[k * WS + c] = tl;
        }
        for (int i = tid; i < 128 * CQ; i += 256) {
            int r = i >> 3, q = (i & 7) * 4;
            float4 v = make_float4(0.f, 0.f, 0.f, 0.f);
            if (row0 + r < M)
                v = *(const float4*)(A + (size_t)(row0 + r) * K + kb + q);
            if (PRO == 1) {
                v.x = fmaxf(0.f, v.x); v.y = fmaxf(0.f, v.y);
                v.z = fmaxf(0.f, v.z); v.w = fmaxf(0.f, v.w);
            } else if (PRO == 2) {
                int kg = kb + q;
                v.x = fmaxf(0.f, fmaf(v.x, g_bnp[kg + 0], g_bnp[WN + kg + 0]));
                v.y = fmaxf(0.f, fmaf(v.y, g_bnp[kg + 1], g_bnp[WN + kg + 1]));
                v.z = fmaxf(0.f, fmaf(v.z, g_bnp[kg + 2], g_bnp[WN + kg + 2]));
                v.w = fmaxf(0.f, fmaf(v.w, g_bnp[kg + 3], g_bnp[WN + kg + 3]));
            }
            uint4 th, tl;
            split_tf32(v.x, th.x, tl.x);
            split_tf32(v.y, th.y, tl.y);
            split_tf32(v.z, th.z, tl.z);
            split_tf32(v.w, th.w, tl.w);
            *(uint4*)&Ah[r * AS + q] = th;
            *(uint4*)&Al[r * AS + q] = tl;
        }
        __syncthreads();

#pragma unroll
        for (int ks = 0; ks < CH / 8; ++ks) {
            int ka = ks * 8 + (lane & 3);
            unsigned ah[2][4], al[2][4];
            int r = wm * 32 + (lane >> 2);
#pragma unroll
            for (int mt = 0; mt < 2; ++mt) {
                const unsigned* ph = &Ah[(r + mt * 16) * AS + ka];
                const unsigned* pl = &Al[(r + mt * 16) * AS + ka];
                ah[mt][0] = ph[0]; ah[mt][1] = ph[8 * AS];
                ah[mt][2] = ph[4]; ah[mt][3] = ph[8 * AS + 4];
                al[mt][0] = pl[0]; al[mt][1] = pl[8 * AS];
                al[mt][2] = pl[4]; al[mt][3] = pl[8 * AS + 4];
            }
#pragma unroll
            for (int nh = 0; nh < 2; ++nh) {
                unsigned bh[4][2], bl[4][2];
#pragma unroll
                for (int j = 0; j < 4; ++j) {
                    int c = wn * 64 + (nh * 4 + j) * 8 + (lane >> 2);
                    bh[j][0] = Wh[ka * WS + c];
                    bh[j][1] = Wh[(ka + 4) * WS + c];
                    bl[j][0] = Wl[ka * WS + c];
                    bl[j][1] = Wl[(ka + 4) * WS + c];
                }
#pragma unroll
                for (int mt = 0; mt < 2; ++mt)
#pragma unroll
                    for (int j = 0; j < 4; ++j) {
                        float* cc = acc[mt][nh * 4 + j];
                        mma_tf32(cc, al[mt], bh[j]);
                        mma_tf32(cc, ah[mt], bl[j]);
                        mma_tf32(cc, ah[mt], bh[j]);
                    }
            }
        }
    }

    // ---------------- epilogue ----------------
    if (POOL) {
        // rows handled by this thread: rbase + {0, 8, 16, 24}  (t = mt*2 + h)
        int rbase = row0 + wm * 32 + (lane >> 2);
        int bt[4];
#pragma unroll
        for (int t = 0; t < 4; ++t) {
            int r = rbase + t * 8;
            bt[t] = (r < M) ? batch[r] : -1;
        }
        bool same = (bt[0] == bt[1]) && (bt[1] == bt[2]) && (bt[2] == bt[3]) && (bt[0] >= 0);
#pragma unroll
        for (int nt = 0; nt < 8; ++nt) {
#pragma unroll
            for (int c = 0; c < 2; ++c) {
                int col = wn * 64 + nt * 8 + (lane & 3) * 2 + c;
                float bb = bias[col];
                float v[4];
                v[0] = fmaxf(0.f, acc[0][nt][c] + bb);       // mt0,h0
                v[1] = fmaxf(0.f, acc[0][nt][2 + c] + bb);   // mt0,h1
                v[2] = fmaxf(0.f, acc[1][nt][c] + bb);       // mt1,h0
                v[3] = fmaxf(0.f, acc[1][nt][2 + c] + bb);   // mt1,h1
                if (same) {
                    float m = fmaxf(fmaxf(v[0], v[1]), fmaxf(v[2], v[3]));
                    atomicMax((int*)&g_pooled[(size_t)bt[0] * WN + col], __float_as_int(m));
                } else {
#pragma unroll
                    for (int t = 0; t < 4; ++t)
                        if (bt[t] >= 0)
                            atomicMax((int*)&g_pooled[(size_t)bt[t] * WN + col],
                                      __float_as_int(v[t]));
                }
            }
        }
        return;
    }

    float ss[16], sq[16];
    if (STATS) {
#pragma unroll
        for (int i = 0; i < 16; ++i) { ss[i] = 0.f; sq[i] = 0.f; }
    }

#pragma unroll
    for (int mt = 0; mt < 2; ++mt) {
#pragma unroll
        for (int h = 0; h < 2; ++h) {
            int row = row0 + wm * 32 + mt * 16 + (lane >> 2) + h * 8;
            bool ok = row < M;
#pragma unroll
            for (int nt = 0; nt < 8; ++nt) {
                int col = wn * 64 + nt * 8 + (lane & 3) * 2;
                float b0 = bias ? bias[col] : 0.f;
                float b1 = bias ? bias[col + 1] : 0.f;
                float o0 = acc[mt][nt][h * 2 + 0] + b0;
                float o1 = acc[mt][nt][h * 2 + 1] + b1;
                if (ok)
                    *(float2*)(C + (size_t)row * WN + col) = make_float2(o0, o1);
                if (STATS) {
                    if (!ok) { o0 = 0.f; o1 = 0.f; }
                    ss[nt * 2 + 0] += o0; sq[nt * 2 + 0] += o0 * o0;
                    ss[nt * 2 + 1] += o1; sq[nt * 2 + 1] += o1 * o1;
                }
            }
        }
    }

    if (STATS) {
#pragma unroll
        for (int i = 0; i < 16; ++i) {
#pragma unroll
            for (int o = 4; o <= 16; o <<= 1) {
                ss[i] += __shfl_xor_sync(0xffffffffu, ss[i], o);
                sq[i] += __shfl_xor_sync(0xffffffffu, sq[i], o);
            }
        }
        if (lane < 4) {
#pragma unroll
            for (int nt = 0; nt < 8; ++nt)
#pragma unroll
                for (int c = 0; c < 2; ++c) {
                    int col = wn * 64 + nt * 8 + lane * 2 + c;
                    atomicAdd(&sstat[col], ss[nt * 2 + c]);
                    atomicAdd(&sstat[WN + col], sq[nt * 2 + c]);
                }
        }
        __syncthreads();
        atomicAdd(&g_stats[tid], sstat[tid]);
    }
}

// ---------------- BN finalize ----------------
__global__ void bnfinal_kernel(const float* __restrict__ g, const float* __restrict__ be, int N) {
    int f = threadIdx.x;
    float inv = 1.0f / (float)N;
    float mu = g_stats[f] * inv;
    float var = g_stats[WN + f] * inv - mu * mu;
    float sc = g[f] * rsqrtf(var + 1e-5f);
    g_bnp[f] = sc;
    g_bnp[WN + f] = be[f] - mu * sc;
}

// ---------------- final tiny MLP ----------------
__global__ void final_kernel(const float* __restrict__ W5, const float* __restrict__ b5,
                             const float* __restrict__ g2, const float* __restrict__ be2,
                             const float* __restrict__ W6, const float* __restrict__ b6,
                             float* __restrict__ out, int G) {
    __shared__ float W5s[WN * 64];
    __shared__ float ys[GMAX][65];
    __shared__ float sc[64], sh[64];
    int tid = threadIdx.x;
    for (int i = tid; i < WN * 64; i += 256) W5s[i] = W5[i];
    __syncthreads();

    int g = tid & 63;
    int jb = tid >> 6;
    float acc[16];
#pragma unroll
    for (int j = 0; j < 16; ++j) acc[j] = 0.f;
    if (g < G) {
        for (int k = 0; k < WN; ++k) {
            float p = g_pooled[(size_t)g * WN + k];
#pragma unroll
            for (int j = 0; j < 16; ++j)
                acc[j] = fmaf(p, W5s[k * 64 + jb * 16 + j], acc[j]);
        }
#pragma unroll
        for (int j = 0; j < 16; ++j)
            ys[g][jb * 16 + j] = acc[j] + b5[jb * 16 + j];
    }
    __syncthreads();

    if (tid < 64) {
        float s = 0.f, q = 0.f;
        for (int r = 0; r < G; ++r) {
            float v = ys[r][tid];
            s += v;
            q += v * v;
        }
        float inv = 1.0f / (float)G;
        float mu = s * inv;
        float var = q * inv - mu * mu;
        float scale = g2[tid] * rsqrtf(var + 1e-5f);
        sc[tid] = scale;
        sh[tid] = be2[tid] - mu * scale;
    }
    __syncthreads();

    if (tid < G) {
        float o = b6[0];
        for (int j = 0; j < 64; ++j) {
            float v = fmaxf(0.f, fmaf(ys[tid][j], sc[j], sh[j]));
            o = fmaf(v, W6[j], o);
        }
        out[tid] = o;
    }
}

// ---------------- launch ----------------
extern "C" void kernel_launch(void* const* d_in, const int* in_sizes, int n_in,
                              void* d_out, int out_size) {
    const float* x   = (const float*)d_in[0];
    const int*   ei  = (const int*)d_in[1];
    const int*   bat = (const int*)d_in[2];
    const float* W1  = (const float*)d_in[3];
    const float* b1  = (const float*)d_in[4];
    const float* W2  = (const float*)d_in[5];
    const float* b2  = (const float*)d_in[6];
    const float* W3  = (const float*)d_in[7];
    const float* b3  = (const float*)d_in[8];
    const float* g1  = (const float*)d_in[9];
    const float* be1 = (const float*)d_in[10];
    const float* W4  = (const float*)d_in[11];
    const float* b4  = (const float*)d_in[12];
    const float* W5  = (const float*)d_in[13];
    const float* b5  = (const float*)d_in[14];
    const float* g2  = (const float*)d_in[15];
    const float* be2 = (const float*)d_in[16];
    const float* W6  = (const float*)d_in[17];
    const float* b6  = (const float*)d_in[18];

    int N = in_sizes[2];
    int E = in_sizes[1] / 2;
    int G = out_size;
    const int* src = ei;
    const int* dst = ei + E;

    float *B0, *B1, *B2;
    void *pcnt, *pstats, *ppooled;
    cudaGetSymbolAddress((void**)&B0, g_B0);
    cudaGetSymbolAddress((void**)&B1, g_B1);
    cudaGetSymbolAddress((void**)&B2, g_B2);
    cudaGetSymbolAddress(&pcnt, g_cnt);
    cudaGetSymbolAddress(&pstats, g_stats);
    cudaGetSymbolAddress(&ppooled, g_pooled);

    // side stream + events (host objects, created once)
    static cudaStream_t s2 = nullptr;
    static cudaEvent_t evA = nullptr, evB = nullptr;
    if (!s2) {
        cudaStreamCreateWithFlags(&s2, cudaStreamNonBlocking);
        cudaEventCreateWithFlags(&evA, cudaEventDisableTiming);
        cudaEventCreateWithFlags(&evB, cudaEventDisableTiming);
    }

    int nb = (N + 1023) / 1024;
    int gb = (N + 127) / 128;
    int gather_blocks = (int)(((long long)N * 32 + 255) / 256);
    int smemB = 17920 * 4;   // 71680 B -> 2 CTAs/SM

    cudaFuncSetAttribute(mma_gemm<32, 0, false, false>,
                         cudaFuncAttributeMaxDynamicSharedMemorySize, smemB);
    cudaFuncSetAttribute(mma_gemm<128, 1, false, false>,
                         cudaFuncAttributeMaxDynamicSharedMemorySize, smemB);
    cudaFuncSetAttribute(mma_gemm<128, 1, true, false>,
                         cudaFuncAttributeMaxDynamicSharedMemorySize, smemB);
    cudaFuncSetAttribute(mma_gemm<128, 2, false, true>,
                         cudaFuncAttributeMaxDynamicSharedMemorySize, smemB);

    // ---- fork: CSR build on side stream, GEMM1 on main stream ----
    cudaEventRecord(evA, 0);
    cudaStreamWaitEvent(s2, evA, 0);

    cudaMemsetAsync(pcnt, 0, (size_t)N * sizeof(int), s2);
    deg_kernel<<<(E + 255) / 256, 256, 0, s2>>>(dst, E);
    dinv_kernel<<<(N + 255) / 256, 256, 0, s2>>>(N);
    scan1_kernel<<<nb, 1024, 0, s2>>>(N);
    scan2_kernel<<<1, 128, 0, s2>>>(nb, N);
    scan3_kernel<<<(N + 255) / 256, 256, 0, s2>>>(N);
    bin_kernel<<<(E + 255) / 256, 256, 0, s2>>>(src, dst, E);
    cudaEventRecord(evB, s2);

    cudaMemsetAsync(pstats, 0, 2 * WN * sizeof(float));
    cudaMemsetAsync(ppooled, 0, (size_t)G * WN * sizeof(float));

    // conv1 GEMM: h = x@W1 -> B0 (independent of CSR)
    mma_gemm<32, 0, false, false><<<gb, 256, smemB>>>(x, W1, nullptr, B0, nullptr, N);

    // join: gather needs CSR + dinv
    cudaStreamWaitEvent(0, evB, 0);
    gather_kernel<<<gather_blocks, 256>>>(B0, b1, B1, N);

    // conv2: reads relu(B1); h=B0; gather -> B2
    mma_gemm<128, 1, false, false><<<gb, 256, smemB>>>(B1, W2, nullptr, B0, nullptr, N);
    gather_kernel<<<gather_blocks, 256>>>(B0, b2, B2, N);

    // mlp_first: y = relu(B2)@W3 + b3 -> B1 (+BN stats) ; z = relu(bn(B1))@W4 + b4, fused max-pool
    mma_gemm<128, 1, true, false><<<gb, 256, smemB>>>(B2, W3, b3, B1, nullptr, N);
    bnfinal_kernel<<<1, 128>>>(g1, be1, N);
    mma_gemm<128, 2, false, true><<<gb, 256, smemB>>>(B1, W4, b4, nullptr, bat, N);

    // final MLP
    final_kernel<<<1, 256>>>(W5, b5, g2, be2, W6, b6, (float*)d_out, G);
}

// round 8
// speedup vs baseline: 1.9758x; 1.2084x over previous
#include <cuda_runtime.h>

#define WN 128
#define NMAXN 100000
#define EMAX 600000
#define GMAX 64

// ---------------- scratch ----------------
__device__ float g_B0[(size_t)NMAXN * WN];
__device__ float g_B1[(size_t)NMAXN * WN];
__device__ float g_B2[(size_t)NMAXN * WN];
__device__ float g_dinv[NMAXN];
__device__ int   g_cnt[NMAXN];
__device__ int   g_rowtmp[NMAXN];
__device__ int   g_rowptr[NMAXN + 1];
__device__ int   g_cursor[NMAXN];
__device__ int   g_bsum[128];
__device__ int   g_boff[128];
__device__ int   g_csrc[EMAX];
__device__ float g_cdinv[EMAX];
__device__ float g_stats[2 * WN];
__device__ float g_bnp[2 * WN];
__device__ float g_pooled[GMAX * WN];

// ---------------- degree / dinv ----------------
__global__ void deg_kernel(const int* __restrict__ dst, int E) {
    int e = blockIdx.x * blockDim.x + threadIdx.x;
    if (e < E) atomicAdd(&g_cnt[dst[e]], 1);
}

__global__ void dinv_kernel(int N) {
    int i = blockIdx.x * blockDim.x + threadIdx.x;
    if (i < N) g_dinv[i] = rsqrtf((float)g_cnt[i] + 1.0f);
}

// ---------------- CSR build ----------------
__global__ void scan1_kernel(int N) {
    __shared__ int sm[1024];
    int tid = threadIdx.x;
    int i = blockIdx.x * 1024 + tid;
    int v = (i < N) ? g_cnt[i] : 0;
    sm[tid] = v;
    __syncthreads();
#pragma unroll
    for (int o = 1; o < 1024; o <<= 1) {
        int t = 0;
        if (tid >= o) t = sm[tid - o];
        __syncthreads();
        if (tid >= o) sm[tid] += t;
        __syncthreads();
    }
    if (i < N) g_rowtmp[i] = sm[tid];
    if (tid == 1023) g_bsum[blockIdx.x] = sm[1023];
}

__global__ void scan2_kernel(int nb, int N) {
    __shared__ int sm[128];
    int t = threadIdx.x;
    int v = (t < nb) ? g_bsum[t] : 0;
    sm[t] = v;
    __syncthreads();
#pragma unroll
    for (int o = 1; o < 128; o <<= 1) {
        int u = 0;
        if (t >= o) u = sm[t - o];
        __syncthreads();
        if (t >= o) sm[t] += u;
        __syncthreads();
    }
    if (t < nb) g_boff[t] = sm[t] - v;
    if (t == 127) g_rowptr[N] = sm[127];
}

__global__ void scan3_kernel(int N) {
    int i = blockIdx.x * blockDim.x + threadIdx.x;
    if (i < N) {
        int rp = g_rowtmp[i] - g_cnt[i] + g_boff[i >> 10];
        g_rowptr[i] = rp;
        g_cursor[i] = rp;
    }
}

__global__ void bin_kernel(const int* __restrict__ src, const int* __restrict__ dst, int E) {
    int e = blockIdx.x * blockDim.x + threadIdx.x;
    if (e >= E) return;
    int s = src[e], d = dst[e];
    int pos = atomicAdd(&g_cursor[d], 1);
    g_csrc[pos] = s;
    g_cdinv[pos] = g_dinv[s];
}

// ---------------- gather_x (32-wide): out[d] = (Σ x[s]*dinv[s])*dinv[d] + x[d]*dinv[d]^2 ----------------
__global__ void gatherx_kernel(const float* __restrict__ x, float* __restrict__ out, int N) {
    int t = blockIdx.x * blockDim.x + threadIdx.x;
    int w = t >> 5;
    if (w >= N) return;
    int lane = t & 31;
    int p0 = g_rowptr[w], p1 = g_rowptr[w + 1];
    float acc = 0.f;
    int e = p0;
    for (; e + 4 <= p1; e += 4) {
        int s0 = g_csrc[e], s1 = g_csrc[e + 1], s2 = g_csrc[e + 2], s3 = g_csrc[e + 3];
        float n0 = g_cdinv[e], n1 = g_cdinv[e + 1], n2 = g_cdinv[e + 2], n3 = g_cdinv[e + 3];
        acc = fmaf(x[(size_t)s0 * 32 + lane], n0, acc);
        acc = fmaf(x[(size_t)s1 * 32 + lane], n1, acc);
        acc = fmaf(x[(size_t)s2 * 32 + lane], n2, acc);
        acc = fmaf(x[(size_t)s3 * 32 + lane], n3, acc);
    }
    for (; e < p1; ++e)
        acc = fmaf(x[(size_t)g_csrc[e] * 32 + lane], g_cdinv[e], acc);
    float dv = g_dinv[w];
    out[(size_t)w * 32 + lane] = fmaf(acc, dv, x[(size_t)w * 32 + lane] * dv * dv);
}

// ---------------- gather (128-wide): out[d] = (Σ h[s]*dinv[s])*dinv[d] + h[d]*dinv[d]^2 + bias ----------------
__global__ void gather_kernel(const float* __restrict__ h, const float* __restrict__ bias,
                              float* __restrict__ out, int N) {
    int t = blockIdx.x * blockDim.x + threadIdx.x;
    int w = t >> 5;
    if (w >= N) return;
    int lane = t & 31;
    int p0 = g_rowptr[w], p1 = g_rowptr[w + 1];
    float4 acc = make_float4(0.f, 0.f, 0.f, 0.f);
    int e = p0;
    for (; e + 4 <= p1; e += 4) {
        int s0 = g_csrc[e], s1 = g_csrc[e + 1], s2 = g_csrc[e + 2], s3 = g_csrc[e + 3];
        float n0 = g_cdinv[e], n1 = g_cdinv[e + 1], n2 = g_cdinv[e + 2], n3 = g_cdinv[e + 3];
        float4 v0 = ((const float4*)(h + (size_t)s0 * WN))[lane];
        float4 v1 = ((const float4*)(h + (size_t)s1 * WN))[lane];
        float4 v2 = ((const float4*)(h + (size_t)s2 * WN))[lane];
        float4 v3 = ((const float4*)(h + (size_t)s3 * WN))[lane];
        acc.x = fmaf(v0.x, n0, acc.x); acc.y = fmaf(v0.y, n0, acc.y);
        acc.z = fmaf(v0.z, n0, acc.z); acc.w = fmaf(v0.w, n0, acc.w);
        acc.x = fmaf(v1.x, n1, acc.x); acc.y = fmaf(v1.y, n1, acc.y);
        acc.z = fmaf(v1.z, n1, acc.z); acc.w = fmaf(v1.w, n1, acc.w);
        acc.x = fmaf(v2.x, n2, acc.x); acc.y = fmaf(v2.y, n2, acc.y);
        acc.z = fmaf(v2.z, n2, acc.z); acc.w = fmaf(v2.w, n2, acc.w);
        acc.x = fmaf(v3.x, n3, acc.x); acc.y = fmaf(v3.y, n3, acc.y);
        acc.z = fmaf(v3.z, n3, acc.z); acc.w = fmaf(v3.w, n3, acc.w);
    }
    for (; e < p1; ++e) {
        int s = g_csrc[e];
        float n = g_cdinv[e];
        float4 v = ((const float4*)(h + (size_t)s * WN))[lane];
        acc.x = fmaf(v.x, n, acc.x); acc.y = fmaf(v.y, n, acc.y);
        acc.z = fmaf(v.z, n, acc.z); acc.w = fmaf(v.w, n, acc.w);
    }
    float dv = g_dinv[w];
    float d2 = dv * dv;
    float4 hd = ((const float4*)(h + (size_t)w * WN))[lane];
    float4 b = ((const float4*)bias)[lane];
    float4 o;
    o.x = fmaf(acc.x, dv, fmaf(hd.x, d2, b.x));
    o.y = fmaf(acc.y, dv, fmaf(hd.y, d2, b.y));
    o.z = fmaf(acc.z, dv, fmaf(hd.z, d2, b.z));
    o.w = fmaf(acc.w, dv, fmaf(hd.w, d2, b.w));
    ((float4*)(out + (size_t)w * WN))[lane] = o;
}

// ---------------- bf16 2-split helpers ----------------
__device__ __forceinline__ void split_bf16(float x, unsigned short& h, float& r) {
    asm("cvt.rn.bf16.f32 %0, %1;" : "=h"(h) : "f"(x));
    r = x - __uint_as_float(((unsigned)h) << 16);
}
__device__ __forceinline__ unsigned packf_bf16x2(float lo_, float hi_) {
    unsigned u;
    asm("cvt.rn.bf16x2.f32 %0, %1, %2;" : "=r"(u) : "f"(hi_), "f"(lo_));
    return u;
}
// pair (a = k even, b = k odd) -> hi word, lo word (a in low half)
__device__ __forceinline__ void split_pair(float a, float b, unsigned& hi, unsigned& lo) {
    unsigned short ha, hb;
    float ra, rb;
    split_bf16(a, ha, ra);
    split_bf16(b, hb, rb);
    hi = ((unsigned)hb << 16) | (unsigned)ha;
    lo = packf_bf16x2(ra, rb);
}
__device__ __forceinline__ void mma_bf16(float* c, const unsigned* a, const unsigned* b) {
    asm volatile(
        "mma.sync.aligned.m16n8k16.row.col.f32.bf16.bf16.f32 "
        "{%0,%1,%2,%3}, {%4,%5,%6,%7}, {%8,%9}, {%0,%1,%2,%3};"
        : "+f"(c[0]), "+f"(c[1]), "+f"(c[2]), "+f"(c[3])
        : "r"(a[0]), "r"(a[1]), "r"(a[2]), "r"(a[3]), "r"(b[0]), "r"(b[1]));
}

// ---------------- 3x bf16-split tensor-core GEMM: C[M,128] = pro(A)[M,K] @ W[K,128] (+bias) ----------------
// PRO: 0 identity, 1 relu, 2 relu(BN affine via g_bnp). bias may be null.
// STATS: accumulate column sums/sumsq. POOL: no C write; atomicMax into g_pooled[batch[row]].
template<int K, int PRO, bool STATS, bool POOL>
__global__ __launch_bounds__(256, 2) void mma_gemm(
        const float* __restrict__ A, const float* __restrict__ W,
        const float* __restrict__ bias, float* __restrict__ C,
        const int* __restrict__ batch, int M) {
    constexpr int CH = 32;          // k per chunk
    constexpr int ST = 20;          // smem stride in u32 (16 kpairs + pad)
    extern __shared__ unsigned smem[];
    unsigned* Ah = smem;            // [128][ST]
    unsigned* Al = smem + 2560;
    unsigned* Wh = smem + 5120;     // [128 cols][ST] (n-major, packed kpairs)
    unsigned* Wl = smem + 7680;
    __shared__ float sstat[2 * WN];

    int tid = threadIdx.x;
    int lane = tid & 31, wid = tid >> 5;
    int wm = wid >> 1, wn = wid & 1;
    int gr = lane >> 2;
    int row0 = blockIdx.x * 128;

    if (STATS) sstat[tid] = 0.f;

    float acc[2][8][4];
#pragma unroll
    for (int mt = 0; mt < 2; ++mt)
#pragma unroll
        for (int nt = 0; nt < 8; ++nt)
#pragma unroll
            for (int q = 0; q < 4; ++q) acc[mt][nt][q] = 0.f;

    for (int kb = 0; kb < K; kb += CH) {
        __syncthreads();
        // stage W chunk, transposed to n-major packed kpairs (hi/lo)
        for (int i = tid; i < 128 * (CH / 2); i += 256) {
            int c = i & 127, kp = i >> 7;
            float w0 = W[(size_t)(kb + 2 * kp) * WN + c];
            float w1 = W[(size_t)(kb + 2 * kp + 1) * WN + c];
            unsigned h, l;
            split_pair(w0, w1, h, l);
            Wh[c * ST + kp] = h;
            Wl[c * ST + kp] = l;
        }
        // stage A chunk with prologue (hi/lo)
        for (int i = tid; i < 128 * (CH / 4); i += 256) {
            int r = i >> 3, q = i & 7;
            float4 v = make_float4(0.f, 0.f, 0.f, 0.f);
            if (row0 + r < M)
                v = *(const float4*)(A + (size_t)(row0 + r) * K + kb + 4 * q);
            if (PRO == 1) {
                v.x = fmaxf(0.f, v.x); v.y = fmaxf(0.f, v.y);
                v.z = fmaxf(0.f, v.z); v.w = fmaxf(0.f, v.w);
            } else if (PRO == 2) {
                int kg = kb + 4 * q;
                v.x = fmaxf(0.f, fmaf(v.x, g_bnp[kg + 0], g_bnp[WN + kg + 0]));
                v.y = fmaxf(0.f, fmaf(v.y, g_bnp[kg + 1], g_bnp[WN + kg + 1]));
                v.z = fmaxf(0.f, fmaf(v.z, g_bnp[kg + 2], g_bnp[WN + kg + 2]));
                v.w = fmaxf(0.f, fmaf(v.w, g_bnp[kg + 3], g_bnp[WN + kg + 3]));
            }
            unsigned h0, l0, h1, l1;
            split_pair(v.x, v.y, h0, l0);
            split_pair(v.z, v.w, h1, l1);
            *(uint2*)&Ah[r * ST + 2 * q] = make_uint2(h0, h1);
            *(uint2*)&Al[r * ST + 2 * q] = make_uint2(l0, l1);
        }
        __syncthreads();

#pragma unroll
        for (int ks = 0; ks < CH / 16; ++ks) {
            int kc = ks * 8 + (lane & 3);
            unsigned ah[2][4], al[2][4];
#pragma unroll
            for (int mt = 0; mt < 2; ++mt) {
                int r = wm * 32 + mt * 16 + gr;
                const unsigned* ph = &Ah[r * ST + kc];
                const unsigned* pl = &Al[r * ST + kc];
                ah[mt][0] = ph[0]; ah[mt][1] = ph[8 * ST];
                ah[mt][2] = ph[4]; ah[mt][3] = ph[8 * ST + 4];
                al[mt][0] = pl[0]; al[mt][1] = pl[8 * ST];
                al[mt][2] = pl[4]; al[mt][3] = pl[8 * ST + 4];
            }
#pragma unroll
            for (int nh = 0; nh < 2; ++nh) {
                unsigned bh[4][2], bl[4][2];
#pragma unroll
                for (int j = 0; j < 4; ++j) {
                    int c = wn * 64 + (nh * 4 + j) * 8 + gr;
                    bh[j][0] = Wh[c * ST + kc];
                    bh[j][1] = Wh[c * ST + kc + 4];
                    bl[j][0] = Wl[c * ST + kc];
                    bl[j][1] = Wl[c * ST + kc + 4];
                }
#pragma unroll
                for (int mt = 0; mt < 2; ++mt)
#pragma unroll
                    for (int j = 0; j < 4; ++j) {
                        float* cc = acc[mt][nh * 4 + j];
                        mma_bf16(cc, al[mt], bh[j]);   // small terms first
                        mma_bf16(cc, ah[mt], bl[j]);
                        mma_bf16(cc, ah[mt], bh[j]);
                    }
            }
        }
    }

    // ---------------- epilogue ----------------
    if (POOL) {
        int rbase = row0 + wm * 32 + gr;
        int bt[4];
#pragma unroll
        for (int t = 0; t < 4; ++t) {
            int r = rbase + t * 8;
            bt[t] = (r < M) ? batch[r] : -1;
        }
        bool same = (bt[0] == bt[1]) && (bt[1] == bt[2]) && (bt[2] == bt[3]) && (bt[0] >= 0);
#pragma unroll
        for (int nt = 0; nt < 8; ++nt) {
#pragma unroll
            for (int c = 0; c < 2; ++c) {
                int col = wn * 64 + nt * 8 + (lane & 3) * 2 + c;
                float bb = bias[col];
                float v[4];
                v[0] = fmaxf(0.f, acc[0][nt][c] + bb);
                v[1] = fmaxf(0.f, acc[0][nt][2 + c] + bb);
                v[2] = fmaxf(0.f, acc[1][nt][c] + bb);
                v[3] = fmaxf(0.f, acc[1][nt][2 + c] + bb);
                if (same) {
                    float m = fmaxf(fmaxf(v[0], v[1]), fmaxf(v[2], v[3]));
                    atomicMax((int*)&g_pooled[(size_t)bt[0] * WN + col], __float_as_int(m));
                } else {
#pragma unroll
                    for (int t = 0; t < 4; ++t)
                        if (bt[t] >= 0)
                            atomicMax((int*)&g_pooled[(size_t)bt[t] * WN + col],
                                      __float_as_int(v[t]));
                }
            }
        }
        return;
    }

    float ss[16], sq[16];
    if (STATS) {
#pragma unroll
        for (int i = 0; i < 16; ++i) { ss[i] = 0.f; sq[i] = 0.f; }
    }

#pragma unroll
    for (int mt = 0; mt < 2; ++mt) {
#pragma unroll
        for (int h = 0; h < 2; ++h) {
            int row = row0 + wm * 32 + mt * 16 + gr + h * 8;
            bool ok = row < M;
#pragma unroll
            for (int nt = 0; nt < 8; ++nt) {
                int col = wn * 64 + nt * 8 + (lane & 3) * 2;
                float b0 = bias ? bias[col] : 0.f;
                float b1 = bias ? bias[col + 1] : 0.f;
                float o0 = acc[mt][nt][h * 2 + 0] + b0;
                float o1 = acc[mt][nt][h * 2 + 1] + b1;
                if (ok)
                    *(float2*)(C + (size_t)row * WN + col) = make_float2(o0, o1);
                if (STATS) {
                    if (!ok) { o0 = 0.f; o1 = 0.f; }
                    ss[nt * 2 + 0] += o0; sq[nt * 2 + 0] += o0 * o0;
                    ss[nt * 2 + 1] += o1; sq[nt * 2 + 1] += o1 * o1;
                }
            }
        }
    }

    if (STATS) {
#pragma unroll
        for (int i = 0; i < 16; ++i) {
#pragma unroll
            for (int o = 4; o <= 16; o <<= 1) {
                ss[i] += __shfl_xor_sync(0xffffffffu, ss[i], o);
                sq[i] += __shfl_xor_sync(0xffffffffu, sq[i], o);
            }
        }
        if (lane < 4) {
#pragma unroll
            for (int nt = 0; nt < 8; ++nt)
#pragma unroll
                for (int c = 0; c < 2; ++c) {
                    int col = wn * 64 + nt * 8 + lane * 2 + c;
                    atomicAdd(&sstat[col], ss[nt * 2 + c]);
                    atomicAdd(&sstat[WN + col], sq[nt * 2 + c]);
                }
        }
        __syncthreads();
        atomicAdd(&g_stats[tid], sstat[tid]);
    }
}

// ---------------- BN finalize ----------------
__global__ void bnfinal_kernel(const float* __restrict__ g, const float* __restrict__ be, int N) {
    int f = threadIdx.x;
    float inv = 1.0f / (float)N;
    float mu = g_stats[f] * inv;
    float var = g_stats[WN + f] * inv - mu * mu;
    float sc = g[f] * rsqrtf(var + 1e-5f);
    g_bnp[f] = sc;
    g_bnp[WN + f] = be[f] - mu * sc;
}

// ---------------- final tiny MLP ----------------
__global__ void final_kernel(const float* __restrict__ W5, const float* __restrict__ b5,
                             const float* __restrict__ g2, const float* __restrict__ be2,
                             const float* __restrict__ W6, const float* __restrict__ b6,
                             float* __restrict__ out, int G) {
    __shared__ float W5s[WN * 64];
    __shared__ float ys[GMAX][65];
    __shared__ float sc[64], sh[64];
    int tid = threadIdx.x;
    for (int i = tid; i < WN * 64; i += 256) W5s[i] = W5[i];
    __syncthreads();

    int g = tid & 63;
    int jb = tid >> 6;
    float acc[16];
#pragma unroll
    for (int j = 0; j < 16; ++j) acc[j] = 0.f;
    if (g < G) {
        for (int k = 0; k < WN; ++k) {
            float p = g_pooled[(size_t)g * WN + k];
#pragma unroll
            for (int j = 0; j < 16; ++j)
                acc[j] = fmaf(p, W5s[k * 64 + jb * 16 + j], acc[j]);
        }
#pragma unroll
        for (int j = 0; j < 16; ++j)
            ys[g][jb * 16 + j] = acc[j] + b5[jb * 16 + j];
    }
    __syncthreads();

    if (tid < 64) {
        float s = 0.f, q = 0.f;
        for (int r = 0; r < G; ++r) {
            float v = ys[r][tid];
            s += v;
            q += v * v;
        }
        float inv = 1.0f / (float)G;
        float mu = s * inv;
        float var = q * inv - mu * mu;
        float scale = g2[tid] * rsqrtf(var + 1e-5f);
        sc[tid] = scale;
        sh[tid] = be2[tid] - mu * scale;
    }
    __syncthreads();

    if (tid < G) {
        float o = b6[0];
        for (int j = 0; j < 64; ++j) {
            float v = fmaxf(0.f, fmaf(ys[tid][j], sc[j], sh[j]));
            o = fmaf(v, W6[j], o);
        }
        out[tid] = o;
    }
}

// ---------------- launch ----------------
extern "C" void kernel_launch(void* const* d_in, const int* in_sizes, int n_in,
                              void* d_out, int out_size) {
    const float* x   = (const float*)d_in[0];
    const int*   ei  = (const int*)d_in[1];
    const int*   bat = (const int*)d_in[2];
    const float* W1  = (const float*)d_in[3];
    const float* b1  = (const float*)d_in[4];
    const float* W2  = (const float*)d_in[5];
    const float* b2  = (const float*)d_in[6];
    const float* W3  = (const float*)d_in[7];
    const float* b3  = (const float*)d_in[8];
    const float* g1  = (const float*)d_in[9];
    const float* be1 = (const float*)d_in[10];
    const float* W4  = (const float*)d_in[11];
    const float* b4  = (const float*)d_in[12];
    const float* W5  = (const float*)d_in[13];
    const float* b5  = (const float*)d_in[14];
    const float* g2  = (const float*)d_in[15];
    const float* be2 = (const float*)d_in[16];
    const float* W6  = (const float*)d_in[17];
    const float* b6  = (const float*)d_in[18];

    int N = in_sizes[2];
    int E = in_sizes[1] / 2;
    int G = out_size;
    const int* src = ei;
    const int* dst = ei + E;

    float *B0, *B1, *B2;
    void *pcnt, *pstats, *ppooled;
    cudaGetSymbolAddress((void**)&B0, g_B0);
    cudaGetSymbolAddress((void**)&B1, g_B1);
    cudaGetSymbolAddress((void**)&B2, g_B2);
    cudaGetSymbolAddress(&pcnt, g_cnt);
    cudaGetSymbolAddress(&pstats, g_stats);
    cudaGetSymbolAddress(&ppooled, g_pooled);

    static cudaStream_t s2 = nullptr;
    static cudaEvent_t evA = nullptr, evB = nullptr;
    if (!s2) {
        cudaStreamCreateWithFlags(&s2, cudaStreamNonBlocking);
        cudaEventCreateWithFlags(&evA, cudaEventDisableTiming);
        cudaEventCreateWithFlags(&evB, cudaEventDisableTiming);
    }

    int nb = (N + 1023) / 1024;
    int gb = (N + 127) / 128;
    int gather_blocks = (int)(((long long)N * 32 + 255) / 256);
    int smemB = 10240 * 4;   // 40960 B

    cudaFuncSetAttribute(mma_gemm<32, 0, false, false>,
                         cudaFuncAttributeMaxDynamicSharedMemorySize, smemB);
    cudaFuncSetAttribute(mma_gemm<128, 1, false, false>,
                         cudaFuncAttributeMaxDynamicSharedMemorySize, smemB);
    cudaFuncSetAttribute(mma_gemm<128, 1, true, false>,
                         cudaFuncAttributeMaxDynamicSharedMemorySize, smemB);
    cudaFuncSetAttribute(mma_gemm<128, 2, false, true>,
                         cudaFuncAttributeMaxDynamicSharedMemorySize, smemB);

    // ---- fork: CSR build + gather_x on side stream ----
    cudaEventRecord(evA, 0);
    cudaStreamWaitEvent(s2, evA, 0);

    cudaMemsetAsync(pcnt, 0, (size_t)N * sizeof(int), s2);
    deg_kernel<<<(E + 255) / 256, 256, 0, s2>>>(dst, E);
    dinv_kernel<<<(N + 255) / 256, 256, 0, s2>>>(N);
    scan1_kernel<<<nb, 1024, 0, s2>>>(N);
    scan2_kernel<<<1, 128, 0, s2>>>(nb, N);
    scan3_kernel<<<(N + 255) / 256, 256, 0, s2>>>(N);
    bin_kernel<<<(E + 255) / 256, 256, 0, s2>>>(src, dst, E);
    gatherx_kernel<<<gather_blocks, 256, 0, s2>>>(x, B2, N);   // Xs = S_norm * x -> B2
    cudaEventRecord(evB, s2);

    cudaMemsetAsync(pstats, 0, 2 * WN * sizeof(float));
    cudaMemsetAsync(ppooled, 0, (size_t)G * WN * sizeof(float));

    // join
    cudaStreamWaitEvent(0, evB, 0);

    // conv1: B1 = Xs @ W1 + b1   (conv1 output, pre-relu)
    mma_gemm<32, 0, false, false><<<gb, 256, smemB>>>(B2, W1, b1, B1, nullptr, N);

    // conv2: h2 = relu(B1)@W2 -> B0 ; gather -> B2 (adds self + b2)
    mma_gemm<128, 1, false, false><<<gb, 256, smemB>>>(B1, W2, nullptr, B0, nullptr, N);
    gather_kernel<<<gather_blocks, 256>>>(B0, b2, B2, N);

    // mlp_first: y = relu(B2)@W3 + b3 -> B1 (+BN stats); z = relu(bn(B1))@W4 + b4, fused max-pool
    mma_gemm<128, 1, true, false><<<gb, 256, smemB>>>(B2, W3, b3, B1, nullptr, N);
    bnfinal_kernel<<<1, 128>>>(g1, be1, N);
    mma_gemm<128, 2, false, true><<<gb, 256, smemB>>>(B1, W4, b4, nullptr, bat, N);

    // final MLP
    final_kernel<<<1, 256>>>(W5, b5, g2, be2, W6, b6, (float*)d_out, G);
}

// round 9
// speedup vs baseline: 2.1388x; 1.0825x over previous
#include <cuda_runtime.h>

#define WN 128
#define NMAXN 100000
#define EMAX 600000
#define GMAX 64

// ---------------- scratch ----------------
__device__ float g_B0[(size_t)NMAXN * WN];
__device__ float g_B1[(size_t)NMAXN * WN];
__device__ float g_B2[(size_t)NMAXN * WN];
__device__ unsigned g_S0h[(size_t)NMAXN * 64];
__device__ unsigned g_S0l[(size_t)NMAXN * 64];
__device__ unsigned g_S1h[(size_t)NMAXN * 64];
__device__ unsigned g_S1l[(size_t)NMAXN * 64];
__device__ unsigned g_Wsh[4 * 8192];
__device__ unsigned g_Wsl[4 * 8192];
__device__ float g_dinv[NMAXN];
__device__ int   g_cnt[NMAXN];
__device__ int   g_rowtmp[NMAXN];
__device__ int   g_rowptr[NMAXN + 1];
__device__ int   g_cursor[NMAXN];
__device__ int   g_bsum[128];
__device__ int   g_boff[128];
__device__ int   g_csrc[EMAX];
__device__ float g_cdinv[EMAX];
__device__ float g_stats[2 * WN];
__device__ float g_bnp[2 * WN];
__device__ float g_pooled[GMAX * WN];

// ---------------- bf16 2-split helpers ----------------
__device__ __forceinline__ void split_bf16(float x, unsigned short& h, float& r) {
    asm("cvt.rn.bf16.f32 %0, %1;" : "=h"(h) : "f"(x));
    r = x - __uint_as_float(((unsigned)h) << 16);
}
__device__ __forceinline__ unsigned packf_bf16x2(float lo_, float hi_) {
    unsigned u;
    asm("cvt.rn.bf16x2.f32 %0, %1, %2;" : "=r"(u) : "f"(hi_), "f"(lo_));
    return u;
}
__device__ __forceinline__ void split_pair(float a, float b, unsigned& hi, unsigned& lo) {
    unsigned short ha, hb;
    float ra, rb;
    split_bf16(a, ha, ra);
    split_bf16(b, hb, rb);
    hi = ((unsigned)hb << 16) | (unsigned)ha;
    lo = packf_bf16x2(ra, rb);
}
__device__ __forceinline__ void mma_bf16(float* c, const unsigned* a, const unsigned* b) {
    asm volatile(
        "mma.sync.aligned.m16n8k16.row.col.f32.bf16.bf16.f32 "
        "{%0,%1,%2,%3}, {%4,%5,%6,%7}, {%8,%9}, {%0,%1,%2,%3};"
        : "+f"(c[0]), "+f"(c[1]), "+f"(c[2]), "+f"(c[3])
        : "r"(a[0]), "r"(a[1]), "r"(a[2]), "r"(a[3]), "r"(b[0]), "r"(b[1]));
}

// ---------------- degree / dinv ----------------
__global__ void deg_kernel(const int* __restrict__ dst, int E) {
    int e = blockIdx.x * blockDim.x + threadIdx.x;
    if (e < E) atomicAdd(&g_cnt[dst[e]], 1);
}

__global__ void dinv_kernel(int N) {
    int i = blockIdx.x * blockDim.x + threadIdx.x;
    if (i < N) g_dinv[i] = rsqrtf((float)g_cnt[i] + 1.0f);
}

// ---------------- CSR build ----------------
__global__ void scan1_kernel(int N) {
    __shared__ int sm[1024];
    int tid = threadIdx.x;
    int i = blockIdx.x * 1024 + tid;
    int v = (i < N) ? g_cnt[i] : 0;
    sm[tid] = v;
    __syncthreads();
#pragma unroll
    for (int o = 1; o < 1024; o <<= 1) {
        int t = 0;
        if (tid >= o) t = sm[tid - o];
        __syncthreads();
        if (tid >= o) sm[tid] += t;
        __syncthreads();
    }
    if (i < N) g_rowtmp[i] = sm[tid];
    if (tid == 1023) g_bsum[blockIdx.x] = sm[1023];
}

__global__ void scan2_kernel(int nb, int N) {
    __shared__ int sm[128];
    int t = threadIdx.x;
    int v = (t < nb) ? g_bsum[t] : 0;
    sm[t] = v;
    __syncthreads();
#pragma unroll
    for (int o = 1; o < 128; o <<= 1) {
        int u = 0;
        if (t >= o) u = sm[t - o];
        __syncthreads();
        if (t >= o) sm[t] += u;
        __syncthreads();
    }
    if (t < nb) g_boff[t] = sm[t] - v;
    if (t == 127) g_rowptr[N] = sm[127];
}

__global__ void scan3_kernel(int N) {
    int i = blockIdx.x * blockDim.x + threadIdx.x;
    if (i < N) {
        int rp = g_rowtmp[i] - g_cnt[i] + g_boff[i >> 10];
        g_rowptr[i] = rp;
        g_cursor[i] = rp;
    }
}

__global__ void bin_kernel(const int* __restrict__ src, const int* __restrict__ dst, int E) {
    int e = blockIdx.x * blockDim.x + threadIdx.x;
    if (e >= E) return;
    int s = src[e], d = dst[e];
    int pos = atomicAdd(&g_cursor[d], 1);
    g_csrc[pos] = s;
    g_cdinv[pos] = g_dinv[s];
}

// ---------------- W split: oh/ol[c*KP+kp] = split(W[2kp][c], W[2kp+1][c]) ----------------
__global__ void wsplit_kernel(const float* __restrict__ W, unsigned* __restrict__ oh,
                              unsigned* __restrict__ ol, int K) {
    int i = blockIdx.x * blockDim.x + threadIdx.x;
    int KP = K >> 1;
    if (i >= 128 * KP) return;
    int c = i / KP, kp = i % KP;
    unsigned h, l;
    split_pair(W[(size_t)(2 * kp) * WN + c], W[(size_t)(2 * kp + 1) * WN + c], h, l);
    oh[i] = h;
    ol[i] = l;
}

// ---------------- gather_x (32-wide): out[d] = (Σ x[s]*dinv[s])*dinv[d] + x[d]*dinv[d]^2 ----------------
__global__ void gatherx_kernel(const float* __restrict__ x, float* __restrict__ out, int N) {
    int t = blockIdx.x * blockDim.x + threadIdx.x;
    int w = t >> 5;
    if (w >= N) return;
    int lane = t & 31;
    int p0 = g_rowptr[w], p1 = g_rowptr[w + 1];
    float acc = 0.f;
    int e = p0;
    for (; e + 4 <= p1; e += 4) {
        int s0 = g_csrc[e], s1 = g_csrc[e + 1], s2 = g_csrc[e + 2], s3 = g_csrc[e + 3];
        float n0 = g_cdinv[e], n1 = g_cdinv[e + 1], n2 = g_cdinv[e + 2], n3 = g_cdinv[e + 3];
        acc = fmaf(x[(size_t)s0 * 32 + lane], n0, acc);
        acc = fmaf(x[(size_t)s1 * 32 + lane], n1, acc);
        acc = fmaf(x[(size_t)s2 * 32 + lane], n2, acc);
        acc = fmaf(x[(size_t)s3 * 32 + lane], n3, acc);
    }
    for (; e < p1; ++e)
        acc = fmaf(x[(size_t)g_csrc[e] * 32 + lane], g_cdinv[e], acc);
    float dv = g_dinv[w];
    out[(size_t)w * 32 + lane] = fmaf(acc, dv, x[(size_t)w * 32 + lane] * dv * dv);
}

// ---------------- gather -> split: S = split(relu((Σ h[s]*dinv[s])*dinv[d] + h[d]*dinv[d]^2 + b)) ----------------
__global__ void gather_split_kernel(const float* __restrict__ h, const float* __restrict__ bias,
                                    unsigned* __restrict__ oh, unsigned* __restrict__ ol, int N) {
    int t = blockIdx.x * blockDim.x + threadIdx.x;
    int w = t >> 5;
    if (w >= N) return;
    int lane = t & 31;
    int p0 = g_rowptr[w], p1 = g_rowptr[w + 1];
    float4 acc = make_float4(0.f, 0.f, 0.f, 0.f);
    int e = p0;
    for (; e + 4 <= p1; e += 4) {
        int s0 = g_csrc[e], s1 = g_csrc[e + 1], s2 = g_csrc[e + 2], s3 = g_csrc[e + 3];
        float n0 = g_cdinv[e], n1 = g_cdinv[e + 1], n2 = g_cdinv[e + 2], n3 = g_cdinv[e + 3];
        float4 v0 = ((const float4*)(h + (size_t)s0 * WN))[lane];
        float4 v1 = ((const float4*)(h + (size_t)s1 * WN))[lane];
        float4 v2 = ((const float4*)(h + (size_t)s2 * WN))[lane];
        float4 v3 = ((const float4*)(h + (size_t)s3 * WN))[lane];
        acc.x = fmaf(v0.x, n0, acc.x); acc.y = fmaf(v0.y, n0, acc.y);
        acc.z = fmaf(v0.z, n0, acc.z); acc.w = fmaf(v0.w, n0, acc.w);
        acc.x = fmaf(v1.x, n1, acc.x); acc.y = fmaf(v1.y, n1, acc.y);
        acc.z = fmaf(v1.z, n1, acc.z); acc.w = fmaf(v1.w, n1, acc.w);
        acc.x = fmaf(v2.x, n2, acc.x); acc.y = fmaf(v2.y, n2, acc.y);
        acc.z = fmaf(v2.z, n2, acc.z); acc.w = fmaf(v2.w, n2, acc.w);
        acc.x = fmaf(v3.x, n3, acc.x); acc.y = fmaf(v3.y, n3, acc.y);
        acc.z = fmaf(v3.z, n3, acc.z); acc.w = fmaf(v3.w, n3, acc.w);
    }
    for (; e < p1; ++e) {
        int s = g_csrc[e];
        float n = g_cdinv[e];
        float4 v = ((const float4*)(h + (size_t)s * WN))[lane];
        acc.x = fmaf(v.x, n, acc.x); acc.y = fmaf(v.y, n, acc.y);
        acc.z = fmaf(v.z, n, acc.z); acc.w = fmaf(v.w, n, acc.w);
    }
    float dv = g_dinv[w];
    float d2 = dv * dv;
    float4 hd = ((const float4*)(h + (size_t)w * WN))[lane];
    float4 b = ((const float4*)bias)[lane];
    float4 o;
    o.x = fmaxf(0.f, fmaf(acc.x, dv, fmaf(hd.x, d2, b.x)));
    o.y = fmaxf(0.f, fmaf(acc.y, dv, fmaf(hd.y, d2, b.y)));
    o.z = fmaxf(0.f, fmaf(acc.z, dv, fmaf(hd.z, d2, b.z)));
    o.w = fmaxf(0.f, fmaf(acc.w, dv, fmaf(hd.w, d2, b.w)));
    unsigned h0, l0, h1, l1;
    split_pair(o.x, o.y, h0, l0);
    split_pair(o.z, o.w, h1, l1);
    *(uint2*)&oh[(size_t)w * 64 + lane * 2] = make_uint2(h0, h1);
    *(uint2*)&ol[(size_t)w * 64 + lane * 2] = make_uint2(l0, l1);
}

// ---------------- 3x bf16-split tensor-core GEMM ----------------
// INSPLIT: A given as pre-split (Ash/Asl, kpair layout). Else A f32 with PRO (0 id, 2 BN-relu).
// OUTSPLIT: write relu(acc+bias) split to Ch/Cl. STATS: column sums/sumsq. POOL: atomicMax pooled.
template<int K, int PRO, bool INSPLIT, bool OUTSPLIT, bool STATS, bool POOL>
__global__ __launch_bounds__(256, 2) void mma_gemm(
        const float* __restrict__ A,
        const unsigned* __restrict__ Agh, const unsigned* __restrict__ Agl,
        const unsigned* __restrict__ Wgh, const unsigned* __restrict__ Wgl,
        const float* __restrict__ bias, float* __restrict__ C,
        unsigned* __restrict__ Ch, unsigned* __restrict__ Cl,
        const int* __restrict__ batch, int M) {
    constexpr int CH = 32;
    constexpr int KP = K / 2;
    constexpr int ST = 20;
    extern __shared__ unsigned smem[];
    unsigned* Ah = smem;
    unsigned* Al = smem + 2560;
    unsigned* Wh = smem + 5120;
    unsigned* Wl = smem + 7680;
    __shared__ float sstat[2 * WN];

    int tid = threadIdx.x;
    int lane = tid & 31, wid = tid >> 5;
    int wm = wid >> 1, wn = wid & 1;
    int gr = lane >> 2;
    int row0 = blockIdx.x * 128;

    if (STATS) sstat[tid] = 0.f;

    float acc[2][8][4];
#pragma unroll
    for (int mt = 0; mt < 2; ++mt)
#pragma unroll
        for (int nt = 0; nt < 8; ++nt)
#pragma unroll
            for (int q = 0; q < 4; ++q) acc[mt][nt][q] = 0.f;

    for (int kb = 0; kb < K; kb += CH) {
        int kp0 = kb >> 1;
        __syncthreads();
        // stage W (pre-split copy)
        for (int i = tid; i < 512; i += 256) {
            int c = i >> 2, q = (i & 3) * 4;
            *(uint4*)&Wh[c * ST + q] = *(const uint4*)&Wgh[(size_t)c * KP + kp0 + q];
            *(uint4*)&Wl[c * ST + q] = *(const uint4*)&Wgl[(size_t)c * KP + kp0 + q];
        }
        // stage A
        if (INSPLIT) {
            for (int i = tid; i < 512; i += 256) {
                int r = i >> 2, q = (i & 3) * 4;
                uint4 vh = make_uint4(0u, 0u, 0u, 0u), vl = vh;
                if (row0 + r < M) {
                    vh = *(const uint4*)&Agh[(size_t)(row0 + r) * 64 + kp0 + q];
                    vl = *(const uint4*)&Agl[(size_t)(row0 + r) * 64 + kp0 + q];
                }
                *(uint4*)&Ah[r * ST + q] = vh;
                *(uint4*)&Al[r * ST + q] = vl;
            }
        } else {
            for (int i = tid; i < 128 * 8; i += 256) {
                int r = i >> 3, q = i & 7;
                float4 v = make_float4(0.f, 0.f, 0.f, 0.f);
                if (row0 + r < M)
                    v = *(const float4*)(A + (size_t)(row0 + r) * K + kb + 4 * q);
                if (PRO == 2) {
                    int kg = kb + 4 * q;
                    v.x = fmaxf(0.f, fmaf(v.x, g_bnp[kg + 0], g_bnp[WN + kg + 0]));
                    v.y = fmaxf(0.f, fmaf(v.y, g_bnp[kg + 1], g_bnp[WN + kg + 1]));
                    v.z = fmaxf(0.f, fmaf(v.z, g_bnp[kg + 2], g_bnp[WN + kg + 2]));
                    v.w = fmaxf(0.f, fmaf(v.w, g_bnp[kg + 3], g_bnp[WN + kg + 3]));
                }
                unsigned h0, l0, h1, l1;
                split_pair(v.x, v.y, h0, l0);
                split_pair(v.z, v.w, h1, l1);
                *(uint2*)&Ah[r * ST + 2 * q] = make_uint2(h0, h1);
                *(uint2*)&Al[r * ST + 2 * q] = make_uint2(l0, l1);
            }
        }
        __syncthreads();

#pragma unroll
        for (int ks = 0; ks < 2; ++ks) {
            int kc = ks * 8 + (lane & 3);
            unsigned ah[2][4], al[2][4];
#pragma unroll
            for (int mt = 0; mt < 2; ++mt) {
                int r = wm * 32 + mt * 16 + gr;
                const unsigned* ph = &Ah[r * ST + kc];
                const unsigned* pl = &Al[r * ST + kc];
                ah[mt][0] = ph[0]; ah[mt][1] = ph[8 * ST];
                ah[mt][2] = ph[4]; ah[mt][3] = ph[8 * ST + 4];
                al[mt][0] = pl[0]; al[mt][1] = pl[8 * ST];
                al[mt][2] = pl[4]; al[mt][3] = pl[8 * ST + 4];
            }
#pragma unroll
            for (int nh = 0; nh < 2; ++nh) {
                unsigned bh[4][2], bl[4][2];
#pragma unroll
                for (int j = 0; j < 4; ++j) {
                    int c = wn * 64 + (nh * 4 + j) * 8 + gr;
                    bh[j][0] = Wh[c * ST + kc];
                    bh[j][1] = Wh[c * ST + kc + 4];
                    bl[j][0] = Wl[c * ST + kc];
                    bl[j][1] = Wl[c * ST + kc + 4];
                }
#pragma unroll
                for (int mt = 0; mt < 2; ++mt)
#pragma unroll
                    for (int j = 0; j < 4; ++j) {
                        float* cc = acc[mt][nh * 4 + j];
                        mma_bf16(cc, al[mt], bh[j]);
                        mma_bf16(cc, ah[mt], bl[j]);
                        mma_bf16(cc, ah[mt], bh[j]);
                    }
            }
        }
    }

    // ---------------- epilogue ----------------
    if (POOL) {
        int rbase = row0 + wm * 32 + gr;
        int bt[4];
#pragma unroll
        for (int t = 0; t < 4; ++t) {
            int r = rbase + t * 8;
            bt[t] = (r < M) ? batch[r] : -1;
        }
        bool same = (bt[0] == bt[1]) && (bt[1] == bt[2]) && (bt[2] == bt[3]) && (bt[0] >= 0);
#pragma unroll
        for (int nt = 0; nt < 8; ++nt) {
#pragma unroll
            for (int c = 0; c < 2; ++c) {
                int col = wn * 64 + nt * 8 + (lane & 3) * 2 + c;
                float bb = bias[col];
                float v[4];
                v[0] = fmaxf(0.f, acc[0][nt][c] + bb);
                v[1] = fmaxf(0.f, acc[0][nt][2 + c] + bb);
                v[2] = fmaxf(0.f, acc[1][nt][c] + bb);
                v[3] = fmaxf(0.f, acc[1][nt][2 + c] + bb);
                if (same) {
                    float m = fmaxf(fmaxf(v[0], v[1]), fmaxf(v[2], v[3]));
                    atomicMax((int*)&g_pooled[(size_t)bt[0] * WN + col], __float_as_int(m));
                } else {
#pragma unroll
                    for (int t = 0; t < 4; ++t)
                        if (bt[t] >= 0)
                            atomicMax((int*)&g_pooled[(size_t)bt[t] * WN + col],
                                      __float_as_int(v[t]));
                }
            }
        }
        return;
    }

    float ss[16], sq[16];
    if (STATS) {
#pragma unroll
        for (int i = 0; i < 16; ++i) { ss[i] = 0.f; sq[i] = 0.f; }
    }

#pragma unroll
    for (int mt = 0; mt < 2; ++mt) {
#pragma unroll
        for (int h = 0; h < 2; ++h) {
            int row = row0 + wm * 32 + mt * 16 + gr + h * 8;
            bool ok = row < M;
#pragma unroll
            for (int nt = 0; nt < 8; ++nt) {
                int col = wn * 64 + nt * 8 + (lane & 3) * 2;
                float b0 = bias ? bias[col] : 0.f;
                float b1 = bias ? bias[col + 1] : 0.f;
                float o0 = acc[mt][nt][h * 2 + 0] + b0;
                float o1 = acc[mt][nt][h * 2 + 1] + b1;
                if (OUTSPLIT) {
                    if (ok) {
                        o0 = fmaxf(0.f, o0);
                        o1 = fmaxf(0.f, o1);
                        unsigned hh, ll;
                        split_pair(o0, o1, hh, ll);
                        int kp = col >> 1;
                        Ch[(size_t)row * 64 + kp] = hh;
                        Cl[(size_t)row * 64 + kp] = ll;
                    }
                } else {
                    if (ok)
                        *(float2*)(C + (size_t)row * WN + col) = make_float2(o0, o1);
                }
                if (STATS) {
                    if (!ok) { o0 = 0.f; o1 = 0.f; }
                    ss[nt * 2 + 0] += o0; sq[nt * 2 + 0] += o0 * o0;
                    ss[nt * 2 + 1] += o1; sq[nt * 2 + 1] += o1 * o1;
                }
            }
        }
    }

    if (STATS) {
#pragma unroll
        for (int i = 0; i < 16; ++i) {
#pragma unroll
            for (int o = 4; o <= 16; o <<= 1) {
                ss[i] += __shfl_xor_sync(0xffffffffu, ss[i], o);
                sq[i] += __shfl_xor_sync(0xffffffffu, sq[i], o);
            }
        }
        if (lane < 4) {
#pragma unroll
            for (int nt = 0; nt < 8; ++nt)
#pragma unroll
                for (int c = 0; c < 2; ++c) {
                    int col = wn * 64 + nt * 8 + lane * 2 + c;
                    atomicAdd(&sstat[col], ss[nt * 2 + c]);
                    atomicAdd(&sstat[WN + col], sq[nt * 2 + c]);
                }
        }
        __syncthreads();
        atomicAdd(&g_stats[tid], sstat[tid]);
    }
}

// ---------------- BN finalize ----------------
__global__ void bnfinal_kernel(const float* __restrict__ g, const float* __restrict__ be, int N) {
    int f = threadIdx.x;
    float inv = 1.0f / (float)N;
    float mu = g_stats[f] * inv;
    float var = g_stats[WN + f] * inv - mu * mu;
    float sc = g[f] * rsqrtf(var + 1e-5f);
    g_bnp[f] = sc;
    g_bnp[WN + f] = be[f] - mu * sc;
}

// ---------------- final tiny MLP ----------------
__global__ void final_kernel(const float* __restrict__ W5, const float* __restrict__ b5,
                             const float* __restrict__ g2, const float* __restrict__ be2,
                             const float* __restrict__ W6, const float* __restrict__ b6,
                             float* __restrict__ out, int G) {
    __shared__ float W5s[WN * 64];
    __shared__ float ys[GMAX][65];
    __shared__ float sc[64], sh[64];
    int tid = threadIdx.x;
    for (int i = tid; i < WN * 64; i += 256) W5s[i] = W5[i];
    __syncthreads();

    int g = tid & 63;
    int jb = tid >> 6;
    float acc[16];
#pragma unroll
    for (int j = 0; j < 16; ++j) acc[j] = 0.f;
    if (g < G) {
        for (int k = 0; k < WN; ++k) {
            float p = g_pooled[(size_t)g * WN + k];
#pragma unroll
            for (int j = 0; j < 16; ++j)
                acc[j] = fmaf(p, W5s[k * 64 + jb * 16 + j], acc[j]);
        }
#pragma unroll
        for (int j = 0; j < 16; ++j)
            ys[g][jb * 16 + j] = acc[j] + b5[jb * 16 + j];
    }
    __syncthreads();

    if (tid < 64) {
        float s = 0.f, q = 0.f;
        for (int r = 0; r < G; ++r) {
            float v = ys[r][tid];
            s += v;
            q += v * v;
        }
        float inv = 1.0f / (float)G;
        float mu = s * inv;
        float var = q * inv - mu * mu;
        float scale = g2[tid] * rsqrtf(var + 1e-5f);
        sc[tid] = scale;
        sh[tid] = be2[tid] - mu * scale;
    }
    __syncthreads();

    if (tid < G) {
        float o = b6[0];
        for (int j = 0; j < 64; ++j) {
            float v = fmaxf(0.f, fmaf(ys[tid][j], sc[j], sh[j]));
            o = fmaf(v, W6[j], o);
        }
        out[tid] = o;
    }
}

// ---------------- launch ----------------
extern "C" void kernel_launch(void* const* d_in, const int* in_sizes, int n_in,
                              void* d_out, int out_size) {
    const float* x   = (const float*)d_in[0];
    const int*   ei  = (const int*)d_in[1];
    const int*   bat = (const int*)d_in[2];
    const float* W1  = (const float*)d_in[3];
    const float* b1  = (const float*)d_in[4];
    const float* W2  = (const float*)d_in[5];
    const float* b2  = (const float*)d_in[6];
    const float* W3  = (const float*)d_in[7];
    const float* b3  = (const float*)d_in[8];
    const float* g1  = (const float*)d_in[9];
    const float* be1 = (const float*)d_in[10];
    const float* W4  = (const float*)d_in[11];
    const float* b4  = (const float*)d_in[12];
    const float* W5  = (const float*)d_in[13];
    const float* b5  = (const float*)d_in[14];
    const float* g2  = (const float*)d_in[15];
    const float* be2 = (const float*)d_in[16];
    const float* W6  = (const float*)d_in[17];
    const float* b6  = (const float*)d_in[18];

    int N = in_sizes[2];
    int E = in_sizes[1] / 2;
    int G = out_size;
    const int* src = ei;
    const int* dst = ei + E;

    float *B0, *B1, *B2;
    unsigned *S0h, *S0l, *S1h, *S1l, *Wsh, *Wsl;
    void *pcnt, *pstats, *ppooled;
    cudaGetSymbolAddress((void**)&B0, g_B0);
    cudaGetSymbolAddress((void**)&B1, g_B1);
    cudaGetSymbolAddress((void**)&B2, g_B2);
    cudaGetSymbolAddress((void**)&S0h, g_S0h);
    cudaGetSymbolAddress((void**)&S0l, g_S0l);
    cudaGetSymbolAddress((void**)&S1h, g_S1h);
    cudaGetSymbolAddress((void**)&S1l, g_S1l);
    cudaGetSymbolAddress((void**)&Wsh, g_Wsh);
    cudaGetSymbolAddress((void**)&Wsl, g_Wsl);
    cudaGetSymbolAddress(&pcnt, g_cnt);
    cudaGetSymbolAddress(&pstats, g_stats);
    cudaGetSymbolAddress(&ppooled, g_pooled);

    static cudaStream_t s2 = nullptr;
    static cudaEvent_t evA = nullptr, evB = nullptr;
    if (!s2) {
        cudaStreamCreateWithFlags(&s2, cudaStreamNonBlocking);
        cudaEventCreateWithFlags(&evA, cudaEventDisableTiming);
        cudaEventCreateWithFlags(&evB, cudaEventDisableTiming);
    }

    int nb = (N + 1023) / 1024;
    int gb = (N + 127) / 128;
    int gather_blocks = (int)(((long long)N * 32 + 255) / 256);
    int smemB = 10240 * 4;

    cudaFuncSetAttribute(mma_gemm<32, 0, false, true, false, false>,
                         cudaFuncAttributeMaxDynamicSharedMemorySize, smemB);
    cudaFuncSetAttribute(mma_gemm<128, 0, true, false, false, false>,
                         cudaFuncAttributeMaxDynamicSharedMemorySize, smemB);
    cudaFuncSetAttribute(mma_gemm<128, 0, true, false, true, false>,
                         cudaFuncAttributeMaxDynamicSharedMemorySize, smemB);
    cudaFuncSetAttribute(mma_gemm<128, 2, false, false, false, true>,
                         cudaFuncAttributeMaxDynamicSharedMemorySize, smemB);

    // ---- fork: CSR build + gather_x on side stream ----
    cudaEventRecord(evA, 0);
    cudaStreamWaitEvent(s2, evA, 0);

    cudaMemsetAsync(pcnt, 0, (size_t)N * sizeof(int), s2);
    deg_kernel<<<(E + 255) / 256, 256, 0, s2>>>(dst, E);
    dinv_kernel<<<(N + 255) / 256, 256, 0, s2>>>(N);
    scan1_kernel<<<nb, 1024, 0, s2>>>(N);
    scan2_kernel<<<1, 128, 0, s2>>>(nb, N);
    scan3_kernel<<<(N + 255) / 256, 256, 0, s2>>>(N);
    bin_kernel<<<(E + 255) / 256, 256, 0, s2>>>(src, dst, E);
    gatherx_kernel<<<gather_blocks, 256, 0, s2>>>(x, B2, N);   // Xs -> B2
    cudaEventRecord(evB, s2);

    // main stream: memsets + W pre-splits (independent of CSR)
    cudaMemsetAsync(pstats, 0, 2 * WN * sizeof(float));
    cudaMemsetAsync(ppooled, 0, (size_t)G * WN * sizeof(float));
    wsplit_kernel<<<8, 256>>>(W1, Wsh + 0, Wsl + 0, 32);
    wsplit_kernel<<<32, 256>>>(W2, Wsh + 8192, Wsl + 8192, 128);
    wsplit_kernel<<<32, 256>>>(W3, Wsh + 16384, Wsl + 16384, 128);
    wsplit_kernel<<<32, 256>>>(W4, Wsh + 24576, Wsl + 24576, 128);

    // join
    cudaStreamWaitEvent(0, evB, 0);

    // GEMM1: relu(Xs@W1 + b1) -> split S0
    mma_gemm<32, 0, false, true, false, false><<<gb, 256, smemB>>>(
        B2, nullptr, nullptr, Wsh, Wsl, b1, nullptr, S0h, S0l, nullptr, N);

    // GEMM2: h2 = S0@W2 -> B0 (f32); gather+relu -> split S1
    mma_gemm<128, 0, true, false, false, false><<<gb, 256, smemB>>>(
        nullptr, S0h, S0l, Wsh + 8192, Wsl + 8192, nullptr, B0, nullptr, nullptr, nullptr, N);
    gather_split_kernel<<<gather_blocks, 256>>>(B0, b2, S1h, S1l, N);

    // GEMM3: y = S1@W3 + b3 -> B1 (f32) + stats
    mma_gemm<128, 0, true, false, true, false><<<gb, 256, smemB>>>(
        nullptr, S1h, S1l, Wsh + 16384, Wsl + 16384, b3, B1, nullptr, nullptr, nullptr, N);
    bnfinal_kernel<<<1, 128>>>(g1, be1, N);

    // GEMM4: relu(bn(B1))@W4 + b4, fused max-pool
    mma_gemm<128, 2, false, false, false, true><<<gb, 256, smemB>>>(
        B1, nullptr, nullptr, Wsh + 24576, Wsl + 24576, b4, nullptr, nullptr, nullptr, bat, N);

    // final MLP
    final_kernel<<<1, 256>>>(W5, b5, g2, be2, W6, b6, (float*)d_out, G);
}

// round 10
// speedup vs baseline: 2.1693x; 1.0142x over previous
#include <cuda_runtime.h>

#define WN 128
#define NMAXN 100000
#define EMAX 600000
#define GMAX 64

// ---------------- scratch ----------------
__device__ float g_B0[(size_t)NMAXN * WN];
__device__ float g_B1[(size_t)NMAXN * WN];
__device__ float g_B2[(size_t)NMAXN * WN];
__device__ unsigned g_S0h[(size_t)NMAXN * 64];
__device__ unsigned g_S0l[(size_t)NMAXN * 64];
__device__ unsigned g_S1h[(size_t)NMAXN * 64];
__device__ unsigned g_S1l[(size_t)NMAXN * 64];
__device__ unsigned g_Wsh[4 * 8192];
__device__ unsigned g_Wsl[4 * 8192];
__device__ float g_dinv[NMAXN];
__device__ int   g_cnt[NMAXN];
__device__ int   g_rowtmp[NMAXN];
__device__ int   g_rowptr[NMAXN + 1];
__device__ int   g_cursor[NMAXN];
__device__ int   g_bsum[128];
__device__ int   g_boff[128];
__device__ int   g_csrc[EMAX];
__device__ float g_cdinv[EMAX];
__device__ float g_stats[2 * WN];
__device__ float g_bnp[2 * WN];
__device__ float g_pooled[GMAX * WN];

// ---------------- bf16 2-split helpers ----------------
__device__ __forceinline__ void split_bf16(float x, unsigned short& h, float& r) {
    asm("cvt.rn.bf16.f32 %0, %1;" : "=h"(h) : "f"(x));
    r = x - __uint_as_float(((unsigned)h) << 16);
}
__device__ __forceinline__ unsigned packf_bf16x2(float lo_, float hi_) {
    unsigned u;
    asm("cvt.rn.bf16x2.f32 %0, %1, %2;" : "=r"(u) : "f"(hi_), "f"(lo_));
    return u;
}
__device__ __forceinline__ void split_pair(float a, float b, unsigned& hi, unsigned& lo) {
    unsigned short ha, hb;
    float ra, rb;
    split_bf16(a, ha, ra);
    split_bf16(b, hb, rb);
    hi = ((unsigned)hb << 16) | (unsigned)ha;
    lo = packf_bf16x2(ra, rb);
}
__device__ __forceinline__ void mma_bf16(float* c, const unsigned* a, const unsigned* b) {
    asm volatile(
        "mma.sync.aligned.m16n8k16.row.col.f32.bf16.bf16.f32 "
        "{%0,%1,%2,%3}, {%4,%5,%6,%7}, {%8,%9}, {%0,%1,%2,%3};"
        : "+f"(c[0]), "+f"(c[1]), "+f"(c[2]), "+f"(c[3])
        : "r"(a[0]), "r"(a[1]), "r"(a[2]), "r"(a[3]), "r"(b[0]), "r"(b[1]));
}
__device__ __forceinline__ void cp16(unsigned* dst, const void* src, bool pred) {
    unsigned d = (unsigned)__cvta_generic_to_shared(dst);
    int sz = pred ? 16 : 0;
    asm volatile("cp.async.cg.shared.global [%0], [%1], 16, %2;"
                 :: "r"(d), "l"(src), "r"(sz));
}
__device__ __forceinline__ void cp_commit() {
    asm volatile("cp.async.commit_group;");
}
template<int NG>
__device__ __forceinline__ void cp_wait() {
    asm volatile("cp.async.wait_group %0;" :: "n"(NG));
}

// ---------------- degree / dinv ----------------
__global__ void deg_kernel(const int* __restrict__ dst, int E) {
    int e = blockIdx.x * blockDim.x + threadIdx.x;
    if (e < E) atomicAdd(&g_cnt[dst[e]], 1);
}

__global__ void dinv_kernel(int N) {
    int i = blockIdx.x * blockDim.x + threadIdx.x;
    if (i < N) g_dinv[i] = rsqrtf((float)g_cnt[i] + 1.0f);
}

// ---------------- CSR build ----------------
__global__ void scan1_kernel(int N) {
    __shared__ int sm[1024];
    int tid = threadIdx.x;
    int i = blockIdx.x * 1024 + tid;
    int v = (i < N) ? g_cnt[i] : 0;
    sm[tid] = v;
    __syncthreads();
#pragma unroll
    for (int o = 1; o < 1024; o <<= 1) {
        int t = 0;
        if (tid >= o) t = sm[tid - o];
        __syncthreads();
        if (tid >= o) sm[tid] += t;
        __syncthreads();
    }
    if (i < N) g_rowtmp[i] = sm[tid];
    if (tid == 1023) g_bsum[blockIdx.x] = sm[1023];
}

__global__ void scan2_kernel(int nb, int N) {
    __shared__ int sm[128];
    int t = threadIdx.x;
    int v = (t < nb) ? g_bsum[t] : 0;
    sm[t] = v;
    __syncthreads();
#pragma unroll
    for (int o = 1; o < 128; o <<= 1) {
        int u = 0;
        if (t >= o) u = sm[t - o];
        __syncthreads();
        if (t >= o) sm[t] += u;
        __syncthreads();
    }
    if (t < nb) g_boff[t] = sm[t] - v;
    if (t == 127) g_rowptr[N] = sm[127];
}

__global__ void scan3_kernel(int N) {
    int i = blockIdx.x * blockDim.x + threadIdx.x;
    if (i < N) {
        int rp = g_rowtmp[i] - g_cnt[i] + g_boff[i >> 10];
        g_rowptr[i] = rp;
        g_cursor[i] = rp;
    }
}

__global__ void bin_kernel(const int* __restrict__ src, const int* __restrict__ dst, int E) {
    int e = blockIdx.x * blockDim.x + threadIdx.x;
    if (e >= E) return;
    int s = src[e], d = dst[e];
    int pos = atomicAdd(&g_cursor[d], 1);
    g_csrc[pos] = s;
    g_cdinv[pos] = g_dinv[s];
}

// ---------------- W split ----------------
__global__ void wsplit_kernel(const float* __restrict__ W, unsigned* __restrict__ oh,
                              unsigned* __restrict__ ol, int K) {
    int i = blockIdx.x * blockDim.x + threadIdx.x;
    int KP = K >> 1;
    if (i >= 128 * KP) return;
    int c = i / KP, kp = i % KP;
    unsigned h, l;
    split_pair(W[(size_t)(2 * kp) * WN + c], W[(size_t)(2 * kp + 1) * WN + c], h, l);
    oh[i] = h;
    ol[i] = l;
}

// ---------------- gather_x (32-wide) ----------------
__global__ void gatherx_kernel(const float* __restrict__ x, float* __restrict__ out, int N) {
    int t = blockIdx.x * blockDim.x + threadIdx.x;
    int w = t >> 5;
    if (w >= N) return;
    int lane = t & 31;
    int p0 = g_rowptr[w], p1 = g_rowptr[w + 1];
    float acc = 0.f;
    int e = p0;
    for (; e + 4 <= p1; e += 4) {
        int s0 = g_csrc[e], s1 = g_csrc[e + 1], s2 = g_csrc[e + 2], s3 = g_csrc[e + 3];
        float n0 = g_cdinv[e], n1 = g_cdinv[e + 1], n2 = g_cdinv[e + 2], n3 = g_cdinv[e + 3];
        acc = fmaf(x[(size_t)s0 * 32 + lane], n0, acc);
        acc = fmaf(x[(size_t)s1 * 32 + lane], n1, acc);
        acc = fmaf(x[(size_t)s2 * 32 + lane], n2, acc);
        acc = fmaf(x[(size_t)s3 * 32 + lane], n3, acc);
    }
    for (; e < p1; ++e)
        acc = fmaf(x[(size_t)g_csrc[e] * 32 + lane], g_cdinv[e], acc);
    float dv = g_dinv[w];
    out[(size_t)w * 32 + lane] = fmaf(acc, dv, x[(size_t)w * 32 + lane] * dv * dv);
}

// ---------------- gather -> split ----------------
__global__ void gather_split_kernel(const float* __restrict__ h, const float* __restrict__ bias,
                                    unsigned* __restrict__ oh, unsigned* __restrict__ ol, int N) {
    int t = blockIdx.x * blockDim.x + threadIdx.x;
    int w = t >> 5;
    if (w >= N) return;
    int lane = t & 31;
    int p0 = g_rowptr[w], p1 = g_rowptr[w + 1];
    float4 acc = make_float4(0.f, 0.f, 0.f, 0.f);
    int e = p0;
    for (; e + 4 <= p1; e += 4) {
        int s0 = g_csrc[e], s1 = g_csrc[e + 1], s2 = g_csrc[e + 2], s3 = g_csrc[e + 3];
        float n0 = g_cdinv[e], n1 = g_cdinv[e + 1], n2 = g_cdinv[e + 2], n3 = g_cdinv[e + 3];
        float4 v0 = ((const float4*)(h + (size_t)s0 * WN))[lane];
        float4 v1 = ((const float4*)(h + (size_t)s1 * WN))[lane];
        float4 v2 = ((const float4*)(h + (size_t)s2 * WN))[lane];
        float4 v3 = ((const float4*)(h + (size_t)s3 * WN))[lane];
        acc.x = fmaf(v0.x, n0, acc.x); acc.y = fmaf(v0.y, n0, acc.y);
        acc.z = fmaf(v0.z, n0, acc.z); acc.w = fmaf(v0.w, n0, acc.w);
        acc.x = fmaf(v1.x, n1, acc.x); acc.y = fmaf(v1.y, n1, acc.y);
        acc.z = fmaf(v1.z, n1, acc.z); acc.w = fmaf(v1.w, n1, acc.w);
        acc.x = fmaf(v2.x, n2, acc.x); acc.y = fmaf(v2.y, n2, acc.y);
        acc.z = fmaf(v2.z, n2, acc.z); acc.w = fmaf(v2.w, n2, acc.w);
        acc.x = fmaf(v3.x, n3, acc.x); acc.y = fmaf(v3.y, n3, acc.y);
        acc.z = fmaf(v3.z, n3, acc.z); acc.w = fmaf(v3.w, n3, acc.w);
    }
    for (; e < p1; ++e) {
        int s = g_csrc[e];
        float n = g_cdinv[e];
        float4 v = ((const float4*)(h + (size_t)s * WN))[lane];
        acc.x = fmaf(v.x, n, acc.x); acc.y = fmaf(v.y, n, acc.y);
        acc.z = fmaf(v.z, n, acc.z); acc.w = fmaf(v.w, n, acc.w);
    }
    float dv = g_dinv[w];
    float d2 = dv * dv;
    float4 hd = ((const float4*)(h + (size_t)w * WN))[lane];
    float4 b = ((const float4*)bias)[lane];
    float4 o;
    o.x = fmaxf(0.f, fmaf(acc.x, dv, fmaf(hd.x, d2, b.x)));
    o.y = fmaxf(0.f, fmaf(acc.y, dv, fmaf(hd.y, d2, b.y)));
    o.z = fmaxf(0.f, fmaf(acc.z, dv, fmaf(hd.z, d2, b.z)));
    o.w = fmaxf(0.f, fmaf(acc.w, dv, fmaf(hd.w, d2, b.w)));
    unsigned h0, l0, h1, l1;
    split_pair(o.x, o.y, h0, l0);
    split_pair(o.z, o.w, h1, l1);
    *(uint2*)&oh[(size_t)w * 64 + lane * 2] = make_uint2(h0, h1);
    *(uint2*)&ol[(size_t)w * 64 + lane * 2] = make_uint2(l0, l1);
}

// ---------------- 3x bf16-split tensor-core GEMM ----------------
// INSPLIT: pre-split input, cp.async double-buffered pipeline.
// OUTSPLIT: write relu(acc+bias) split. STATS: column sums/sumsq. POOL: atomicMax pooled.
template<int K, int PRO, bool INSPLIT, bool OUTSPLIT, bool STATS, bool POOL>
__global__ __launch_bounds__(256, 2) void mma_gemm(
        const float* __restrict__ A,
        const unsigned* __restrict__ Agh, const unsigned* __restrict__ Agl,
        const unsigned* __restrict__ Wgh, const unsigned* __restrict__ Wgl,
        const float* __restrict__ bias, float* __restrict__ C,
        unsigned* __restrict__ Ch, unsigned* __restrict__ Cl,
        const int* __restrict__ batch, int M) {
    constexpr int CH = 32;
    constexpr int KP = K / 2;
    constexpr int ST = 20;
    constexpr int NC = K / CH;          // chunks
    constexpr int STAGE = 10240;        // u32 per stage
    extern __shared__ unsigned smem[];
    __shared__ float sstat[2 * WN];

    int tid = threadIdx.x;
    int lane = tid & 31, wid = tid >> 5;
    int wm = wid >> 1, wn = wid & 1;
    int gr = lane >> 2;
    int row0 = blockIdx.x * 128;

    if (STATS) sstat[tid] = 0.f;

    float acc[2][8][4];
#pragma unroll
    for (int mt = 0; mt < 2; ++mt)
#pragma unroll
        for (int nt = 0; nt < 8; ++nt)
#pragma unroll
            for (int q = 0; q < 4; ++q) acc[mt][nt][q] = 0.f;

    // --- issue helper (INSPLIT): cp.async chunk ci into stage s ---
    auto issue = [&](int ci, int s) {
        unsigned* Ah = smem + s * STAGE;
        unsigned* Al = Ah + 2560;
        unsigned* Wh = Al + 2560;
        unsigned* Wl = Wh + 2560;
        int kp0 = ci * (CH / 2);
#pragma unroll
        for (int i = tid; i < 512; i += 256) {
            int c = i >> 2, q = (i & 3) * 4;
            cp16(&Wh[c * ST + q], &Wgh[(size_t)c * KP + kp0 + q], true);
            cp16(&Wl[c * ST + q], &Wgl[(size_t)c * KP + kp0 + q], true);
        }
#pragma unroll
        for (int i = tid; i < 512; i += 256) {
            int r = i >> 2, q = (i & 3) * 4;
            bool ok = row0 + r < M;
            cp16(&Ah[r * ST + q], &Agh[(size_t)(row0 + r) * 64 + kp0 + q], ok);
            cp16(&Al[r * ST + q], &Agl[(size_t)(row0 + r) * 64 + kp0 + q], ok);
        }
        cp_commit();
    };

    // --- compute helper: consume stage s ---
    auto compute = [&](int s) {
        unsigned* Ah = smem + s * STAGE;
        unsigned* Al = Ah + 2560;
        unsigned* Wh = Al + 2560;
        unsigned* Wl = Wh + 2560;
#pragma unroll
        for (int ks = 0; ks < 2; ++ks) {
            int kc = ks * 8 + (lane & 3);
            unsigned ah[2][4], al[2][4];
#pragma unroll
            for (int mt = 0; mt < 2; ++mt) {
                int r = wm * 32 + mt * 16 + gr;
                const unsigned* ph = &Ah[r * ST + kc];
                const unsigned* pl = &Al[r * ST + kc];
                ah[mt][0] = ph[0]; ah[mt][1] = ph[8 * ST];
                ah[mt][2] = ph[4]; ah[mt][3] = ph[8 * ST + 4];
                al[mt][0] = pl[0]; al[mt][1] = pl[8 * ST];
                al[mt][2] = pl[4]; al[mt][3] = pl[8 * ST + 4];
            }
#pragma unroll
            for (int nh = 0; nh < 2; ++nh) {
                unsigned bh[4][2], bl[4][2];
#pragma unroll
                for (int j = 0; j < 4; ++j) {
                    int c = wn * 64 + (nh * 4 + j) * 8 + gr;
                    bh[j][0] = Wh[c * ST + kc];
                    bh[j][1] = Wh[c * ST + kc + 4];
                    bl[j][0] = Wl[c * ST + kc];
                    bl[j][1] = Wl[c * ST + kc + 4];
                }
#pragma unroll
                for (int mt = 0; mt < 2; ++mt)
#pragma unroll
                    for (int j = 0; j < 4; ++j) {
                        float* cc = acc[mt][nh * 4 + j];
                        mma_bf16(cc, al[mt], bh[j]);
                        mma_bf16(cc, ah[mt], bl[j]);
                        mma_bf16(cc, ah[mt], bh[j]);
                    }
            }
        }
    };

    if (INSPLIT) {
        issue(0, 0);
#pragma unroll
        for (int ci = 0; ci < NC; ++ci) {
            if (ci + 1 < NC) {
                issue(ci + 1, (ci + 1) & 1);
                cp_wait<1>();
            } else {
                cp_wait<0>();
            }
            __syncthreads();
            compute(ci & 1);
            __syncthreads();
        }
    } else {
        unsigned* Ah = smem;
        unsigned* Al = smem + 2560;
        unsigned* Wh = smem + 5120;
        unsigned* Wl = smem + 7680;
        for (int kb = 0; kb < K; kb += CH) {
            int kp0 = kb >> 1;
            __syncthreads();
            for (int i = tid; i < 512; i += 256) {
                int c = i >> 2, q = (i & 3) * 4;
                *(uint4*)&Wh[c * ST + q] = *(const uint4*)&Wgh[(size_t)c * KP + kp0 + q];
                *(uint4*)&Wl[c * ST + q] = *(const uint4*)&Wgl[(size_t)c * KP + kp0 + q];
            }
            for (int i = tid; i < 128 * 8; i += 256) {
                int r = i >> 3, q = i & 7;
                float4 v = make_float4(0.f, 0.f, 0.f, 0.f);
                if (row0 + r < M)
                    v = *(const float4*)(A + (size_t)(row0 + r) * K + kb + 4 * q);
                if (PRO == 2) {
                    int kg = kb + 4 * q;
                    v.x = fmaxf(0.f, fmaf(v.x, g_bnp[kg + 0], g_bnp[WN + kg + 0]));
                    v.y = fmaxf(0.f, fmaf(v.y, g_bnp[kg + 1], g_bnp[WN + kg + 1]));
                    v.z = fmaxf(0.f, fmaf(v.z, g_bnp[kg + 2], g_bnp[WN + kg + 2]));
                    v.w = fmaxf(0.f, fmaf(v.w, g_bnp[kg + 3], g_bnp[WN + kg + 3]));
                }
                unsigned h0, l0, h1, l1;
                split_pair(v.x, v.y, h0, l0);
                split_pair(v.z, v.w, h1, l1);
                *(uint2*)&Ah[r * ST + 2 * q] = make_uint2(h0, h1);
                *(uint2*)&Al[r * ST + 2 * q] = make_uint2(l0, l1);
            }
            __syncthreads();
            compute(0);
        }
    }

    // ---------------- epilogue ----------------
    if (POOL) {
        int rbase = row0 + wm * 32 + gr;
        int bt[4];
#pragma unroll
        for (int t = 0; t < 4; ++t) {
            int r = rbase + t * 8;
            bt[t] = (r < M) ? batch[r] : -1;
        }
        bool same = (bt[0] == bt[1]) && (bt[1] == bt[2]) && (bt[2] == bt[3]) && (bt[0] >= 0);
#pragma unroll
        for (int nt = 0; nt < 8; ++nt) {
#pragma unroll
            for (int c = 0; c < 2; ++c) {
                int col = wn * 64 + nt * 8 + (lane & 3) * 2 + c;
                float bb = bias[col];
                float v[4];
                v[0] = fmaxf(0.f, acc[0][nt][c] + bb);
                v[1] = fmaxf(0.f, acc[0][nt][2 + c] + bb);
                v[2] = fmaxf(0.f, acc[1][nt][c] + bb);
                v[3] = fmaxf(0.f, acc[1][nt][2 + c] + bb);
                if (same) {
                    float m = fmaxf(fmaxf(v[0], v[1]), fmaxf(v[2], v[3]));
                    atomicMax((int*)&g_pooled[(size_t)bt[0] * WN + col], __float_as_int(m));
                } else {
#pragma unroll
                    for (int t = 0; t < 4; ++t)
                        if (bt[t] >= 0)
                            atomicMax((int*)&g_pooled[(size_t)bt[t] * WN + col],
                                      __float_as_int(v[t]));
                }
            }
        }
        return;
    }

    float ss[16], sq[16];
    if (STATS) {
#pragma unroll
        for (int i = 0; i < 16; ++i) { ss[i] = 0.f; sq[i] = 0.f; }
    }

#pragma unroll
    for (int mt = 0; mt < 2; ++mt) {
#pragma unroll
        for (int h = 0; h < 2; ++h) {
            int row = row0 + wm * 32 + mt * 16 + gr + h * 8;
            bool ok = row < M;
#pragma unroll
            for (int nt = 0; nt < 8; ++nt) {
                int col = wn * 64 + nt * 8 + (lane & 3) * 2;
                float b0 = bias ? bias[col] : 0.f;
                float b1 = bias ? bias[col + 1] : 0.f;
                float o0 = acc[mt][nt][h * 2 + 0] + b0;
                float o1 = acc[mt][nt][h * 2 + 1] + b1;
                if (OUTSPLIT) {
                    if (ok) {
                        o0 = fmaxf(0.f, o0);
                        o1 = fmaxf(0.f, o1);
                        unsigned hh, ll;
                        split_pair(o0, o1, hh, ll);
                        int kp = col >> 1;
                        Ch[(size_t)row * 64 + kp] = hh;
                        Cl[(size_t)row * 64 + kp] = ll;
                    }
                } else {
                    if (ok)
                        *(float2*)(C + (size_t)row * WN + col) = make_float2(o0, o1);
                }
                if (STATS) {
                    if (!ok) { o0 = 0.f; o1 = 0.f; }
                    ss[nt * 2 + 0] += o0; sq[nt * 2 + 0] += o0 * o0;
                    ss[nt * 2 + 1] += o1; sq[nt * 2 + 1] += o1 * o1;
                }
            }
        }
    }

    if (STATS) {
#pragma unroll
        for (int i = 0; i < 16; ++i) {
#pragma unroll
            for (int o = 4; o <= 16; o <<= 1) {
                ss[i] += __shfl_xor_sync(0xffffffffu, ss[i], o);
                sq[i] += __shfl_xor_sync(0xffffffffu, sq[i], o);
            }
        }
        if (lane < 4) {
#pragma unroll
            for (int nt = 0; nt < 8; ++nt)
#pragma unroll
                for (int c = 0; c < 2; ++c) {
                    int col = wn * 64 + nt * 8 + lane * 2 + c;
                    atomicAdd(&sstat[col], ss[nt * 2 + c]);
                    atomicAdd(&sstat[WN + col], sq[nt * 2 + c]);
                }
        }
        __syncthreads();
        atomicAdd(&g_stats[tid], sstat[tid]);
    }
}

// ---------------- BN finalize ----------------
__global__ void bnfinal_kernel(const float* __restrict__ g, const float* __restrict__ be, int N) {
    int f = threadIdx.x;
    float inv = 1.0f / (float)N;
    float mu = g_stats[f] * inv;
    float var = g_stats[WN + f] * inv - mu * mu;
    float sc = g[f] * rsqrtf(var + 1e-5f);
    g_bnp[f] = sc;
    g_bnp[WN + f] = be[f] - mu * sc;
}

// ---------------- final tiny MLP ----------------
__global__ void final_kernel(const float* __restrict__ W5, const float* __restrict__ b5,
                             const float* __restrict__ g2, const float* __restrict__ be2,
                             const float* __restrict__ W6, const float* __restrict__ b6,
                             float* __restrict__ out, int G) {
    __shared__ float W5s[WN * 64];
    __shared__ float ys[GMAX][65];
    __shared__ float sc[64], sh[64];
    int tid = threadIdx.x;
    for (int i = tid; i < WN * 64; i += 256) W5s[i] = W5[i];
    __syncthreads();

    int g = tid & 63;
    int jb = tid >> 6;
    float acc[16];
#pragma unroll
    for (int j = 0; j < 16; ++j) acc[j] = 0.f;
    if (g < G) {
        for (int k = 0; k < WN; ++k) {
            float p = g_pooled[(size_t)g * WN + k];
#pragma unroll
            for (int j = 0; j < 16; ++j)
                acc[j] = fmaf(p, W5s[k * 64 + jb * 16 + j], acc[j]);
        }
#pragma unroll
        for (int j = 0; j < 16; ++j)
            ys[g][jb * 16 + j] = acc[j] + b5[jb * 16 + j];
    }
    __syncthreads();

    if (tid < 64) {
        float s = 0.f, q = 0.f;
        for (int r = 0; r < G; ++r) {
            float v = ys[r][tid];
            s += v;
            q += v * v;
        }
        float inv = 1.0f / (float)G;
        float mu = s * inv;
        float var = q * inv - mu * mu;
        float scale = g2[tid] * rsqrtf(var + 1e-5f);
        sc[tid] = scale;
        sh[tid] = be2[tid] - mu * scale;
    }
    __syncthreads();

    if (tid < G) {
        float o = b6[0];
        for (int j = 0; j < 64; ++j) {
            float v = fmaxf(0.f, fmaf(ys[tid][j], sc[j], sh[j]));
            o = fmaf(v, W6[j], o);
        }
        out[tid] = o;
    }
}

// ---------------- launch ----------------
extern "C" void kernel_launch(void* const* d_in, const int* in_sizes, int n_in,
                              void* d_out, int out_size) {
    const float* x   = (const float*)d_in[0];
    const int*   ei  = (const int*)d_in[1];
    const int*   bat = (const int*)d_in[2];
    const float* W1  = (const float*)d_in[3];
    const float* b1  = (const float*)d_in[4];
    const float* W2  = (const float*)d_in[5];
    const float* b2  = (const float*)d_in[6];
    const float* W3  = (const float*)d_in[7];
    const float* b3  = (const float*)d_in[8];
    const float* g1  = (const float*)d_in[9];
    const float* be1 = (const float*)d_in[10];
    const float* W4  = (const float*)d_in[11];
    const float* b4  = (const float*)d_in[12];
    const float* W5  = (const float*)d_in[13];
    const float* b5  = (const float*)d_in[14];
    const float* g2  = (const float*)d_in[15];
    const float* be2 = (const float*)d_in[16];
    const float* W6  = (const float*)d_in[17];
    const float* b6  = (const float*)d_in[18];

    int N = in_sizes[2];
    int E = in_sizes[1] / 2;
    int G = out_size;
    const int* src = ei;
    const int* dst = ei + E;

    float *B0, *B1, *B2;
    unsigned *S0h, *S0l, *S1h, *S1l, *Wsh, *Wsl;
    void *pcnt, *pstats, *ppooled;
    cudaGetSymbolAddress((void**)&B0, g_B0);
    cudaGetSymbolAddress((void**)&B1, g_B1);
    cudaGetSymbolAddress((void**)&B2, g_B2);
    cudaGetSymbolAddress((void**)&S0h, g_S0h);
    cudaGetSymbolAddress((void**)&S0l, g_S0l);
    cudaGetSymbolAddress((void**)&S1h, g_S1h);
    cudaGetSymbolAddress((void**)&S1l, g_S1l);
    cudaGetSymbolAddress((void**)&Wsh, g_Wsh);
    cudaGetSymbolAddress((void**)&Wsl, g_Wsl);
    cudaGetSymbolAddress(&pcnt, g_cnt);
    cudaGetSymbolAddress(&pstats, g_stats);
    cudaGetSymbolAddress(&ppooled, g_pooled);

    static cudaStream_t s2 = nullptr;
    static cudaEvent_t evA = nullptr, evB = nullptr;
    if (!s2) {
        cudaStreamCreateWithFlags(&s2, cudaStreamNonBlocking);
        cudaEventCreateWithFlags(&evA, cudaEventDisableTiming);
        cudaEventCreateWithFlags(&evB, cudaEventDisableTiming);
    }

    int nb = (N + 1023) / 1024;
    int gb = (N + 127) / 128;
    int gather_blocks = (int)(((long long)N * 32 + 255) / 256);
    int smem1 = 10240 * 4;     // single stage (GEMM1/4)
    int smem2 = 20480 * 4;     // double-buffered (GEMM2/3)

    cudaFuncSetAttribute(mma_gemm<32, 0, false, true, false, false>,
                         cudaFuncAttributeMaxDynamicSharedMemorySize, smem1);
    cudaFuncSetAttribute(mma_gemm<128, 0, true, false, false, false>,
                         cudaFuncAttributeMaxDynamicSharedMemorySize, smem2);
    cudaFuncSetAttribute(mma_gemm<128, 0, true, false, true, false>,
                         cudaFuncAttributeMaxDynamicSharedMemorySize, smem2);
    cudaFuncSetAttribute(mma_gemm<128, 2, false, false, false, true>,
                         cudaFuncAttributeMaxDynamicSharedMemorySize, smem1);

    // ---- fork: CSR build + gather_x on side stream ----
    cudaEventRecord(evA, 0);
    cudaStreamWaitEvent(s2, evA, 0);

    cudaMemsetAsync(pcnt, 0, (size_t)N * sizeof(int), s2);
    deg_kernel<<<(E + 255) / 256, 256, 0, s2>>>(dst, E);
    dinv_kernel<<<(N + 255) / 256, 256, 0, s2>>>(N);
    scan1_kernel<<<nb, 1024, 0, s2>>>(N);
    scan2_kernel<<<1, 128, 0, s2>>>(nb, N);
    scan3_kernel<<<(N + 255) / 256, 256, 0, s2>>>(N);
    bin_kernel<<<(E + 255) / 256, 256, 0, s2>>>(src, dst, E);
    gatherx_kernel<<<gather_blocks, 256, 0, s2>>>(x, B2, N);   // Xs -> B2
    cudaEventRecord(evB, s2);

    // main stream: memsets + W pre-splits
    cudaMemsetAsync(pstats, 0, 2 * WN * sizeof(float));
    cudaMemsetAsync(ppooled, 0, (size_t)G * WN * sizeof(float));
    wsplit_kernel<<<8, 256>>>(W1, Wsh + 0, Wsl + 0, 32);
    wsplit_kernel<<<32, 256>>>(W2, Wsh + 8192, Wsl + 8192, 128);
    wsplit_kernel<<<32, 256>>>(W3, Wsh + 16384, Wsl + 16384, 128);
    wsplit_kernel<<<32, 256>>>(W4, Wsh + 24576, Wsl + 24576, 128);

    // join
    cudaStreamWaitEvent(0, evB, 0);

    // GEMM1: relu(Xs@W1 + b1) -> split S0
    mma_gemm<32, 0, false, true, false, false><<<gb, 256, smem1>>>(
        B2, nullptr, nullptr, Wsh, Wsl, b1, nullptr, S0h, S0l, nullptr, N);

    // GEMM2 (pipelined): h2 = S0@W2 -> B0 (f32); gather+relu -> split S1
    mma_gemm<128, 0, true, false, false, false><<<gb, 256, smem2>>>(
        nullptr, S0h, S0l, Wsh + 8192, Wsl + 8192, nullptr, B0, nullptr, nullptr, nullptr, N);
    gather_split_kernel<<<gather_blocks, 256>>>(B0, b2, S1h, S1l, N);

    // GEMM3 (pipelined): y = S1@W3 + b3 -> B1 (f32) + stats
    mma_gemm<128, 0, true, false, true, false><<<gb, 256, smem2>>>(
        nullptr, S1h, S1l, Wsh + 16384, Wsl + 16384, b3, B1, nullptr, nullptr, nullptr, N);
    bnfinal_kernel<<<1, 128>>>(g1, be1, N);

    // GEMM4: relu(bn(B1))@W4 + b4, fused max-pool
    mma_gemm<128, 2, false, false, false, true><<<gb, 256, smem1>>>(
        B1, nullptr, nullptr, Wsh + 24576, Wsl + 24576, b4, nullptr, nullptr, nullptr, bat, N);

    // final MLP
    final_kernel<<<1, 256>>>(W5, b5, g2, be2, W6, b6, (float*)d_out, G);
}

// round 12
// speedup vs baseline: 2.3655x; 1.0905x over previous
#include <cuda_runtime.h>

#define WN 128
#define NMAXN 100000
#define EMAX 600000
#define GMAX 64

// ---------------- scratch ----------------
__device__ float g_B0[(size_t)NMAXN * WN];
__device__ float g_B1[(size_t)NMAXN * WN];
__device__ float g_B2[(size_t)NMAXN * WN];
__device__ unsigned g_S1h[(size_t)NMAXN * 64];
__device__ unsigned g_S1l[(size_t)NMAXN * 64];
__device__ unsigned g_Wsh[4 * 8192];
__device__ unsigned g_Wsl[4 * 8192];
__device__ float g_dinv[NMAXN];
__device__ int   g_cnt[NMAXN];
__device__ int   g_rowtmp[NMAXN];
__device__ int   g_rowptr[NMAXN + 1];
__device__ int   g_cursor[NMAXN];
__device__ int   g_bsum[128];
__device__ int   g_boff[128];
__device__ int   g_scan_done;
__device__ int   g_csrc[EMAX];
__device__ float g_cdinv[EMAX];
__device__ float g_stats[2 * WN];
__device__ float g_pooled[GMAX * WN];

// ---------------- bf16 2-split helpers ----------------
__device__ __forceinline__ void split_bf16(float x, unsigned short& h, float& r) {
    asm("cvt.rn.bf16.f32 %0, %1;" : "=h"(h) : "f"(x));
    r = x - __uint_as_float(((unsigned)h) << 16);
}
__device__ __forceinline__ unsigned packf_bf16x2(float lo_, float hi_) {
    unsigned u;
    asm("cvt.rn.bf16x2.f32 %0, %1, %2;" : "=r"(u) : "f"(hi_), "f"(lo_));
    return u;
}
__device__ __forceinline__ void split_pair(float a, float b, unsigned& hi, unsigned& lo) {
    unsigned short ha, hb;
    float ra, rb;
    split_bf16(a, ha, ra);
    split_bf16(b, hb, rb);
    hi = ((unsigned)hb << 16) | (unsigned)ha;
    lo = packf_bf16x2(ra, rb);
}
__device__ __forceinline__ void mma_bf16(float* c, const unsigned* a, const unsigned* b) {
    asm volatile(
        "mma.sync.aligned.m16n8k16.row.col.f32.bf16.bf16.f32 "
        "{%0,%1,%2,%3}, {%4,%5,%6,%7}, {%8,%9}, {%0,%1,%2,%3};"
        : "+f"(c[0]), "+f"(c[1]), "+f"(c[2]), "+f"(c[3])
        : "r"(a[0]), "r"(a[1]), "r"(a[2]), "r"(a[3]), "r"(b[0]), "r"(b[1]));
}
__device__ __forceinline__ void cp16(unsigned* dst, const void* src, bool pred) {
    unsigned d = (unsigned)__cvta_generic_to_shared(dst);
    int sz = pred ? 16 : 0;
    asm volatile("cp.async.cg.shared.global [%0], [%1], 16, %2;"
                 :: "r"(d), "l"(src), "r"(sz));
}
__device__ __forceinline__ void cp_commit() {
    asm volatile("cp.async.commit_group;");
}
template<int NG>
__device__ __forceinline__ void cp_wait() {
    asm volatile("cp.async.wait_group %0;" :: "n"(NG));
}

// ---------------- degree / dinv ----------------
__global__ void deg_kernel(const int* __restrict__ dst, int E) {
    int e = blockIdx.x * blockDim.x + threadIdx.x;
    if (e < E) atomicAdd(&g_cnt[dst[e]], 1);
}

__global__ void dinv_kernel(int N) {
    int i = blockIdx.x * blockDim.x + threadIdx.x;
    if (i < N) g_dinv[i] = rsqrtf((float)g_cnt[i] + 1.0f);
}

// ---------------- CSR build: scan1 with fused last-block finalize ----------------
__global__ void scan1_kernel(int N) {
    __shared__ int sm[1024];
    __shared__ int isLast;
    int tid = threadIdx.x;
    int i = blockIdx.x * 1024 + tid;
    int v = (i < N) ? g_cnt[i] : 0;
    sm[tid] = v;
    __syncthreads();
#pragma unroll
    for (int o = 1; o < 1024; o <<= 1) {
        int t = 0;
        if (tid >= o) t = sm[tid - o];
        __syncthreads();
        if (tid >= o) sm[tid] += t;
        __syncthreads();
    }
    if (i < N) g_rowtmp[i] = sm[tid];
    if (tid == 1023) g_bsum[blockIdx.x] = sm[1023];
    __threadfence();
    if (tid == 0) isLast = (atomicAdd(&g_scan_done, 1) == (int)gridDim.x - 1);
    __syncthreads();
    if (isLast) {
        __shared__ int sm2[128];
        int nb = gridDim.x;
        int v2 = 0;
        if (tid < 128) {
            v2 = (tid < nb) ? g_bsum[tid] : 0;
            sm2[tid] = v2;
        }
        __syncthreads();
#pragma unroll
        for (int o = 1; o < 128; o <<= 1) {
            int u = 0;
            if (tid < 128 && tid >= o) u = sm2[tid - o];
            __syncthreads();
            if (tid < 128 && tid >= o) sm2[tid] += u;
            __syncthreads();
        }
        if (tid < 128 && tid < nb) g_boff[tid] = sm2[tid] - v2;
        if (tid == 127) g_rowptr[N] = sm2[127];
        if (tid == 0) g_scan_done = 0;   // reset for next graph replay
    }
}

__global__ void scan3_kernel(int N) {
    int i = blockIdx.x * blockDim.x + threadIdx.x;
    if (i < N) {
        int rp = g_rowtmp[i] - g_cnt[i] + g_boff[i >> 10];
        g_rowptr[i] = rp;
        g_cursor[i] = rp;
    }
}

__global__ void bin_kernel(const int* __restrict__ src, const int* __restrict__ dst, int E) {
    int e = blockIdx.x * blockDim.x + threadIdx.x;
    if (e >= E) return;
    int s = src[e], d = dst[e];
    int pos = atomicAdd(&g_cursor[d], 1);
    g_csrc[pos] = s;
    g_cdinv[pos] = g_dinv[s];
}

// ---------------- W split ----------------
__global__ void wsplit_kernel(const float* __restrict__ W, unsigned* __restrict__ oh,
                              unsigned* __restrict__ ol, int K) {
    int i = blockIdx.x * blockDim.x + threadIdx.x;
    int KP = K >> 1;
    if (i >= 128 * KP) return;
    int c = i / KP, kp = i % KP;
    unsigned h, l;
    split_pair(W[(size_t)(2 * kp) * WN + c], W[(size_t)(2 * kp + 1) * WN + c], h, l);
    oh[i] = h;
    ol[i] = l;
}

// ---------------- gather_x (32-wide) ----------------
__global__ void gatherx_kernel(const float* __restrict__ x, float* __restrict__ out, int N) {
    int t = blockIdx.x * blockDim.x + threadIdx.x;
    int w = t >> 5;
    if (w >= N) return;
    int lane = t & 31;
    int p0 = g_rowptr[w], p1 = g_rowptr[w + 1];
    float acc = 0.f;
    int e = p0;
    for (; e + 4 <= p1; e += 4) {
        int s0 = g_csrc[e], s1 = g_csrc[e + 1], s2 = g_csrc[e + 2], s3 = g_csrc[e + 3];
        float n0 = g_cdinv[e], n1 = g_cdinv[e + 1], n2 = g_cdinv[e + 2], n3 = g_cdinv[e + 3];
        acc = fmaf(x[(size_t)s0 * 32 + lane], n0, acc);
        acc = fmaf(x[(size_t)s1 * 32 + lane], n1, acc);
        acc = fmaf(x[(size_t)s2 * 32 + lane], n2, acc);
        acc = fmaf(x[(size_t)s3 * 32 + lane], n3, acc);
    }
    for (; e < p1; ++e)
        acc = fmaf(x[(size_t)g_csrc[e] * 32 + lane], g_cdinv[e], acc);
    float dv = g_dinv[w];
    out[(size_t)w * 32 + lane] = fmaf(acc, dv, x[(size_t)w * 32 + lane] * dv * dv);
}

// ---------------- gather -> split ----------------
__global__ void gather_split_kernel(const float* __restrict__ h, const float* __restrict__ bias,
                                    unsigned* __restrict__ oh, unsigned* __restrict__ ol, int N) {
    int t = blockIdx.x * blockDim.x + threadIdx.x;
    int w = t >> 5;
    if (w >= N) return;
    int lane = t & 31;
    int p0 = g_rowptr[w], p1 = g_rowptr[w + 1];
    float4 acc = make_float4(0.f, 0.f, 0.f, 0.f);
    int e = p0;
    for (; e + 4 <= p1; e += 4) {
        int s0 = g_csrc[e], s1 = g_csrc[e + 1], s2 = g_csrc[e + 2], s3 = g_csrc[e + 3];
        float n0 = g_cdinv[e], n1 = g_cdinv[e + 1], n2 = g_cdinv[e + 2], n3 = g_cdinv[e + 3];
        float4 v0 = ((const float4*)(h + (size_t)s0 * WN))[lane];
        float4 v1 = ((const float4*)(h + (size_t)s1 * WN))[lane];
        float4 v2 = ((const float4*)(h + (size_t)s2 * WN))[lane];
        float4 v3 = ((const float4*)(h + (size_t)s3 * WN))[lane];
        acc.x = fmaf(v0.x, n0, acc.x); acc.y = fmaf(v0.y, n0, acc.y);
        acc.z = fmaf(v0.z, n0, acc.z); acc.w = fmaf(v0.w, n0, acc.w);
        acc.x = fmaf(v1.x, n1, acc.x); acc.y = fmaf(v1.y, n1, acc.y);
        acc.z = fmaf(v1.z, n1, acc.z); acc.w = fmaf(v1.w, n1, acc.w);
        acc.x = fmaf(v2.x, n2, acc.x); acc.y = fmaf(v2.y, n2, acc.y);
        acc.z = fmaf(v2.z, n2, acc.z); acc.w = fmaf(v2.w, n2, acc.w);
        acc.x = fmaf(v3.x, n3, acc.x); acc.y = fmaf(v3.y, n3, acc.y);
        acc.z = fmaf(v3.z, n3, acc.z); acc.w = fmaf(v3.w, n3, acc.w);
    }
    for (; e < p1; ++e) {
        int s = g_csrc[e];
        float n = g_cdinv[e];
        float4 v = ((const float4*)(h + (size_t)s * WN))[lane];
        acc.x = fmaf(v.x, n, acc.x); acc.y = fmaf(v.y, n, acc.y);
        acc.z = fmaf(v.z, n, acc.z); acc.w = fmaf(v.w, n, acc.w);
    }
    float dv = g_dinv[w];
    float d2 = dv * dv;
    float4 hd = ((const float4*)(h + (size_t)w * WN))[lane];
    float4 b = ((const float4*)bias)[lane];
    float4 o;
    o.x = fmaxf(0.f, fmaf(acc.x, dv, fmaf(hd.x, d2, b.x)));
    o.y = fmaxf(0.f, fmaf(acc.y, dv, fmaf(hd.y, d2, b.y)));
    o.z = fmaxf(0.f, fmaf(acc.z, dv, fmaf(hd.z, d2, b.z)));
    o.w = fmaxf(0.f, fmaf(acc.w, dv, fmaf(hd.w, d2, b.w)));
    unsigned h0, l0, h1, l1;
    split_pair(o.x, o.y, h0, l0);
    split_pair(o.z, o.w, h1, l1);
    *(uint2*)&oh[(size_t)w * 64 + lane * 2] = make_uint2(h0, h1);
    *(uint2*)&ol[(size_t)w * 64 + lane * 2] = make_uint2(l0, l1);
}

// ---------------- fused GEMM1+GEMM2: B0 = relu(Xs@W1 + b1) @ W2 ----------------
// Xs f32 [M,32]; W1 pre-split (KP=16); W2 pre-split (KP=64). Output B0 f32 (no bias).
__global__ __launch_bounds__(256, 2) void gemm12_kernel(
        const float* __restrict__ Xs,
        const unsigned* __restrict__ W1h, const unsigned* __restrict__ W1l,
        const unsigned* __restrict__ W2h, const unsigned* __restrict__ W2l,
        const float* __restrict__ b1, float* __restrict__ C, int M) {
    constexpr int ST = 20;     // staging stride
    constexpr int ST2 = 68;    // T1 stride
    extern __shared__ unsigned smem[];
    unsigned* T1h = smem;                  // 8704
    unsigned* T1l = smem + 8704;           // 8704
    unsigned* S   = smem + 17408;          // 10240 (phase1 staging / phase2 W2 stages)

    int tid = threadIdx.x;
    int lane = tid & 31, wid = tid >> 5;
    int wm = wid >> 1, wn = wid & 1;
    int gr = lane >> 2;
    int row0 = blockIdx.x * 128;

    float acc[2][8][4];
#pragma unroll
    for (int mt = 0; mt < 2; ++mt)
#pragma unroll
        for (int nt = 0; nt < 8; ++nt)
#pragma unroll
            for (int q = 0; q < 4; ++q) acc[mt][nt][q] = 0.f;

    // generic compute: one 32-k chunk (2 ks iters); Ah/Al pre-offset to the chunk's kpair base
    auto comp = [&](const unsigned* Ah, const unsigned* Al, int STa,
                    const unsigned* Wh, const unsigned* Wl) {
#pragma unroll
        for (int ks = 0; ks < 2; ++ks) {
            int kc = ks * 8 + (lane & 3);
            unsigned ah[2][4], al[2][4];
#pragma unroll
            for (int mt = 0; mt < 2; ++mt) {
                int r = wm * 32 + mt * 16 + gr;
                const unsigned* ph = &Ah[r * STa + kc];
                const unsigned* pl = &Al[r * STa + kc];
                ah[mt][0] = ph[0]; ah[mt][1] = ph[8 * STa];
                ah[mt][2] = ph[4]; ah[mt][3] = ph[8 * STa + 4];
                al[mt][0] = pl[0]; al[mt][1] = pl[8 * STa];
                al[mt][2] = pl[4]; al[mt][3] = pl[8 * STa + 4];
            }
#pragma unroll
            for (int nh = 0; nh < 2; ++nh) {
                unsigned bh[4][2], bl[4][2];
#pragma unroll
                for (int j = 0; j < 4; ++j) {
                    int c = wn * 64 + (nh * 4 + j) * 8 + gr;
                    bh[j][0] = Wh[c * ST + kc];
                    bh[j][1] = Wh[c * ST + kc + 4];
                    bl[j][0] = Wl[c * ST + kc];
                    bl[j][1] = Wl[c * ST + kc + 4];
                }
#pragma unroll
                for (int mt = 0; mt < 2; ++mt)
#pragma unroll
                    for (int j = 0; j < 4; ++j) {
                        float* cc = acc[mt][nh * 4 + j];
                        mma_bf16(cc, al[mt], bh[j]);
                        mma_bf16(cc, ah[mt], bl[j]);
                        mma_bf16(cc, ah[mt], bh[j]);
                    }
            }
        }
    };

    // ---- phase 1: T1 = relu(Xs@W1 + b1) ----
    {
        unsigned* Axh = S;
        unsigned* Axl = S + 2560;
        unsigned* W1s = S + 5120;
        unsigned* W1t = S + 7680;
        // W1 via cp.async (KP=16)
        for (int i = tid; i < 512; i += 256) {
            int c = i >> 2, q = (i & 3) * 4;
            cp16(&W1s[c * ST + q], &W1h[(size_t)c * 16 + q], true);
            cp16(&W1t[c * ST + q], &W1l[(size_t)c * 16 + q], true);
        }
        cp_commit();
        // Xs f32 -> split
        for (int i = tid; i < 1024; i += 256) {
            int r = i >> 3, q = i & 7;
            float4 v = make_float4(0.f, 0.f, 0.f, 0.f);
            if (row0 + r < M)
                v = *(const float4*)(Xs + (size_t)(row0 + r) * 32 + 4 * q);
            unsigned h0, l0, h1, l1;
            split_pair(v.x, v.y, h0, l0);
            split_pair(v.z, v.w, h1, l1);
            *(uint2*)&Axh[r * ST + 2 * q] = make_uint2(h0, h1);
            *(uint2*)&Axl[r * ST + 2 * q] = make_uint2(l0, l1);
        }
        cp_wait<0>();
        __syncthreads();
        comp(Axh, Axl, ST, W1s, W1t);
        __syncthreads();   // phase-1 staging region free for reuse
    }

    // issue W2 chunks 0,1 into stages (region S reused)
    auto issueW2 = [&](int ci, int s) {
        unsigned* Wh = S + s * 5120;
        unsigned* Wl = Wh + 2560;
        int kp0 = ci * 16;
        for (int i = tid; i < 512; i += 256) {
            int c = i >> 2, q = (i & 3) * 4;
            cp16(&Wh[c * ST + q], &W2h[(size_t)c * 64 + kp0 + q], true);
            cp16(&Wl[c * ST + q], &W2l[(size_t)c * 64 + kp0 + q], true);
        }
        cp_commit();
    };
    issueW2(0, 0);
    issueW2(1, 1);

    // epilogue-1: relu(acc + b1) -> split T1; reset acc
    {
        float bv[16];
#pragma unroll
        for (int nt = 0; nt < 8; ++nt) {
            int col = wn * 64 + nt * 8 + (lane & 3) * 2;
            bv[nt * 2] = b1[col];
            bv[nt * 2 + 1] = b1[col + 1];
        }
#pragma unroll
        for (int mt = 0; mt < 2; ++mt)
#pragma unroll
            for (int h = 0; h < 2; ++h) {
                int r = wm * 32 + mt * 16 + gr + h * 8;
#pragma unroll
                for (int nt = 0; nt < 8; ++nt) {
                    int col = wn * 64 + nt * 8 + (lane & 3) * 2;
                    float v0 = fmaxf(0.f, acc[mt][nt][h * 2 + 0] + bv[nt * 2]);
                    float v1 = fmaxf(0.f, acc[mt][nt][h * 2 + 1] + bv[nt * 2 + 1]);
                    unsigned hh, ll;
                    split_pair(v0, v1, hh, ll);
                    T1h[r * ST2 + (col >> 1)] = hh;
                    T1l[r * ST2 + (col >> 1)] = ll;
                }
            }
#pragma unroll
        for (int mt = 0; mt < 2; ++mt)
#pragma unroll
            for (int nt = 0; nt < 8; ++nt)
#pragma unroll
                for (int q = 0; q < 4; ++q) acc[mt][nt][q] = 0.f;
    }
    __syncthreads();   // T1 visible; W2 chunk ordering handled by cp_wait

    // ---- phase 2: B0 = T1 @ W2, 4 chunks, double-buffered W2 ----
    // BUGFIX (R11): offset the A base by ci*16 kpairs so chunk ci multiplies
    // T1's k-window [ci*32, ci*32+32) against W2 chunk ci.
#pragma unroll
    for (int ci = 0; ci < 4; ++ci) {
        if (ci < 3) cp_wait<1>(); else cp_wait<0>();
        __syncthreads();
        comp(T1h + ci * 16, T1l + ci * 16, ST2,
             S + (ci & 1) * 5120, S + (ci & 1) * 5120 + 2560);
        __syncthreads();
        if (ci + 2 < 4) issueW2(ci + 2, ci & 1);
    }

    // epilogue-2: write f32 (no bias)
#pragma unroll
    for (int mt = 0; mt < 2; ++mt)
#pragma unroll
        for (int h = 0; h < 2; ++h) {
            int row = row0 + wm * 32 + mt * 16 + gr + h * 8;
            if (row >= M) continue;
#pragma unroll
            for (int nt = 0; nt < 8; ++nt) {
                int col = wn * 64 + nt * 8 + (lane & 3) * 2;
                *(float2*)(C + (size_t)row * WN + col) =
                    make_float2(acc[mt][nt][h * 2 + 0], acc[mt][nt][h * 2 + 1]);
            }
        }
}

// ---------------- 3x bf16-split tensor-core GEMM (GEMM3 / GEMM4) ----------------
// INSPLIT: pre-split input, cp.async double-buffered. PRO==2: BN affine computed
// per-CTA from g_stats (bng/bnb = gamma/beta). STATS: column sums/sumsq. POOL: atomicMax.
template<int K, int PRO, bool INSPLIT, bool STATS, bool POOL>
__global__ __launch_bounds__(256, 2) void mma_gemm(
        const float* __restrict__ A,
        const unsigned* __restrict__ Agh, const unsigned* __restrict__ Agl,
        const unsigned* __restrict__ Wgh, const unsigned* __restrict__ Wgl,
        const float* __restrict__ bias, float* __restrict__ C,
        const float* __restrict__ bng, const float* __restrict__ bnb,
        const int* __restrict__ batch, int M) {
    constexpr int CH = 32;
    constexpr int KP = K / 2;
    constexpr int ST = 20;
    constexpr int NC = K / CH;
    constexpr int STAGE = 10240;
    extern __shared__ unsigned smem[];
    __shared__ float sstat[2 * WN];
    __shared__ float sbnp[2 * WN];

    int tid = threadIdx.x;
    int lane = tid & 31, wid = tid >> 5;
    int wm = wid >> 1, wn = wid & 1;
    int gr = lane >> 2;
    int row0 = blockIdx.x * 128;

    if (STATS) sstat[tid] = 0.f;
    if (PRO == 2) {
        if (tid < WN) {
            float inv = 1.0f / (float)M;
            float mu = g_stats[tid] * inv;
            float var = g_stats[WN + tid] * inv - mu * mu;
            float sc = bng[tid] * rsqrtf(var + 1e-5f);
            sbnp[tid] = sc;
            sbnp[WN + tid] = bnb[tid] - mu * sc;
        }
        __syncthreads();
    }

    float acc[2][8][4];
#pragma unroll
    for (int mt = 0; mt < 2; ++mt)
#pragma unroll
        for (int nt = 0; nt < 8; ++nt)
#pragma unroll
            for (int q = 0; q < 4; ++q) acc[mt][nt][q] = 0.f;

    auto issue = [&](int ci, int s) {
        unsigned* Ah = smem + s * STAGE;
        unsigned* Al = Ah + 2560;
        unsigned* Wh = Al + 2560;
        unsigned* Wl = Wh + 2560;
        int kp0 = ci * (CH / 2);
#pragma unroll
        for (int i = tid; i < 512; i += 256) {
            int c = i >> 2, q = (i & 3) * 4;
            cp16(&Wh[c * ST + q], &Wgh[(size_t)c * KP + kp0 + q], true);
            cp16(&Wl[c * ST + q], &Wgl[(size_t)c * KP + kp0 + q], true);
        }
#pragma unroll
        for (int i = tid; i < 512; i += 256) {
            int r = i >> 2, q = (i & 3) * 4;
            bool ok = row0 + r < M;
            cp16(&Ah[r * ST + q], &Agh[(size_t)(row0 + r) * 64 + kp0 + q], ok);
            cp16(&Al[r * ST + q], &Agl[(size_t)(row0 + r) * 64 + kp0 + q], ok);
        }
        cp_commit();
    };

    auto compute = [&](int s) {
        unsigned* Ah = smem + s * STAGE;
        unsigned* Al = Ah + 2560;
        unsigned* Wh = Al + 2560;
        unsigned* Wl = Wh + 2560;
#pragma unroll
        for (int ks = 0; ks < 2; ++ks) {
            int kc = ks * 8 + (lane & 3);
            unsigned ah[2][4], al[2][4];
#pragma unroll
            for (int mt = 0; mt < 2; ++mt) {
                int r = wm * 32 + mt * 16 + gr;
                const unsigned* ph = &Ah[r * ST + kc];
                const unsigned* pl = &Al[r * ST + kc];
                ah[mt][0] = ph[0]; ah[mt][1] = ph[8 * ST];
                ah[mt][2] = ph[4]; ah[mt][3] = ph[8 * ST + 4];
                al[mt][0] = pl[0]; al[mt][1] = pl[8 * ST];
                al[mt][2] = pl[4]; al[mt][3] = pl[8 * ST + 4];
            }
#pragma unroll
            for (int nh = 0; nh < 2; ++nh) {
                unsigned bh[4][2], bl[4][2];
#pragma unroll
                for (int j = 0; j < 4; ++j) {
                    int c = wn * 64 + (nh * 4 + j) * 8 + gr;
                    bh[j][0] = Wh[c * ST + kc];
                    bh[j][1] = Wh[c * ST + kc + 4];
                    bl[j][0] = Wl[c * ST + kc];
                    bl[j][1] = Wl[c * ST + kc + 4];
                }
#pragma unroll
                for (int mt = 0; mt < 2; ++mt)
#pragma unroll
                    for (int j = 0; j < 4; ++j) {
                        float* cc = acc[mt][nh * 4 + j];
                        mma_bf16(cc, al[mt], bh[j]);
                        mma_bf16(cc, ah[mt], bl[j]);
                        mma_bf16(cc, ah[mt], bh[j]);
                    }
            }
        }
    };

    if (INSPLIT) {
        issue(0, 0);
#pragma unroll
        for (int ci = 0; ci < NC; ++ci) {
            if (ci + 1 < NC) {
                issue(ci + 1, (ci + 1) & 1);
                cp_wait<1>();
            } else {
                cp_wait<0>();
            }
            __syncthreads();
            compute(ci & 1);
            __syncthreads();
        }
    } else {
        unsigned* Ah = smem;
        unsigned* Al = smem + 2560;
        unsigned* Wh = smem + 5120;
        unsigned* Wl = smem + 7680;
        for (int kb = 0; kb < K; kb += CH) {
            int kp0 = kb >> 1;
            __syncthreads();
            for (int i = tid; i < 512; i += 256) {
                int c = i >> 2, q = (i & 3) * 4;
                *(uint4*)&Wh[c * ST + q] = *(const uint4*)&Wgh[(size_t)c * KP + kp0 + q];
                *(uint4*)&Wl[c * ST + q] = *(const uint4*)&Wgl[(size_t)c * KP + kp0 + q];
            }
            for (int i = tid; i < 128 * 8; i += 256) {
                int r = i >> 3, q = i & 7;
                float4 v = make_float4(0.f, 0.f, 0.f, 0.f);
                if (row0 + r < M)
                    v = *(const float4*)(A + (size_t)(row0 + r) * K + kb + 4 * q);
                if (PRO == 2) {
                    int kg = kb + 4 * q;
                    v.x = fmaxf(0.f, fmaf(v.x, sbnp[kg + 0], sbnp[WN + kg + 0]));
                    v.y = fmaxf(0.f, fmaf(v.y, sbnp[kg + 1], sbnp[WN + kg + 1]));
                    v.z = fmaxf(0.f, fmaf(v.z, sbnp[kg + 2], sbnp[WN + kg + 2]));
                    v.w = fmaxf(0.f, fmaf(v.w, sbnp[kg + 3], sbnp[WN + kg + 3]));
                }
                unsigned h0, l0, h1, l1;
                split_pair(v.x, v.y, h0, l0);
                split_pair(v.z, v.w, h1, l1);
                *(uint2*)&Ah[r * ST + 2 * q] = make_uint2(h0, h1);
                *(uint2*)&Al[r * ST + 2 * q] = make_uint2(l0, l1);
            }
            __syncthreads();
            compute(0);
        }
    }

    // ---------------- epilogue ----------------
    if (POOL) {
        int rbase = row0 + wm * 32 + gr;
        int bt[4];
#pragma unroll
        for (int t = 0; t < 4; ++t) {
            int r = rbase + t * 8;
            bt[t] = (r < M) ? batch[r] : -1;
        }
        bool same = (bt[0] == bt[1]) && (bt[1] == bt[2]) && (bt[2] == bt[3]) && (bt[0] >= 0);
#pragma unroll
        for (int nt = 0; nt < 8; ++nt) {
#pragma unroll
            for (int c = 0; c < 2; ++c) {
                int col = wn * 64 + nt * 8 + (lane & 3) * 2 + c;
                float bb = bias[col];
                float v[4];
                v[0] = fmaxf(0.f, acc[0][nt][c] + bb);
                v[1] = fmaxf(0.f, acc[0][nt][2 + c] + bb);
                v[2] = fmaxf(0.f, acc[1][nt][c] + bb);
                v[3] = fmaxf(0.f, acc[1][nt][2 + c] + bb);
                if (same) {
                    float m = fmaxf(fmaxf(v[0], v[1]), fmaxf(v[2], v[3]));
                    atomicMax((int*)&g_pooled[(size_t)bt[0] * WN + col], __float_as_int(m));
                } else {
#pragma unroll
                    for (int t = 0; t < 4; ++t)
                        if (bt[t] >= 0)
                            atomicMax((int*)&g_pooled[(size_t)bt[t] * WN + col],
                                      __float_as_int(v[t]));
                }
            }
        }
        return;
    }

    float ss[16], sq[16];
    if (STATS) {
#pragma unroll
        for (int i = 0; i < 16; ++i) { ss[i] = 0.f; sq[i] = 0.f; }
    }

#pragma unroll
    for (int mt = 0; mt < 2; ++mt) {
#pragma unroll
        for (int h = 0; h < 2; ++h) {
            int row = row0 + wm * 32 + mt * 16 + gr + h * 8;
            bool ok = row < M;
#pragma unroll
            for (int nt = 0; nt < 8; ++nt) {
                int col = wn * 64 + nt * 8 + (lane & 3) * 2;
                float b0 = bias ? bias[col] : 0.f;
                float b1 = bias ? bias[col + 1] : 0.f;
                float o0 = acc[mt][nt][h * 2 + 0] + b0;
                float o1 = acc[mt][nt][h * 2 + 1] + b1;
                if (ok)
                    *(float2*)(C + (size_t)row * WN + col) = make_float2(o0, o1);
                if (STATS) {
                    if (!ok) { o0 = 0.f; o1 = 0.f; }
                    ss[nt * 2 + 0] += o0; sq[nt * 2 + 0] += o0 * o0;
                    ss[nt * 2 + 1] += o1; sq[nt * 2 + 1] += o1 * o1;
                }
            }
        }
    }

    if (STATS) {
#pragma unroll
        for (int i = 0; i < 16; ++i) {
#pragma unroll
            for (int o = 4; o <= 16; o <<= 1) {
                ss[i] += __shfl_xor_sync(0xffffffffu, ss[i], o);
                sq[i] += __shfl_xor_sync(0xffffffffu, sq[i], o);
            }
        }
        if (lane < 4) {
#pragma unroll
            for (int nt = 0; nt < 8; ++nt)
#pragma unroll
                for (int c = 0; c < 2; ++c) {
                    int col = wn * 64 + nt * 8 + lane * 2 + c;
                    atomicAdd(&sstat[col], ss[nt * 2 + c]);
                    atomicAdd(&sstat[WN + col], sq[nt * 2 + c]);
                }
        }
        __syncthreads();
        atomicAdd(&g_stats[tid], sstat[tid]);
    }
}

// ---------------- final tiny MLP ----------------
__global__ void final_kernel(const float* __restrict__ W5, const float* __restrict__ b5,
                             const float* __restrict__ g2, const float* __restrict__ be2,
                             const float* __restrict__ W6, const float* __restrict__ b6,
                             float* __restrict__ out, int G) {
    __shared__ float W5s[WN * 64];
    __shared__ float ys[GMAX][65];
    __shared__ float sc[64], sh[64];
    int tid = threadIdx.x;
    for (int i = tid; i < WN * 64; i += 256) W5s[i] = W5[i];
    __syncthreads();

    int g = tid & 63;
    int jb = tid >> 6;
    float acc[16];
#pragma unroll
    for (int j = 0; j < 16; ++j) acc[j] = 0.f;
    if (g < G) {
        for (int k = 0; k < WN; ++k) {
            float p = g_pooled[(size_t)g * WN + k];
#pragma unroll
            for (int j = 0; j < 16; ++j)
                acc[j] = fmaf(p, W5s[k * 64 + jb * 16 + j], acc[j]);
        }
#pragma unroll
        for (int j = 0; j < 16; ++j)
            ys[g][jb * 16 + j] = acc[j] + b5[jb * 16 + j];
    }
    __syncthreads();

    if (tid < 64) {
        float s = 0.f, q = 0.f;
        for (int r = 0; r < G; ++r) {
            float v = ys[r][tid];
            s += v;
            q += v * v;
        }
        float inv = 1.0f / (float)G;
        float mu = s * inv;
        float var = q * inv - mu * mu;
        float scale = g2[tid] * rsqrtf(var + 1e-5f);
        sc[tid] = scale;
        sh[tid] = be2[tid] - mu * scale;
    }
    __syncthreads();

    if (tid < G) {
        float o = b6[0];
        for (int j = 0; j < 64; ++j) {
            float v = fmaxf(0.f, fmaf(ys[tid][j], sc[j], sh[j]));
            o = fmaf(v, W6[j], o);
        }
        out[tid] = o;
    }
}

// ---------------- launch ----------------
extern "C" void kernel_launch(void* const* d_in, const int* in_sizes, int n_in,
                              void* d_out, int out_size) {
    const float* x   = (const float*)d_in[0];
    const int*   ei  = (const int*)d_in[1];
    const int*   bat = (const int*)d_in[2];
    const float* W1  = (const float*)d_in[3];
    const float* b1  = (const float*)d_in[4];
    const float* W2  = (const float*)d_in[5];
    const float* b2  = (const float*)d_in[6];
    const float* W3  = (const float*)d_in[7];
    const float* b3  = (const float*)d_in[8];
    const float* g1  = (const float*)d_in[9];
    const float* be1 = (const float*)d_in[10];
    const float* W4  = (const float*)d_in[11];
    const float* b4  = (const float*)d_in[12];
    const float* W5  = (const float*)d_in[13];
    const float* b5  = (const float*)d_in[14];
    const float* g2  = (const float*)d_in[15];
    const float* be2 = (const float*)d_in[16];
    const float* W6  = (const float*)d_in[17];
    const float* b6  = (const float*)d_in[18];

    int N = in_sizes[2];
    int E = in_sizes[1] / 2;
    int G = out_size;
    const int* src = ei;
    const int* dst = ei + E;

    float *B0, *B1, *B2;
    unsigned *S1h, *S1l, *Wsh, *Wsl;
    void *pcnt, *pstats, *ppooled;
    cudaGetSymbolAddress((void**)&B0, g_B0);
    cudaGetSymbolAddress((void**)&B1, g_B1);
    cudaGetSymbolAddress((void**)&B2, g_B2);
    cudaGetSymbolAddress((void**)&S1h, g_S1h);
    cudaGetSymbolAddress((void**)&S1l, g_S1l);
    cudaGetSymbolAddress((void**)&Wsh, g_Wsh);
    cudaGetSymbolAddress((void**)&Wsl, g_Wsl);
    cudaGetSymbolAddress(&pcnt, g_cnt);
    cudaGetSymbolAddress(&pstats, g_stats);
    cudaGetSymbolAddress(&ppooled, g_pooled);

    static cudaStream_t s2 = nullptr;
    static cudaEvent_t evA = nullptr, evB = nullptr;
    if (!s2) {
        cudaStreamCreateWithFlags(&s2, cudaStreamNonBlocking);
        cudaEventCreateWithFlags(&evA, cudaEventDisableTiming);
        cudaEventCreateWithFlags(&evB, cudaEventDisableTiming);
    }

    int nb = (N + 1023) / 1024;
    int gb = (N + 127) / 128;
    int gather_blocks = (int)(((long long)N * 32 + 255) / 256);
    int smem1 = 10240 * 4;     // single stage (GEMM4)
    int smem2 = 20480 * 4;     // double-buffered (GEMM3)
    int smem12 = 27648 * 4;    // fused GEMM1+2

    cudaFuncSetAttribute(gemm12_kernel,
                         cudaFuncAttributeMaxDynamicSharedMemorySize, smem12);
    cudaFuncSetAttribute(mma_gemm<128, 0, true, true, false>,
                         cudaFuncAttributeMaxDynamicSharedMemorySize, smem2);
    cudaFuncSetAttribute(mma_gemm<128, 2, false, false, true>,
                         cudaFuncAttributeMaxDynamicSharedMemorySize, smem1);

    // ---- fork: CSR build + gather_x on side stream ----
    cudaEventRecord(evA, 0);
    cudaStreamWaitEvent(s2, evA, 0);

    cudaMemsetAsync(pcnt, 0, (size_t)N * sizeof(int), s2);
    deg_kernel<<<(E + 255) / 256, 256, 0, s2>>>(dst, E);
    dinv_kernel<<<(N + 255) / 256, 256, 0, s2>>>(N);
    scan1_kernel<<<nb, 1024, 0, s2>>>(N);
    scan3_kernel<<<(N + 255) / 256, 256, 0, s2>>>(N);
    bin_kernel<<<(E + 255) / 256, 256, 0, s2>>>(src, dst, E);
    gatherx_kernel<<<gather_blocks, 256, 0, s2>>>(x, B2, N);   // Xs -> B2
    cudaEventRecord(evB, s2);

    // main stream: memsets + W pre-splits
    cudaMemsetAsync(pstats, 0, 2 * WN * sizeof(float));
    cudaMemsetAsync(ppooled, 0, (size_t)G * WN * sizeof(float));
    wsplit_kernel<<<8, 256>>>(W1, Wsh + 0, Wsl + 0, 32);
    wsplit_kernel<<<32, 256>>>(W2, Wsh + 8192, Wsl + 8192, 128);
    wsplit_kernel<<<32, 256>>>(W3, Wsh + 16384, Wsl + 16384, 128);
    wsplit_kernel<<<32, 256>>>(W4, Wsh + 24576, Wsl + 24576, 128);

    // join
    cudaStreamWaitEvent(0, evB, 0);

    // fused GEMM1+2: B0 = relu(Xs@W1 + b1) @ W2
    gemm12_kernel<<<gb, 256, smem12>>>(B2, Wsh, Wsl, Wsh + 8192, Wsl + 8192, b1, B0, N);

    // gather+relu -> split S1 (adds self + b2)
    gather_split_kernel<<<gather_blocks, 256>>>(B0, b2, S1h, S1l, N);

    // GEMM3 (pipelined): y = S1@W3 + b3 -> B1 (f32) + stats
    mma_gemm<128, 0, true, true, false><<<gb, 256, smem2>>>(
        nullptr, S1h, S1l, Wsh + 16384, Wsl + 16384, b3, B1, nullptr, nullptr, nullptr, N);

    // GEMM4: relu(bn(B1))@W4 + b4 (BN computed in-kernel from g_stats), fused max-pool
    mma_gemm<128, 2, false, false, true><<<gb, 256, smem1>>>(
        B1, nullptr, nullptr, Wsh + 24576, Wsl + 24576, b4, nullptr, g1, be1, bat, N);

    // final MLP
    final_kernel<<<1, 256>>>(W5, b5, g2, be2, W6, b6, (float*)d_out, G);
}